// round 2
// baseline (speedup 1.0000x reference)
#include <cuda_runtime.h>
#include <math.h>

namespace sg {
constexpr int Bn = 8, Cc = 256, Hh = 16, Ww = 24, Pp = 7, Nn = 16;
constexpr int HW = Hh * Ww;           // 384
constexpr int C32 = 384;
constexpr float SCALE = 1.0f / 16.0f;
constexpr float IMGW = 384.0f, IMGH = 256.0f;
constexpr int PP = 49;
constexpr int NPAIR = 256;
constexpr int KFC = 12544;            // 256*49

constexpr long SZ_CTXF  = (long)Bn * Cc * HW;
constexpr long SZ_RELF  = (long)Bn * C32 * HW;
constexpr long SZ_FEATT = SZ_CTXF;
constexpr long SZ_RELFT = SZ_RELF;
constexpr long SZ_PCTX  = (long)Bn * Cc * PP;
constexpr long SZ_BIMAP = (long)Bn * Nn * PP;
constexpr long SZ_XOBJ  = (long)Bn * 512 * 784;
constexpr long SZ_OBJ   = (long)Bn * 256 * 784;
constexpr long SZ_ASUB  = SZ_OBJ;
constexpr long SZ_AOBJ  = SZ_OBJ;
constexpr long SZ_XREL  = (long)Bn * C32 * KFC;
constexpr long SZ_REL5  = (long)Bn * 256 * KFC;
constexpr long SZ_R     = (long)KFC * (Bn * NPAIR);   // [12544][2048]
constexpr long SZ_ROBJ  = (long)KFC * (Bn * Nn);      // [12544][128]
constexpr long SZ_FREL  = 256L * (Bn * NPAIR);
constexpr long SZ_FOBJ  = 256L * (Bn * Nn);

constexpr long OF_CTXF  = 0;
constexpr long OF_RELF  = OF_CTXF  + SZ_CTXF;
constexpr long OF_FEATT = OF_RELF  + SZ_RELF;
constexpr long OF_RELFT = OF_FEATT + SZ_FEATT;
constexpr long OF_PCTX  = OF_RELFT + SZ_RELFT;
constexpr long OF_BIMAP = OF_PCTX  + SZ_PCTX;
constexpr long OF_XOBJ  = OF_BIMAP + SZ_BIMAP;
constexpr long OF_OBJ   = OF_XOBJ  + SZ_XOBJ;
constexpr long OF_ASUB  = OF_OBJ   + SZ_OBJ;
constexpr long OF_AOBJ  = OF_ASUB  + SZ_ASUB;
constexpr long OF_XREL  = OF_AOBJ  + SZ_AOBJ;
constexpr long OF_REL5  = OF_XREL  + SZ_XREL;
constexpr long OF_R     = OF_REL5  + SZ_REL5;
constexpr long OF_ROBJ  = OF_R     + SZ_R;
constexpr long OF_FREL  = OF_ROBJ  + SZ_ROBJ;
constexpr long OF_FOBJ  = OF_FREL  + SZ_FREL;
constexpr long TOTAL    = OF_FOBJ  + SZ_FOBJ;
}  // namespace sg

__device__ float g_buf[sg::TOTAL];

// ---------------------------------------------------------------------------
static __device__ __forceinline__ float hatG(float t) {
    float tl = fminf(fmaxf(t, -1.0f), 0.0f);
    float tr = fminf(fmaxf(t, 0.0f), 1.0f);
    return 0.5f * (tl + 1.0f) * (tl + 1.0f) + 0.5f - 0.5f * (1.0f - tr) * (1.0f - tr);
}

// Bin weights (feature-scale coords) + active index ranges. Cooperative.
static __device__ __forceinline__ void compute_weights(
    float x1, float y1, float x2, float y2,
    float (*wy)[16], float (*wx)[24],
    int* h0, int* h1, int* w0, int* w1, int tid)
{
    if (tid < 112) {
        int p = tid / 16, i = tid % 16;
        float e0 = y1 + (y2 - y1) * (float)p * (1.0f / 7.0f);
        float e1 = y1 + (y2 - y1) * (float)(p + 1) * (1.0f / 7.0f);
        wy[p][i] = hatG(e1 - (float)i) - hatG(e0 - (float)i);
    }
    if (tid < 168) {
        int q = tid / 24, i = tid % 24;
        float e0 = x1 + (x2 - x1) * (float)q * (1.0f / 7.0f);
        float e1 = x1 + (x2 - x1) * (float)(q + 1) * (1.0f / 7.0f);
        wx[q][i] = hatG(e1 - (float)i) - hatG(e0 - (float)i);
    }
    if (tid < 7) {
        float e0 = y1 + (y2 - y1) * (float)tid * (1.0f / 7.0f);
        float e1 = y1 + (y2 - y1) * (float)(tid + 1) * (1.0f / 7.0f);
        h0[tid] = max(0, (int)floorf(e0) - 1);
        h1[tid] = min(16, (int)ceilf(e1) + 2);
    }
    if (tid >= 32 && tid < 39) {
        int q = tid - 32;
        float e0 = x1 + (x2 - x1) * (float)q * (1.0f / 7.0f);
        float e1 = x1 + (x2 - x1) * (float)(q + 1) * (1.0f / 7.0f);
        w0[q] = max(0, (int)floorf(e0) - 1);
        w1[q] = min(24, (int)ceilf(e1) + 2);
    }
}

// Accumulate 49 pooled bin sums for one channel; pixel (h,w) at fb[(h*24+w)*ps].
static __device__ __forceinline__ void pool_channel_acc(
    const float* __restrict__ fb, int ps,
    const float (*wy)[16], const float (*wx)[24],
    const int* h0, const int* h1, const int* w0, const int* w1,
    float* acc)
{
#pragma unroll
    for (int p = 0; p < 7; p++) {
        for (int h = h0[p]; h < h1[p]; h++) {
            float wyv = wy[p][h];
            const float* row = fb + (long)h * 24 * ps;
#pragma unroll
            for (int q = 0; q < 7; q++) {
                float a = 0.0f;
                for (int w = w0[q]; w < w1[q]; w++)
                    a += wx[q][w] * row[(long)w * ps];
                acc[p * 7 + q] += wyv * a;
            }
        }
    }
}

// ---------------------------------------------------------------------------
// Batched SGEMM: C[b] = A * B[b] (+bias per row). Row-major fp32.
// M mult of 64, K mult of 16, N guarded. grid(ceil(N/64), M/64, batch), blk 256.
// ---------------------------------------------------------------------------
__global__ void __launch_bounds__(256) sgemm_kernel(
    const float* __restrict__ Aext, long offA, int lda, long sAb,
    const float* __restrict__ Bext, long offB, int ldb, long sBb,
    long offC, int ldc, long sCb,
    int M, int N, int K, const float* __restrict__ bias)
{
    const int b = blockIdx.z;
    const float* A  = (Aext ? Aext + offA : g_buf + offA) + (long)b * sAb;
    const float* Bm = (Bext ? Bext + offB : g_buf + offB) + (long)b * sBb;
    float* Cm = g_buf + offC + (long)b * sCb;

    __shared__ float As[16][65];
    __shared__ float Bs[16][68];

    const int tid = threadIdx.x;
    const int row0 = blockIdx.y * 64;
    const int col0 = blockIdx.x * 64;
    const int ty = tid >> 4, tx = tid & 15;
    const int ty4 = ty * 4, tx4 = tx * 4;

    const int ar = tid >> 2;
    const int ak = (tid & 3) << 2;
    const int br = tid >> 4;
    const int bc = (tid & 15) << 2;

    float acc[4][4] = {};

    for (int k0 = 0; k0 < K; k0 += 16) {
        float4 av = *(const float4*)(A + (long)(row0 + ar) * lda + k0 + ak);
        As[ak + 0][ar] = av.x; As[ak + 1][ar] = av.y;
        As[ak + 2][ar] = av.z; As[ak + 3][ar] = av.w;

        const float* bp = Bm + (long)(k0 + br) * ldb + col0 + bc;
        float4 bv;
        if (col0 + bc + 3 < N) {
            bv = *(const float4*)bp;
        } else {
            bv.x = (col0 + bc + 0 < N) ? bp[0] : 0.0f;
            bv.y = (col0 + bc + 1 < N) ? bp[1] : 0.0f;
            bv.z = (col0 + bc + 2 < N) ? bp[2] : 0.0f;
            bv.w = 0.0f;
        }
        *(float4*)&Bs[br][bc] = bv;
        __syncthreads();

#pragma unroll
        for (int k = 0; k < 16; k++) {
            float a0 = As[k][ty4 + 0], a1 = As[k][ty4 + 1];
            float a2 = As[k][ty4 + 2], a3 = As[k][ty4 + 3];
            float4 b4 = *(const float4*)&Bs[k][tx4];
            acc[0][0] += a0 * b4.x; acc[0][1] += a0 * b4.y; acc[0][2] += a0 * b4.z; acc[0][3] += a0 * b4.w;
            acc[1][0] += a1 * b4.x; acc[1][1] += a1 * b4.y; acc[1][2] += a1 * b4.z; acc[1][3] += a1 * b4.w;
            acc[2][0] += a2 * b4.x; acc[2][1] += a2 * b4.y; acc[2][2] += a2 * b4.z; acc[2][3] += a2 * b4.w;
            acc[3][0] += a3 * b4.x; acc[3][1] += a3 * b4.y; acc[3][2] += a3 * b4.z; acc[3][3] += a3 * b4.w;
        }
        __syncthreads();
    }

#pragma unroll
    for (int u = 0; u < 4; u++) {
        int r = row0 + ty4 + u;
        float bz = bias ? bias[r] : 0.0f;
#pragma unroll
        for (int v = 0; v < 4; v++) {
            int cidx = col0 + tx4 + v;
            if (cidx < N) Cm[(long)r * ldc + cidx] = acc[u][v] + bz;
        }
    }
}

// ---------------------------------------------------------------------------
// Transpose src[b][R][C] -> dst[b][C][R]. R, C multiples of 32.
// grid(C/32, R/32, batch), block(32,8).
// ---------------------------------------------------------------------------
__global__ void transpose_kernel(const float* __restrict__ srcExt,
                                 long offSrc, long offDst, int R, int C)
{
    __shared__ float tile[32][33];
    int b = blockIdx.z;
    const float* src = (srcExt ? srcExt : (const float*)g_buf + offSrc) + (long)b * R * C;
    float* dst = g_buf + offDst + (long)b * R * C;
    int c0 = blockIdx.x * 32, r0 = blockIdx.y * 32;
    int tx = threadIdx.x, ty = threadIdx.y;
#pragma unroll
    for (int k = 0; k < 32; k += 8)
        tile[ty + k][tx] = src[(long)(r0 + ty + k) * C + c0 + tx];
    __syncthreads();
#pragma unroll
    for (int k = 0; k < 32; k += 8)
        dst[(long)(c0 + ty + k) * R + r0 + tx] = tile[tx][ty + k];
}

// ---------------------------------------------------------------------------
// Pool raw features over object boxes -> Xobj channels [0,256); also box_imap.
// grid(16, 8), block 256 (thread = channel).
// ---------------------------------------------------------------------------
__global__ void __launch_bounds__(256) pool_obj_kernel(const float* __restrict__ boxes)
{
    using namespace sg;
    int b = blockIdx.y, n = blockIdx.x, tid = threadIdx.x;
    const float* bx = boxes + ((long)b * Nn + n) * 4;
    float x1 = bx[0], y1 = bx[1], x2 = bx[2], y2 = bx[3];
    float sx1 = x1 * SCALE, sy1 = y1 * SCALE, sx2 = x2 * SCALE, sy2 = y2 * SCALE;

    __shared__ float wy[7][16], wx[7][24];
    __shared__ int h0[7], h1[7], w0[7], w1[7];
    compute_weights(sx1, sy1, sx2, sy2, wy, wx, h0, h1, w0, w1, tid);

    if (tid < 49) {
        int p = tid / 7, q = tid % 7;
        float ye0 = IMGH * (float)p * (1.0f / 7.0f), ye1 = IMGH * (float)(p + 1) * (1.0f / 7.0f);
        float xe0 = IMGW * (float)q * (1.0f / 7.0f), xe1 = IMGW * (float)(q + 1) * (1.0f / 7.0f);
        float oy = fmaxf(fminf(ye1, y2) - fmaxf(ye0, y1), 0.0f);
        float ox = fmaxf(fminf(xe1, x2) - fmaxf(xe0, x1), 0.0f);
        float ch = IMGH * (1.0f / 7.0f), cw = IMGW * (1.0f / 7.0f);
        g_buf[OF_BIMAP + ((long)b * Nn + n) * PP + tid] = (oy / ch) * (ox / cw);
    }
    __syncthreads();

    float area = (sx2 - sx1) * (sy2 - sy1) * (1.0f / 49.0f);
    float inv = (area > 0.0f) ? 1.0f / fmaxf(area, 1e-9f) : 0.0f;

    int c = tid;
    const float* fb = g_buf + OF_FEATT + (long)b * HW * Cc + c;   // [hw][c]
    float acc[49];
#pragma unroll
    for (int s = 0; s < 49; s++) acc[s] = 0.0f;
    pool_channel_acc(fb, Cc, wy, wx, h0, h1, w0, w1, acc);

    float* X = g_buf + OF_XOBJ + ((long)b * 512 + c) * 784 + (long)n * 49;
#pragma unroll
    for (int s = 0; s < 49; s++) X[s] = acc[s] * inv;
}

// ---------------------------------------------------------------------------
// Pool ctx features over the full-image box. grid 8, block 256.
// ---------------------------------------------------------------------------
__global__ void __launch_bounds__(256) pool_ctx_kernel()
{
    using namespace sg;
    int b = blockIdx.x, tid = threadIdx.x;
    __shared__ float wy[7][16], wx[7][24];
    __shared__ int h0[7], h1[7], w0[7], w1[7];
    compute_weights(0.0f, 0.0f, 24.0f, 16.0f, wy, wx, h0, h1, w0, w1, tid);
    __syncthreads();

    float inv = 49.0f / (24.0f * 16.0f);
    int c = tid;
    const float* fb = g_buf + OF_CTXF + ((long)b * Cc + c) * HW;  // [c][hw]
    float acc[49];
#pragma unroll
    for (int s = 0; s < 49; s++) acc[s] = 0.0f;
    pool_channel_acc(fb, 1, wy, wx, h0, h1, w0, w1, acc);
    float* X = g_buf + OF_PCTX + ((long)b * Cc + c) * PP;
#pragma unroll
    for (int s = 0; s < 49; s++) X[s] = acc[s] * inv;
}

// ---------------------------------------------------------------------------
// Fill Xobj channels [256,512): x (ctx 0..127), y*box_imap (ctx 128..255).
// grid(16, 8), block 256.
// ---------------------------------------------------------------------------
__global__ void pack_xobj_kernel()
{
    using namespace sg;
    int b = blockIdx.y;
    int base = blockIdx.x * blockDim.x + threadIdx.x;
    int stride = gridDim.x * blockDim.x;
    for (int idx = base; idx < 256 * 784; idx += stride) {
        int cc = idx / 784, rem = idx - cc * 784;
        int n = rem / 49, s = rem - n * 49;
        float v = g_buf[OF_PCTX + ((long)b * Cc + cc) * PP + s];
        if (cc >= 128) v *= g_buf[OF_BIMAP + ((long)b * Nn + n) * PP + s];
        g_buf[OF_XOBJ + ((long)b * 512 + 256 + cc) * 784 + rem] = v;
    }
}

// ---------------------------------------------------------------------------
// Pool rel features over 256 union boxes, apply imap masks -> Xrel[b][c][pair*49+s].
// grid(256, 8), block 384 (thread = channel). Dynamic smem: 384*49 floats.
// ---------------------------------------------------------------------------
__global__ void __launch_bounds__(384) pool_rel_kernel(const float* __restrict__ boxes)
{
    using namespace sg;
    extern __shared__ float stage[];
    int b = blockIdx.y, pair = blockIdx.x, tid = threadIdx.x;
    int i = pair >> 4, j = pair & 15;
    const float* bi = boxes + ((long)b * Nn + i) * 4;
    const float* bj = boxes + ((long)b * Nn + j) * 4;
    float ix1 = bi[0], iy1 = bi[1], ix2 = bi[2], iy2 = bi[3];
    float jx1 = bj[0], jy1 = bj[1], jx2 = bj[2], jy2 = bj[3];
    float ux1 = fminf(ix1, jx1), uy1 = fminf(iy1, jy1);
    float ux2 = fmaxf(ix2, jx2), uy2 = fmaxf(iy2, jy2);
    float sx1 = ux1 * SCALE, sy1 = uy1 * SCALE, sx2 = ux2 * SCALE, sy2 = uy2 * SCALE;

    __shared__ float wy[7][16], wx[7][24];
    __shared__ int h0[7], h1[7], w0[7], w1[7];
    __shared__ float subm[49], objm[49];
    compute_weights(sx1, sy1, sx2, sy2, wy, wx, h0, h1, w0, w1, tid);

    if (tid < 49) {
        int p = tid / 7, q = tid - p * 7;
        float ye0 = uy1 + (uy2 - uy1) * (float)p * (1.0f / 7.0f);
        float ye1 = uy1 + (uy2 - uy1) * (float)(p + 1) * (1.0f / 7.0f);
        float xe0 = ux1 + (ux2 - ux1) * (float)q * (1.0f / 7.0f);
        float xe1 = ux1 + (ux2 - ux1) * (float)(q + 1) * (1.0f / 7.0f);
        float ch = fmaxf((uy2 - uy1) * (1.0f / 7.0f), 1e-9f);
        float cw = fmaxf((ux2 - ux1) * (1.0f / 7.0f), 1e-9f);
        float oy = fmaxf(fminf(ye1, iy2) - fmaxf(ye0, iy1), 0.0f);
        float ox = fmaxf(fminf(xe1, ix2) - fmaxf(xe0, ix1), 0.0f);
        subm[tid] = (oy / ch) * (ox / cw);
        oy = fmaxf(fminf(ye1, jy2) - fmaxf(ye0, jy1), 0.0f);
        ox = fmaxf(fminf(xe1, jx2) - fmaxf(xe0, jx1), 0.0f);
        objm[tid] = (oy / ch) * (ox / cw);
    }
    __syncthreads();

    float area = (sx2 - sx1) * (sy2 - sy1) * (1.0f / 49.0f);
    float inv = (area > 0.0f) ? 1.0f / fmaxf(area, 1e-9f) : 0.0f;

    int c = tid;
    const float* fb = g_buf + OF_RELFT + (long)b * HW * C32 + c;  // [hw][c]
    float acc[49];
#pragma unroll
    for (int s = 0; s < 49; s++) acc[s] = 0.0f;
    pool_channel_acc(fb, C32, wy, wx, h0, h1, w0, w1, acc);

#pragma unroll
    for (int s = 0; s < 49; s++) {
        float mk = (c < 128) ? 1.0f : (c < 256 ? subm[s] : objm[s]);
        stage[c * 49 + s] = acc[s] * inv * mk;
    }
    __syncthreads();

    float* X = g_buf + OF_XREL + (long)b * C32 * KFC + (long)pair * 49;
    for (int idx = tid; idx < C32 * 49; idx += 384) {
        int cc = idx / 49, ss = idx - cc * 49;
        X[(long)cc * KFC + ss] = stage[idx];
    }
}

// ---------------------------------------------------------------------------
// rel = pairGEMM + A_sub[i] + A_obj[j] + bias; relu; transpose ->
// Rt[(o*49+s)][b*256+pair]  (B matrix of the batched-over-images rel FC).
// grid(8, 512, 8)  [x: pair-tile/32, y: (o<<1)|sTile, z: b], block(32,8).
// ---------------------------------------------------------------------------
__global__ void combine_rel_kernel(const float* __restrict__ brf)
{
    using namespace sg;
    __shared__ float t[32][33];
    int b = blockIdx.z;
    int o = blockIdx.y >> 1;
    int st = (blockIdx.y & 1) * 32;
    int pt = blockIdx.x * 32;
    int tx = threadIdx.x, ty = threadIdx.y;
    const float* rel5 = g_buf + OF_REL5 + ((long)b * 256 + o) * KFC;
    const float* A1   = g_buf + OF_ASUB + ((long)b * 256 + o) * 784;
    const float* A2   = g_buf + OF_AOBJ + ((long)b * 256 + o) * 784;
    float bias = brf[o];
    int s = st + tx;
    if (s < 49) {
#pragma unroll
        for (int k = 0; k < 32; k += 8) {
            int pair = pt + ty + k;
            int i = pair >> 4, j = pair & 15;
            float v = rel5[(long)pair * 49 + s] + A1[i * 49 + s] + A2[j * 49 + s] + bias;
            t[ty + k][tx] = fmaxf(v, 0.0f);
        }
    }
    __syncthreads();
#pragma unroll
    for (int k = 0; k < 32; k += 8) {
        int sw = st + ty + k;
        if (sw < 49)
            g_buf[OF_R + (long)(o * 49 + sw) * 2048 + (long)b * 256 + pt + tx] = t[tx][ty + k];
    }
}

// ---------------------------------------------------------------------------
// relu(obj) transposed into Robj[(o*49+s)][b*16+i].
// ---------------------------------------------------------------------------
__global__ void combine_obj_kernel()
{
    using namespace sg;
    long idx = (long)blockIdx.x * blockDim.x + threadIdx.x;
    if (idx >= (long)KFC * 128) return;
    int row = (int)(idx >> 7), col = (int)(idx & 127);
    int o = row / 49, s = row - o * 49;
    int b = col >> 4, i = col & 15;
    float v = g_buf[OF_OBJ + ((long)b * 256 + o) * 784 + i * 49 + s];
    g_buf[OF_ROBJ + idx] = fmaxf(v, 0.0f);
}

// ---------------------------------------------------------------------------
// l2norm over n=256 per column; out[col][n] = src[n][col]/||.||.
// grid = ncols blocks, block = 256.
// ---------------------------------------------------------------------------
__global__ void finalize_kernel(long srcOff, int ncols, float* __restrict__ out)
{
    int col = blockIdx.x, n = threadIdx.x;
    float v = g_buf[srcOff + (long)n * ncols + col];
    float s = v * v;
#pragma unroll
    for (int o = 16; o > 0; o >>= 1) s += __shfl_xor_sync(0xffffffffu, s, o);
    __shared__ float red[8];
    if ((n & 31) == 0) red[n >> 5] = s;
    __syncthreads();
    float tot = red[0] + red[1] + red[2] + red[3] + red[4] + red[5] + red[6] + red[7];
    out[(long)col * 256 + n] = v / sqrtf(tot);
}

// ---------------------------------------------------------------------------
extern "C" void kernel_launch(void* const* d_in, const int* in_sizes, int n_in,
                              void* d_out, int out_size)
{
    using namespace sg;
    const float* input = (const float*)d_in[0];
    const float* boxes = (const float*)d_in[1];
    const float* W_ctx = (const float*)d_in[3];
    const float* b_ctx = (const float*)d_in[4];
    const float* W_rel = (const float*)d_in[5];
    const float* b_rel = (const float*)d_in[6];
    const float* W_of  = (const float*)d_in[7];
    const float* b_of  = (const float*)d_in[8];
    const float* W_rf  = (const float*)d_in[9];
    const float* b_rf  = (const float*)d_in[10];
    const float* W_ofc = (const float*)d_in[11];
    const float* b_ofc = (const float*)d_in[12];
    const float* W_rfc = (const float*)d_in[13];
    const float* b_rfc = (const float*)d_in[14];
    float* out = (float*)d_out;

    const long sFeat = (long)Cc * HW;       // 98304
    const long sRelf = (long)C32 * HW;      // 147456
    const long s784  = 256L * 784;          // 200704

    // 1. ctx conv: [256,384] = W_ctx[256,256] x feat[256,384]
    sgemm_kernel<<<dim3(6, 4, 8), 256>>>(W_ctx, 0, 256, 0, input, 0, 384, sFeat,
                                         OF_CTXF, 384, sFeat, 256, 384, 256, b_ctx);
    // 2. rel conv: [384,384]
    sgemm_kernel<<<dim3(6, 6, 8), 256>>>(W_rel, 0, 256, 0, input, 0, 384, sFeat,
                                         OF_RELF, 384, sRelf, 384, 384, 256, b_rel);
    // 3. featT [hw][c]
    transpose_kernel<<<dim3(12, 8, 8), dim3(32, 8)>>>(input, 0, OF_FEATT, 256, 384);
    // 4. relfT [hw][c]
    transpose_kernel<<<dim3(12, 12, 8), dim3(32, 8)>>>(nullptr, OF_RELF, OF_RELFT, 384, 384);
    // 5. pool ctx over image box
    pool_ctx_kernel<<<8, 256>>>();
    // 6. pool raw feat over object boxes (+ box_imap)
    pool_obj_kernel<<<dim3(16, 8), 256>>>(boxes);
    // 7. pack ctx-pooled channels into Xobj
    pack_xobj_kernel<<<dim3(16, 8), 256>>>();
    // 8. obj conv: [256,784] = W_of[256,512] x Xobj[512,784]
    sgemm_kernel<<<dim3(13, 4, 8), 256>>>(W_of, 0, 512, 0, nullptr, OF_XOBJ, 784, 512L * 784,
                                          OF_OBJ, 784, s784, 256, 784, 512, b_of);
    // 9. A_sub = W_rf[:,0:256] x obj
    sgemm_kernel<<<dim3(13, 4, 8), 256>>>(W_rf, 0, 896, 0, nullptr, OF_OBJ, 784, s784,
                                          OF_ASUB, 784, s784, 256, 784, 256, nullptr);
    // 10. A_obj = W_rf[:,256:512] x obj
    sgemm_kernel<<<dim3(13, 4, 8), 256>>>(W_rf, 256, 896, 0, nullptr, OF_OBJ, 784, s784,
                                          OF_AOBJ, 784, s784, 256, 784, 256, nullptr);
    // 11. pool rel feat over union boxes -> Xrel
    cudaFuncSetAttribute(pool_rel_kernel, cudaFuncAttributeMaxDynamicSharedMemorySize, 384 * 49 * 4);
    pool_rel_kernel<<<dim3(256, 8), 384, 384 * 49 * 4>>>(boxes);
    // 12. pair GEMM: rel5[256,12544] = W_rf[:,512:896] x Xrel[384,12544]
    sgemm_kernel<<<dim3(196, 4, 8), 256>>>(W_rf, 512, 896, 0, nullptr, OF_XREL, KFC, (long)C32 * KFC,
                                           OF_REL5, KFC, 256L * KFC, 256, KFC, 384, nullptr);
    // 13. combine + relu + transpose -> Rt[12544][2048]
    combine_rel_kernel<<<dim3(8, 512, 8), dim3(32, 8)>>>(b_rf);
    // 14. rel FC: frel[256,2048] = W_rfc[256,12544] x Rt
    sgemm_kernel<<<dim3(32, 4, 1), 256>>>(W_rfc, 0, KFC, 0, nullptr, OF_R, 2048, 0,
                                          OF_FREL, 2048, 0, 256, 2048, KFC, b_rfc);
    // 15. relu(obj) transpose -> Robj[12544][128]
    combine_obj_kernel<<<(int)(((long)KFC * 128 + 255) / 256), 256>>>();
    // 16. obj FC: fobj[256,128] = W_ofc[256,12544] x Robj
    sgemm_kernel<<<dim3(2, 4, 1), 256>>>(W_ofc, 0, KFC, 0, nullptr, OF_ROBJ, 128, 0,
                                         OF_FOBJ, 128, 0, 256, 128, KFC, b_ofc);
    // 17. l2norm obj -> out[0 : 8*16*256]
    finalize_kernel<<<128, 256>>>(OF_FOBJ, 128, out);
    // 18. l2norm rel -> out[32768 : ]
    finalize_kernel<<<2048, 256>>>(OF_FREL, 2048, out + 32768);
}

// round 3
// speedup vs baseline: 1.7752x; 1.7752x over previous
#include <cuda_runtime.h>
#include <math.h>

namespace sg {
constexpr int Bn = 8, Cc = 256, Hh = 16, Ww = 24, Pp = 7, Nn = 16;
constexpr int HW = Hh * Ww;           // 384
constexpr int C32 = 384;
constexpr float SCALE = 1.0f / 16.0f;
constexpr float IMGW = 384.0f, IMGH = 256.0f;
constexpr int PP = 49;
constexpr int NPAIR = 256;
constexpr int KFC = 12544;            // 256*49

constexpr long SZ_CTXF  = (long)Bn * Cc * HW;
constexpr long SZ_RELF  = (long)Bn * C32 * HW;
constexpr long SZ_FEATT = SZ_CTXF;
constexpr long SZ_RELFT = SZ_RELF;
constexpr long SZ_PCTX  = (long)Bn * Cc * PP;
constexpr long SZ_BIMAP = (long)Bn * Nn * PP;
constexpr long SZ_XOBJ  = (long)Bn * 512 * 784;
constexpr long SZ_OBJ   = (long)Bn * 256 * 784;
constexpr long SZ_ASUB  = SZ_OBJ;
constexpr long SZ_AOBJ  = SZ_OBJ;
constexpr long SZ_XREL  = (long)Bn * C32 * KFC;
constexpr long SZ_REL5  = (long)Bn * 256 * KFC;
constexpr long SZ_R     = (long)KFC * (Bn * NPAIR);   // [12544][2048]
constexpr long SZ_ROBJ  = (long)KFC * (Bn * Nn);      // [12544][128]
constexpr long SZ_FREL  = 256L * (Bn * NPAIR);
constexpr long SZ_FOBJ  = 256L * (Bn * Nn);
constexpr long SZ_FP    = 8L  * 256 * 2048;           // rel FC split-K partials
constexpr long SZ_FPO   = 32L * 256 * 128;            // obj FC split-K partials

constexpr long OF_CTXF  = 0;
constexpr long OF_RELF  = OF_CTXF  + SZ_CTXF;
constexpr long OF_FEATT = OF_RELF  + SZ_RELF;
constexpr long OF_RELFT = OF_FEATT + SZ_FEATT;
constexpr long OF_PCTX  = OF_RELFT + SZ_RELFT;
constexpr long OF_BIMAP = OF_PCTX  + SZ_PCTX;
constexpr long OF_XOBJ  = OF_BIMAP + SZ_BIMAP;
constexpr long OF_OBJ   = OF_XOBJ  + SZ_XOBJ;
constexpr long OF_ASUB  = OF_OBJ   + SZ_OBJ;
constexpr long OF_AOBJ  = OF_ASUB  + SZ_ASUB;
constexpr long OF_XREL  = OF_AOBJ  + SZ_AOBJ;
constexpr long OF_REL5  = OF_XREL  + SZ_XREL;
constexpr long OF_R     = OF_REL5  + SZ_REL5;
constexpr long OF_ROBJ  = OF_R     + SZ_R;
constexpr long OF_FREL  = OF_ROBJ  + SZ_ROBJ;
constexpr long OF_FOBJ  = OF_FREL  + SZ_FREL;
constexpr long OF_FP    = OF_FOBJ  + SZ_FOBJ;
constexpr long OF_FPO   = OF_FP    + SZ_FP;
constexpr long TOTAL    = OF_FPO   + SZ_FPO;
}  // namespace sg

__device__ float g_buf[sg::TOTAL];

// ---------------------------------------------------------------------------
static __device__ __forceinline__ float hatG(float t) {
    float tl = fminf(fmaxf(t, -1.0f), 0.0f);
    float tr = fminf(fmaxf(t, 0.0f), 1.0f);
    return 0.5f * (tl + 1.0f) * (tl + 1.0f) + 0.5f - 0.5f * (1.0f - tr) * (1.0f - tr);
}

static __device__ __forceinline__ void compute_weights(
    float x1, float y1, float x2, float y2,
    float (*wy)[16], float (*wx)[24],
    int* h0, int* h1, int* w0, int* w1, int tid)
{
    if (tid < 112) {
        int p = tid / 16, i = tid % 16;
        float e0 = y1 + (y2 - y1) * (float)p * (1.0f / 7.0f);
        float e1 = y1 + (y2 - y1) * (float)(p + 1) * (1.0f / 7.0f);
        wy[p][i] = hatG(e1 - (float)i) - hatG(e0 - (float)i);
    }
    if (tid < 168) {
        int q = tid / 24, i = tid % 24;
        float e0 = x1 + (x2 - x1) * (float)q * (1.0f / 7.0f);
        float e1 = x1 + (x2 - x1) * (float)(q + 1) * (1.0f / 7.0f);
        wx[q][i] = hatG(e1 - (float)i) - hatG(e0 - (float)i);
    }
    if (tid < 7) {
        float e0 = y1 + (y2 - y1) * (float)tid * (1.0f / 7.0f);
        float e1 = y1 + (y2 - y1) * (float)(tid + 1) * (1.0f / 7.0f);
        h0[tid] = max(0, (int)floorf(e0) - 1);
        h1[tid] = min(16, (int)ceilf(e1) + 2);
    }
    if (tid >= 32 && tid < 39) {
        int q = tid - 32;
        float e0 = x1 + (x2 - x1) * (float)q * (1.0f / 7.0f);
        float e1 = x1 + (x2 - x1) * (float)(q + 1) * (1.0f / 7.0f);
        w0[q] = max(0, (int)floorf(e0) - 1);
        w1[q] = min(24, (int)ceilf(e1) + 2);
    }
}

static __device__ __forceinline__ void pool_channel_acc(
    const float* __restrict__ fb, int ps,
    const float (*wy)[16], const float (*wx)[24],
    const int* h0, const int* h1, const int* w0, const int* w1,
    float* acc)
{
#pragma unroll
    for (int p = 0; p < 7; p++) {
        for (int h = h0[p]; h < h1[p]; h++) {
            float wyv = wy[p][h];
            const float* row = fb + (long)h * 24 * ps;
#pragma unroll
            for (int q = 0; q < 7; q++) {
                float a = 0.0f;
                for (int w = w0[q]; w < w1[q]; w++)
                    a += wx[q][w] * row[(long)w * ps];
                acc[p * 7 + q] += wyv * a;
            }
        }
    }
}

// ---------------------------------------------------------------------------
// Small-GEMM path (64x64x16). C[b] = A * B[b] (+bias). Used for the two convs.
// ---------------------------------------------------------------------------
__global__ void __launch_bounds__(256) sgemm_kernel(
    const float* __restrict__ Aext, long offA, int lda, long sAb,
    const float* __restrict__ Bext, long offB, int ldb, long sBb,
    long offC, int ldc, long sCb,
    int M, int N, int K, const float* __restrict__ bias)
{
    const int b = blockIdx.z;
    const float* A  = (Aext ? Aext + offA : g_buf + offA) + (long)b * sAb;
    const float* Bm = (Bext ? Bext + offB : g_buf + offB) + (long)b * sBb;
    float* Cm = g_buf + offC + (long)b * sCb;

    __shared__ float As[16][65];
    __shared__ float Bs[16][68];

    const int tid = threadIdx.x;
    const int row0 = blockIdx.y * 64;
    const int col0 = blockIdx.x * 64;
    const int ty = tid >> 4, tx = tid & 15;
    const int ty4 = ty * 4, tx4 = tx * 4;

    const int ar = tid >> 2;
    const int ak = (tid & 3) << 2;
    const int br = tid >> 4;
    const int bc = (tid & 15) << 2;

    float acc[4][4] = {};

    for (int k0 = 0; k0 < K; k0 += 16) {
        float4 av = *(const float4*)(A + (long)(row0 + ar) * lda + k0 + ak);
        As[ak + 0][ar] = av.x; As[ak + 1][ar] = av.y;
        As[ak + 2][ar] = av.z; As[ak + 3][ar] = av.w;

        const float* bp = Bm + (long)(k0 + br) * ldb + col0 + bc;
        float4 bv;
        if (col0 + bc + 3 < N) {
            bv = *(const float4*)bp;
        } else {
            bv.x = (col0 + bc + 0 < N) ? bp[0] : 0.0f;
            bv.y = (col0 + bc + 1 < N) ? bp[1] : 0.0f;
            bv.z = (col0 + bc + 2 < N) ? bp[2] : 0.0f;
            bv.w = 0.0f;
        }
        *(float4*)&Bs[br][bc] = bv;
        __syncthreads();

#pragma unroll
        for (int k = 0; k < 16; k++) {
            float a0 = As[k][ty4 + 0], a1 = As[k][ty4 + 1];
            float a2 = As[k][ty4 + 2], a3 = As[k][ty4 + 3];
            float4 b4 = *(const float4*)&Bs[k][tx4];
            acc[0][0] += a0 * b4.x; acc[0][1] += a0 * b4.y; acc[0][2] += a0 * b4.z; acc[0][3] += a0 * b4.w;
            acc[1][0] += a1 * b4.x; acc[1][1] += a1 * b4.y; acc[1][2] += a1 * b4.z; acc[1][3] += a1 * b4.w;
            acc[2][0] += a2 * b4.x; acc[2][1] += a2 * b4.y; acc[2][2] += a2 * b4.z; acc[2][3] += a2 * b4.w;
            acc[3][0] += a3 * b4.x; acc[3][1] += a3 * b4.y; acc[3][2] += a3 * b4.z; acc[3][3] += a3 * b4.w;
        }
        __syncthreads();
    }

#pragma unroll
    for (int u = 0; u < 4; u++) {
        int r = row0 + ty4 + u;
        float bz = bias ? bias[r] : 0.0f;
#pragma unroll
        for (int v = 0; v < 4; v++) {
            int cidx = col0 + tx4 + v;
            if (cidx < N) Cm[(long)r * ldc + cidx] = acc[u][v] + bz;
        }
    }
}

// ---------------------------------------------------------------------------
// Big-GEMM path: 128x128 tile, kstep 8, 8x8 per thread, double-buffered smem.
// A external (weights), row-major [.][lda]; B in g_buf; C in g_buf.
// blockIdx.z = b * splitK + ks : batch OR split-K chunk (C stride sCb per z).
// M (grid.y*128) rows must be fully in-bounds; N guarded; chunk K mult of 8.
// ---------------------------------------------------------------------------
__global__ void __launch_bounds__(256) sgemm128_kernel(
    const float* __restrict__ Aex, long offA, int lda,
    long offB, int ldb, long sBb,
    long offC, int ldc, long sCb,
    int N, int K, int kChunk, int splitK,
    const float* __restrict__ bias)
{
    __shared__ float As[2][8][132];
    __shared__ float Bs[2][8][132];

    const int z = blockIdx.z;
    const int b = z / splitK;
    const int ks = z - b * splitK;
    const int kBeg = ks * kChunk;
    const int kEnd = min(K, kBeg + kChunk);
    const int nk = (kEnd - kBeg) >> 3;

    const float* A = Aex + offA;
    const float* B = g_buf + offB + (long)b * sBb;
    float* C = g_buf + offC + (long)z * sCb;

    const int t = threadIdx.x;
    const int row0 = blockIdx.y * 128, col0 = blockIdx.x * 128;
    const int arow = t >> 1, akq = (t & 1) << 2;
    const int brow = t >> 5, bcol = (t & 31) << 2;
    const int tx = t & 15, ty = t >> 4;

    const float* aPtr = A + (long)(row0 + arow) * lda + kBeg + akq;
    const float* bPtr = B + (long)(kBeg + brow) * ldb + col0 + bcol;
    const bool bIn = (col0 + bcol + 3) < N;

    float4 pa = *(const float4*)aPtr;
    float4 pb;
    if (bIn) {
        pb = *(const float4*)bPtr;
    } else {
        pb.x = (col0 + bcol + 0 < N) ? bPtr[0] : 0.0f;
        pb.y = (col0 + bcol + 1 < N) ? bPtr[1] : 0.0f;
        pb.z = (col0 + bcol + 2 < N) ? bPtr[2] : 0.0f;
        pb.w = 0.0f;
    }
    As[0][akq + 0][arow] = pa.x; As[0][akq + 1][arow] = pa.y;
    As[0][akq + 2][arow] = pa.z; As[0][akq + 3][arow] = pa.w;
    *(float4*)&Bs[0][brow][bcol] = pb;
    __syncthreads();

    float acc[8][8] = {};

    for (int kt = 0; kt < nk; kt++) {
        const int buf = kt & 1;
        if (kt + 1 < nk) {
            pa = *(const float4*)(aPtr + (kt + 1) * 8);
            const float* bp = bPtr + (long)(kt + 1) * 8 * ldb;
            if (bIn) {
                pb = *(const float4*)bp;
            } else {
                pb.x = (col0 + bcol + 0 < N) ? bp[0] : 0.0f;
                pb.y = (col0 + bcol + 1 < N) ? bp[1] : 0.0f;
                pb.z = (col0 + bcol + 2 < N) ? bp[2] : 0.0f;
                pb.w = 0.0f;
            }
        }
#pragma unroll
        for (int kk = 0; kk < 8; kk++) {
            float4 a0 = *(const float4*)&As[buf][kk][ty * 4];
            float4 a1 = *(const float4*)&As[buf][kk][64 + ty * 4];
            float4 b0 = *(const float4*)&Bs[buf][kk][tx * 4];
            float4 b1 = *(const float4*)&Bs[buf][kk][64 + tx * 4];
            float av[8] = {a0.x, a0.y, a0.z, a0.w, a1.x, a1.y, a1.z, a1.w};
            float bv[8] = {b0.x, b0.y, b0.z, b0.w, b1.x, b1.y, b1.z, b1.w};
#pragma unroll
            for (int u = 0; u < 8; u++)
#pragma unroll
                for (int v = 0; v < 8; v++)
                    acc[u][v] += av[u] * bv[v];
        }
        if (kt + 1 < nk) {
            const int nb = buf ^ 1;
            As[nb][akq + 0][arow] = pa.x; As[nb][akq + 1][arow] = pa.y;
            As[nb][akq + 2][arow] = pa.z; As[nb][akq + 3][arow] = pa.w;
            *(float4*)&Bs[nb][brow][bcol] = pb;
            __syncthreads();
        }
    }

#pragma unroll
    for (int u = 0; u < 8; u++) {
        int r = row0 + ((u < 4) ? ty * 4 + u : 64 + ty * 4 + (u - 4));
        float bz = bias ? bias[r] : 0.0f;
#pragma unroll
        for (int v = 0; v < 8; v++) {
            int c = col0 + ((v < 4) ? tx * 4 + v : 64 + tx * 4 + (v - 4));
            if (c < N) C[(long)r * ldc + c] = acc[u][v] + bz;
        }
    }
}

// ---------------------------------------------------------------------------
// Deterministic split-K reduction: out[idx] = sum_s partial[s][idx] + bias[m].
// ---------------------------------------------------------------------------
__global__ void reduce_split_kernel(long offP, long offO, long MN, int Ncols,
                                    int S, const float* __restrict__ bias)
{
    long idx = (long)blockIdx.x * blockDim.x + threadIdx.x;
    if (idx >= MN) return;
    float s = 0.0f;
    for (int i = 0; i < S; i++) s += g_buf[offP + (long)i * MN + idx];
    int m = (int)(idx / Ncols);
    g_buf[offO + idx] = s + bias[m];
}

// ---------------------------------------------------------------------------
__global__ void transpose_kernel(const float* __restrict__ srcExt,
                                 long offSrc, long offDst, int R, int C)
{
    __shared__ float tile[32][33];
    int b = blockIdx.z;
    const float* src = (srcExt ? srcExt : (const float*)g_buf + offSrc) + (long)b * R * C;
    float* dst = g_buf + offDst + (long)b * R * C;
    int c0 = blockIdx.x * 32, r0 = blockIdx.y * 32;
    int tx = threadIdx.x, ty = threadIdx.y;
#pragma unroll
    for (int k = 0; k < 32; k += 8)
        tile[ty + k][tx] = src[(long)(r0 + ty + k) * C + c0 + tx];
    __syncthreads();
#pragma unroll
    for (int k = 0; k < 32; k += 8)
        dst[(long)(c0 + ty + k) * R + r0 + tx] = tile[tx][ty + k];
}

// ---------------------------------------------------------------------------
__global__ void __launch_bounds__(256) pool_obj_kernel(const float* __restrict__ boxes)
{
    using namespace sg;
    int b = blockIdx.y, n = blockIdx.x, tid = threadIdx.x;
    const float* bx = boxes + ((long)b * Nn + n) * 4;
    float x1 = bx[0], y1 = bx[1], x2 = bx[2], y2 = bx[3];
    float sx1 = x1 * SCALE, sy1 = y1 * SCALE, sx2 = x2 * SCALE, sy2 = y2 * SCALE;

    __shared__ float wy[7][16], wx[7][24];
    __shared__ int h0[7], h1[7], w0[7], w1[7];
    compute_weights(sx1, sy1, sx2, sy2, wy, wx, h0, h1, w0, w1, tid);

    if (tid < 49) {
        int p = tid / 7, q = tid % 7;
        float ye0 = IMGH * (float)p * (1.0f / 7.0f), ye1 = IMGH * (float)(p + 1) * (1.0f / 7.0f);
        float xe0 = IMGW * (float)q * (1.0f / 7.0f), xe1 = IMGW * (float)(q + 1) * (1.0f / 7.0f);
        float oy = fmaxf(fminf(ye1, y2) - fmaxf(ye0, y1), 0.0f);
        float ox = fmaxf(fminf(xe1, x2) - fmaxf(xe0, x1), 0.0f);
        float ch = IMGH * (1.0f / 7.0f), cw = IMGW * (1.0f / 7.0f);
        g_buf[OF_BIMAP + ((long)b * Nn + n) * PP + tid] = (oy / ch) * (ox / cw);
    }
    __syncthreads();

    float area = (sx2 - sx1) * (sy2 - sy1) * (1.0f / 49.0f);
    float inv = (area > 0.0f) ? 1.0f / fmaxf(area, 1e-9f) : 0.0f;

    int c = tid;
    const float* fb = g_buf + OF_FEATT + (long)b * HW * Cc + c;
    float acc[49];
#pragma unroll
    for (int s = 0; s < 49; s++) acc[s] = 0.0f;
    pool_channel_acc(fb, Cc, wy, wx, h0, h1, w0, w1, acc);

    float* X = g_buf + OF_XOBJ + ((long)b * 512 + c) * 784 + (long)n * 49;
#pragma unroll
    for (int s = 0; s < 49; s++) X[s] = acc[s] * inv;
}

// ---------------------------------------------------------------------------
__global__ void __launch_bounds__(256) pool_ctx_kernel()
{
    using namespace sg;
    int b = blockIdx.x, tid = threadIdx.x;
    __shared__ float wy[7][16], wx[7][24];
    __shared__ int h0[7], h1[7], w0[7], w1[7];
    compute_weights(0.0f, 0.0f, 24.0f, 16.0f, wy, wx, h0, h1, w0, w1, tid);
    __syncthreads();

    float inv = 49.0f / (24.0f * 16.0f);
    int c = tid;
    const float* fb = g_buf + OF_CTXF + ((long)b * Cc + c) * HW;
    float acc[49];
#pragma unroll
    for (int s = 0; s < 49; s++) acc[s] = 0.0f;
    pool_channel_acc(fb, 1, wy, wx, h0, h1, w0, w1, acc);
    float* X = g_buf + OF_PCTX + ((long)b * Cc + c) * PP;
#pragma unroll
    for (int s = 0; s < 49; s++) X[s] = acc[s] * inv;
}

// ---------------------------------------------------------------------------
__global__ void pack_xobj_kernel()
{
    using namespace sg;
    int b = blockIdx.y;
    int base = blockIdx.x * blockDim.x + threadIdx.x;
    int stride = gridDim.x * blockDim.x;
    for (int idx = base; idx < 256 * 784; idx += stride) {
        int cc = idx / 784, rem = idx - cc * 784;
        int n = rem / 49, s = rem - n * 49;
        float v = g_buf[OF_PCTX + ((long)b * Cc + cc) * PP + s];
        if (cc >= 128) v *= g_buf[OF_BIMAP + ((long)b * Nn + n) * PP + s];
        g_buf[OF_XOBJ + ((long)b * 512 + 256 + cc) * 784 + rem] = v;
    }
}

// ---------------------------------------------------------------------------
__global__ void __launch_bounds__(384) pool_rel_kernel(const float* __restrict__ boxes)
{
    using namespace sg;
    extern __shared__ float stage[];
    int b = blockIdx.y, pair = blockIdx.x, tid = threadIdx.x;
    int i = pair >> 4, j = pair & 15;
    const float* bi = boxes + ((long)b * Nn + i) * 4;
    const float* bj = boxes + ((long)b * Nn + j) * 4;
    float ix1 = bi[0], iy1 = bi[1], ix2 = bi[2], iy2 = bi[3];
    float jx1 = bj[0], jy1 = bj[1], jx2 = bj[2], jy2 = bj[3];
    float ux1 = fminf(ix1, jx1), uy1 = fminf(iy1, jy1);
    float ux2 = fmaxf(ix2, jx2), uy2 = fmaxf(iy2, jy2);
    float sx1 = ux1 * SCALE, sy1 = uy1 * SCALE, sx2 = ux2 * SCALE, sy2 = uy2 * SCALE;

    __shared__ float wy[7][16], wx[7][24];
    __shared__ int h0[7], h1[7], w0[7], w1[7];
    __shared__ float subm[49], objm[49];
    compute_weights(sx1, sy1, sx2, sy2, wy, wx, h0, h1, w0, w1, tid);

    if (tid < 49) {
        int p = tid / 7, q = tid - p * 7;
        float ye0 = uy1 + (uy2 - uy1) * (float)p * (1.0f / 7.0f);
        float ye1 = uy1 + (uy2 - uy1) * (float)(p + 1) * (1.0f / 7.0f);
        float xe0 = ux1 + (ux2 - ux1) * (float)q * (1.0f / 7.0f);
        float xe1 = ux1 + (ux2 - ux1) * (float)(q + 1) * (1.0f / 7.0f);
        float ch = fmaxf((uy2 - uy1) * (1.0f / 7.0f), 1e-9f);
        float cw = fmaxf((ux2 - ux1) * (1.0f / 7.0f), 1e-9f);
        float oy = fmaxf(fminf(ye1, iy2) - fmaxf(ye0, iy1), 0.0f);
        float ox = fmaxf(fminf(xe1, ix2) - fmaxf(xe0, ix1), 0.0f);
        subm[tid] = (oy / ch) * (ox / cw);
        oy = fmaxf(fminf(ye1, jy2) - fmaxf(ye0, jy1), 0.0f);
        ox = fmaxf(fminf(xe1, jx2) - fmaxf(xe0, jx1), 0.0f);
        objm[tid] = (oy / ch) * (ox / cw);
    }
    __syncthreads();

    float area = (sx2 - sx1) * (sy2 - sy1) * (1.0f / 49.0f);
    float inv = (area > 0.0f) ? 1.0f / fmaxf(area, 1e-9f) : 0.0f;

    int c = tid;
    const float* fb = g_buf + OF_RELFT + (long)b * HW * C32 + c;
    float acc[49];
#pragma unroll
    for (int s = 0; s < 49; s++) acc[s] = 0.0f;
    pool_channel_acc(fb, C32, wy, wx, h0, h1, w0, w1, acc);

#pragma unroll
    for (int s = 0; s < 49; s++) {
        float mk = (c < 128) ? 1.0f : (c < 256 ? subm[s] : objm[s]);
        stage[c * 49 + s] = acc[s] * inv * mk;
    }
    __syncthreads();

    float* X = g_buf + OF_XREL + (long)b * C32 * KFC + (long)pair * 49;
    for (int idx = tid; idx < C32 * 49; idx += 384) {
        int cc = idx / 49, ss = idx - cc * 49;
        X[(long)cc * KFC + ss] = stage[idx];
    }
}

// ---------------------------------------------------------------------------
__global__ void combine_rel_kernel(const float* __restrict__ brf)
{
    using namespace sg;
    __shared__ float t[32][33];
    int b = blockIdx.z;
    int o = blockIdx.y >> 1;
    int st = (blockIdx.y & 1) * 32;
    int pt = blockIdx.x * 32;
    int tx = threadIdx.x, ty = threadIdx.y;
    const float* rel5 = g_buf + OF_REL5 + ((long)b * 256 + o) * KFC;
    const float* A1   = g_buf + OF_ASUB + ((long)b * 256 + o) * 784;
    const float* A2   = g_buf + OF_AOBJ + ((long)b * 256 + o) * 784;
    float bias = brf[o];
    int s = st + tx;
    if (s < 49) {
#pragma unroll
        for (int k = 0; k < 32; k += 8) {
            int pair = pt + ty + k;
            int i = pair >> 4, j = pair & 15;
            float v = rel5[(long)pair * 49 + s] + A1[i * 49 + s] + A2[j * 49 + s] + bias;
            t[ty + k][tx] = fmaxf(v, 0.0f);
        }
    }
    __syncthreads();
#pragma unroll
    for (int k = 0; k < 32; k += 8) {
        int sw = st + ty + k;
        if (sw < 49)
            g_buf[OF_R + (long)(o * 49 + sw) * 2048 + (long)b * 256 + pt + tx] = t[tx][ty + k];
    }
}

// ---------------------------------------------------------------------------
__global__ void combine_obj_kernel()
{
    using namespace sg;
    long idx = (long)blockIdx.x * blockDim.x + threadIdx.x;
    if (idx >= (long)KFC * 128) return;
    int row = (int)(idx >> 7), col = (int)(idx & 127);
    int o = row / 49, s = row - o * 49;
    int b = col >> 4, i = col & 15;
    float v = g_buf[OF_OBJ + ((long)b * 256 + o) * 784 + i * 49 + s];
    g_buf[OF_ROBJ + idx] = fmaxf(v, 0.0f);
}

// ---------------------------------------------------------------------------
__global__ void finalize_kernel(long srcOff, int ncols, float* __restrict__ out)
{
    int col = blockIdx.x, n = threadIdx.x;
    float v = g_buf[srcOff + (long)n * ncols + col];
    float s = v * v;
#pragma unroll
    for (int o = 16; o > 0; o >>= 1) s += __shfl_xor_sync(0xffffffffu, s, o);
    __shared__ float red[8];
    if ((n & 31) == 0) red[n >> 5] = s;
    __syncthreads();
    float tot = red[0] + red[1] + red[2] + red[3] + red[4] + red[5] + red[6] + red[7];
    out[(long)col * 256 + n] = v / sqrtf(tot);
}

// ---------------------------------------------------------------------------
extern "C" void kernel_launch(void* const* d_in, const int* in_sizes, int n_in,
                              void* d_out, int out_size)
{
    using namespace sg;
    const float* input = (const float*)d_in[0];
    const float* boxes = (const float*)d_in[1];
    const float* W_ctx = (const float*)d_in[3];
    const float* b_ctx = (const float*)d_in[4];
    const float* W_rel = (const float*)d_in[5];
    const float* b_rel = (const float*)d_in[6];
    const float* W_of  = (const float*)d_in[7];
    const float* b_of  = (const float*)d_in[8];
    const float* W_rf  = (const float*)d_in[9];
    const float* b_rf  = (const float*)d_in[10];
    const float* W_ofc = (const float*)d_in[11];
    const float* b_ofc = (const float*)d_in[12];
    const float* W_rfc = (const float*)d_in[13];
    const float* b_rfc = (const float*)d_in[14];
    float* out = (float*)d_out;

    const long sFeat = (long)Cc * HW;       // 98304
    const long sRelf = (long)C32 * HW;      // 147456
    const long s784  = 256L * 784;          // 200704

    // 1. ctx conv
    sgemm_kernel<<<dim3(6, 4, 8), 256>>>(W_ctx, 0, 256, 0, input, 0, 384, sFeat,
                                         OF_CTXF, 384, sFeat, 256, 384, 256, b_ctx);
    // 2. rel conv
    sgemm_kernel<<<dim3(6, 6, 8), 256>>>(W_rel, 0, 256, 0, input, 0, 384, sFeat,
                                         OF_RELF, 384, sRelf, 384, 384, 256, b_rel);
    // 3. featT
    transpose_kernel<<<dim3(12, 8, 8), dim3(32, 8)>>>(input, 0, OF_FEATT, 256, 384);
    // 4. relfT
    transpose_kernel<<<dim3(12, 12, 8), dim3(32, 8)>>>(nullptr, OF_RELF, OF_RELFT, 384, 384);
    // 5. pool ctx
    pool_ctx_kernel<<<8, 256>>>();
    // 6. pool obj boxes
    pool_obj_kernel<<<dim3(16, 8), 256>>>(boxes);
    // 7. pack ctx-pooled channels into Xobj
    pack_xobj_kernel<<<dim3(16, 8), 256>>>();
    // 8. obj conv: [256,784] = W_of[256,512] x Xobj[512,784]
    sgemm128_kernel<<<dim3(7, 2, 8), 256>>>(W_of, 0, 512, OF_XOBJ, 784, 512L * 784,
                                            OF_OBJ, 784, s784, 784, 512, 512, 1, b_of);
    // 9. A_sub = W_rf[:,0:256] x obj
    sgemm128_kernel<<<dim3(7, 2, 8), 256>>>(W_rf, 0, 896, OF_OBJ, 784, s784,
                                            OF_ASUB, 784, s784, 784, 256, 256, 1, nullptr);
    // 10. A_obj = W_rf[:,256:512] x obj
    sgemm128_kernel<<<dim3(7, 2, 8), 256>>>(W_rf, 256, 896, OF_OBJ, 784, s784,
                                            OF_AOBJ, 784, s784, 784, 256, 256, 1, nullptr);
    // 11. pool rel feat over union boxes -> Xrel
    cudaFuncSetAttribute(pool_rel_kernel, cudaFuncAttributeMaxDynamicSharedMemorySize, 384 * 49 * 4);
    pool_rel_kernel<<<dim3(256, 8), 384, 384 * 49 * 4>>>(boxes);
    // 12. pair GEMM: rel5[256,12544] = W_rf[:,512:896] x Xrel[384,12544]
    sgemm128_kernel<<<dim3(98, 2, 8), 256>>>(W_rf, 512, 896, OF_XREL, KFC, (long)C32 * KFC,
                                             OF_REL5, KFC, 256L * KFC, KFC, 384, 384, 1, nullptr);
    // 13. combine + relu + transpose -> Rt[12544][2048]
    combine_rel_kernel<<<dim3(8, 512, 8), dim3(32, 8)>>>(b_rf);
    // 14. rel FC split-K8: partial[8][256][2048] = W_rfc x Rt chunks
    sgemm128_kernel<<<dim3(16, 2, 8), 256>>>(W_rfc, 0, KFC, OF_R, 2048, 0,
                                             OF_FP, 2048, 256L * 2048, 2048, KFC, 1568, 8, nullptr);
    reduce_split_kernel<<<2048, 256>>>(OF_FP, OF_FREL, 256L * 2048, 2048, 8, b_rfc);
    // 15. relu(obj) transpose -> Robj[12544][128]
    combine_obj_kernel<<<(int)(((long)KFC * 128 + 255) / 256), 256>>>();
    // 16. obj FC split-K32: partial[32][256][128]
    sgemm128_kernel<<<dim3(1, 2, 32), 256>>>(W_ofc, 0, KFC, OF_ROBJ, 128, 0,
                                             OF_FPO, 128, 256L * 128, 128, KFC, 392, 32, nullptr);
    reduce_split_kernel<<<128, 256>>>(OF_FPO, OF_FOBJ, 256L * 128, 128, 32, b_ofc);
    // 17. l2norm obj -> out[0 : 32768]
    finalize_kernel<<<128, 256>>>(OF_FOBJ, 128, out);
    // 18. l2norm rel -> out[32768 : ]
    finalize_kernel<<<2048, 256>>>(OF_FREL, 2048, out + 32768);
}

// round 5
// speedup vs baseline: 1.9852x; 1.1183x over previous
#include <cuda_runtime.h>
#include <cuda_bf16.h>
#include <math.h>
#include <stdint.h>

namespace sg {
constexpr int Bn = 8, Cc = 256, Nn = 16;
constexpr int HW = 384;
constexpr int C32 = 384;
constexpr float SCALE = 1.0f / 16.0f;
constexpr float IMGW = 384.0f, IMGH = 256.0f;
constexpr int PP = 49;
constexpr int KFC = 12544;            // 256*49
constexpr int SPLK = 14;              // rel FC split-K  (14*896 = 12544)
constexpr int SPLKO = 49;             // obj FC split-K  (49*256 = 12544)

constexpr long SZ_CTXF  = (long)Bn * Cc * HW;
constexpr long SZ_RELF  = (long)Bn * C32 * HW;
constexpr long SZ_FEATT = SZ_CTXF;
constexpr long SZ_RELFT = SZ_RELF;
constexpr long SZ_PCTX  = (long)Bn * Cc * PP;
constexpr long SZ_BIMAP = (long)Bn * Nn * PP;
constexpr long SZ_XOBJ  = (long)Bn * 512 * 784;
constexpr long SZ_OBJ   = (long)Bn * 256 * 784;
constexpr long SZ_ASUB  = SZ_OBJ;
constexpr long SZ_AOBJ  = SZ_OBJ;
constexpr long SZ_REL5  = (long)Bn * 256 * KFC;
constexpr long SZ_FREL  = 256L * 2048;
constexpr long SZ_FOBJ  = 256L * 128;
constexpr long SZ_FP    = (long)SPLK * 256 * 2048;
constexpr long SZ_FPO   = (long)SPLKO * 256 * 128;
// bf16 buffers (sizes in float units = bf16count/2)
constexpr long FU_WP  = 256L * 384 / 2;
constexpr long FU_XRT = (long)Bn * KFC * 384 / 2;
constexpr long FU_WR  = 256L * KFC / 2;
constexpr long FU_RT  = 2048L * KFC / 2;
constexpr long FU_WO  = FU_WR;
constexpr long FU_RO  = 128L * KFC / 2;

constexpr long OF_CTXF  = 0;
constexpr long OF_RELF  = OF_CTXF  + SZ_CTXF;
constexpr long OF_FEATT = OF_RELF  + SZ_RELF;
constexpr long OF_RELFT = OF_FEATT + SZ_FEATT;
constexpr long OF_PCTX  = OF_RELFT + SZ_RELFT;
constexpr long OF_BIMAP = OF_PCTX  + SZ_PCTX;
constexpr long OF_XOBJ  = OF_BIMAP + SZ_BIMAP;
constexpr long OF_OBJ   = OF_XOBJ  + SZ_XOBJ;
constexpr long OF_ASUB  = OF_OBJ   + SZ_OBJ;
constexpr long OF_AOBJ  = OF_ASUB  + SZ_ASUB;
constexpr long OF_REL5  = OF_AOBJ  + SZ_AOBJ;
constexpr long OF_FREL  = OF_REL5  + SZ_REL5;
constexpr long OF_FOBJ  = OF_FREL  + SZ_FREL;
constexpr long OF_FP    = OF_FOBJ  + SZ_FOBJ;
constexpr long OF_FPO   = OF_FP    + SZ_FP;
constexpr long OF_WPH   = OF_FPO   + SZ_FPO;
constexpr long OF_WPL   = OF_WPH   + FU_WP;
constexpr long OF_XRTH  = OF_WPL   + FU_WP;
constexpr long OF_XRTL  = OF_XRTH  + FU_XRT;
constexpr long OF_WRH   = OF_XRTL  + FU_XRT;
constexpr long OF_WRL   = OF_WRH   + FU_WR;
constexpr long OF_RTH   = OF_WRL   + FU_WR;
constexpr long OF_RTL   = OF_RTH   + FU_RT;
constexpr long OF_WOH   = OF_RTL   + FU_RT;
constexpr long OF_WOL   = OF_WOH   + FU_WO;
constexpr long OF_ROH   = OF_WOL   + FU_WO;
constexpr long OF_ROL   = OF_ROH   + FU_RO;
constexpr long TOTAL    = OF_ROL   + FU_RO;
}  // namespace sg

__device__ float g_buf[sg::TOTAL];

// ========================= low-level helpers ===============================
__device__ __forceinline__ uint32_t smem_u32(const void* p) {
    uint32_t a;
    asm("{ .reg .u64 t; cvta.to.shared.u64 t, %1; cvt.u32.u64 %0, t; }" : "=r"(a) : "l"(p));
    return a;
}
__device__ __forceinline__ void cp_async16(uint32_t dst, const void* src) {
    asm volatile("cp.async.cg.shared.global [%0], [%1], 16;" :: "r"(dst), "l"(src));
}
__device__ __forceinline__ void cp_commit() {
    asm volatile("cp.async.commit_group;" ::: "memory");
}
__device__ __forceinline__ void ldsm4(uint32_t* a, uint32_t addr) {
    asm volatile("ldmatrix.sync.aligned.m8n8.x4.shared.b16 {%0,%1,%2,%3}, [%4];"
        : "=r"(a[0]), "=r"(a[1]), "=r"(a[2]), "=r"(a[3]) : "r"(addr));
}
__device__ __forceinline__ void ldsm2(uint32_t* b, uint32_t addr) {
    asm volatile("ldmatrix.sync.aligned.m8n8.x2.shared.b16 {%0,%1}, [%2];"
        : "=r"(b[0]), "=r"(b[1]) : "r"(addr));
}
__device__ __forceinline__ void mma16816(float* d, const uint32_t* a, const uint32_t* b) {
    asm volatile("mma.sync.aligned.m16n8k16.row.col.f32.bf16.bf16.f32 "
        "{%0,%1,%2,%3}, {%4,%5,%6,%7}, {%8,%9}, {%0,%1,%2,%3};"
        : "+f"(d[0]), "+f"(d[1]), "+f"(d[2]), "+f"(d[3])
        : "r"(a[0]), "r"(a[1]), "r"(a[2]), "r"(a[3]), "r"(b[0]), "r"(b[1]));
}
__device__ __forceinline__ void split_bf16(float x, __nv_bfloat16& h, __nv_bfloat16& l) {
    h = __float2bfloat16(x);
    l = __float2bfloat16(x - __bfloat162float(h));
}

// ========================= PrRoI pooling helpers ===========================
static __device__ __forceinline__ float hatG(float t) {
    float tl = fminf(fmaxf(t, -1.0f), 0.0f);
    float tr = fminf(fmaxf(t, 0.0f), 1.0f);
    return 0.5f * (tl + 1.0f) * (tl + 1.0f) + 0.5f - 0.5f * (1.0f - tr) * (1.0f - tr);
}

static __device__ __forceinline__ void compute_weights(
    float x1, float y1, float x2, float y2,
    float (*wy)[16], float (*wx)[24],
    int* h0, int* h1, int* w0, int* w1, int tid)
{
    if (tid < 112) {
        int p = tid / 16, i = tid % 16;
        float e0 = y1 + (y2 - y1) * (float)p * (1.0f / 7.0f);
        float e1 = y1 + (y2 - y1) * (float)(p + 1) * (1.0f / 7.0f);
        wy[p][i] = hatG(e1 - (float)i) - hatG(e0 - (float)i);
    }
    if (tid < 168) {
        int q = tid / 24, i = tid % 24;
        float e0 = x1 + (x2 - x1) * (float)q * (1.0f / 7.0f);
        float e1 = x1 + (x2 - x1) * (float)(q + 1) * (1.0f / 7.0f);
        wx[q][i] = hatG(e1 - (float)i) - hatG(e0 - (float)i);
    }
    if (tid < 7) {
        float e0 = y1 + (y2 - y1) * (float)tid * (1.0f / 7.0f);
        float e1 = y1 + (y2 - y1) * (float)(tid + 1) * (1.0f / 7.0f);
        h0[tid] = max(0, (int)floorf(e0) - 1);
        h1[tid] = min(16, (int)ceilf(e1) + 2);
    }
    if (tid >= 32 && tid < 39) {
        int q = tid - 32;
        float e0 = x1 + (x2 - x1) * (float)q * (1.0f / 7.0f);
        float e1 = x1 + (x2 - x1) * (float)(q + 1) * (1.0f / 7.0f);
        w0[q] = max(0, (int)floorf(e0) - 1);
        w1[q] = min(24, (int)ceilf(e1) + 2);
    }
}

static __device__ __forceinline__ void pool_channel_acc(
    const float* __restrict__ fb, int ps,
    const float (*wy)[16], const float (*wx)[24],
    const int* h0, const int* h1, const int* w0, const int* w1,
    float* acc)
{
#pragma unroll
    for (int p = 0; p < 7; p++) {
        for (int h = h0[p]; h < h1[p]; h++) {
            float wyv = wy[p][h];
            const float* row = fb + (long)h * 24 * ps;
#pragma unroll
            for (int q = 0; q < 7; q++) {
                float a = 0.0f;
                for (int w = w0[q]; w < w1[q]; w++)
                    a += wx[q][w] * row[(long)w * ps];
                acc[p * 7 + q] += wyv * a;
            }
        }
    }
}

// ============================ fp32 GEMM paths ==============================
__global__ void __launch_bounds__(256) sgemm_kernel(
    const float* __restrict__ Aext, long offA, int lda, long sAb,
    const float* __restrict__ Bext, long offB, int ldb, long sBb,
    long offC, int ldc, long sCb,
    int M, int N, int K, const float* __restrict__ bias)
{
    const int b = blockIdx.z;
    const float* A  = (Aext ? Aext + offA : g_buf + offA) + (long)b * sAb;
    const float* Bm = (Bext ? Bext + offB : g_buf + offB) + (long)b * sBb;
    float* Cm = g_buf + offC + (long)b * sCb;

    __shared__ float As[16][65];
    __shared__ float Bs[16][68];

    const int tid = threadIdx.x;
    const int row0 = blockIdx.y * 64;
    const int col0 = blockIdx.x * 64;
    const int ty = tid >> 4, tx = tid & 15;
    const int ty4 = ty * 4, tx4 = tx * 4;
    const int ar = tid >> 2;
    const int ak = (tid & 3) << 2;
    const int br = tid >> 4;
    const int bc = (tid & 15) << 2;

    float acc[4][4] = {};

    for (int k0 = 0; k0 < K; k0 += 16) {
        float4 av = *(const float4*)(A + (long)(row0 + ar) * lda + k0 + ak);
        As[ak + 0][ar] = av.x; As[ak + 1][ar] = av.y;
        As[ak + 2][ar] = av.z; As[ak + 3][ar] = av.w;

        const float* bp = Bm + (long)(k0 + br) * ldb + col0 + bc;
        float4 bv;
        if (col0 + bc + 3 < N) {
            bv = *(const float4*)bp;
        } else {
            bv.x = (col0 + bc + 0 < N) ? bp[0] : 0.0f;
            bv.y = (col0 + bc + 1 < N) ? bp[1] : 0.0f;
            bv.z = (col0 + bc + 2 < N) ? bp[2] : 0.0f;
            bv.w = 0.0f;
        }
        *(float4*)&Bs[br][bc] = bv;
        __syncthreads();

#pragma unroll
        for (int k = 0; k < 16; k++) {
            float a0 = As[k][ty4 + 0], a1 = As[k][ty4 + 1];
            float a2 = As[k][ty4 + 2], a3 = As[k][ty4 + 3];
            float4 b4 = *(const float4*)&Bs[k][tx4];
            acc[0][0] += a0 * b4.x; acc[0][1] += a0 * b4.y; acc[0][2] += a0 * b4.z; acc[0][3] += a0 * b4.w;
            acc[1][0] += a1 * b4.x; acc[1][1] += a1 * b4.y; acc[1][2] += a1 * b4.z; acc[1][3] += a1 * b4.w;
            acc[2][0] += a2 * b4.x; acc[2][1] += a2 * b4.y; acc[2][2] += a2 * b4.z; acc[2][3] += a2 * b4.w;
            acc[3][0] += a3 * b4.x; acc[3][1] += a3 * b4.y; acc[3][2] += a3 * b4.z; acc[3][3] += a3 * b4.w;
        }
        __syncthreads();
    }

#pragma unroll
    for (int u = 0; u < 4; u++) {
        int r = row0 + ty4 + u;
        float bz = bias ? bias[r] : 0.0f;
#pragma unroll
        for (int v = 0; v < 4; v++) {
            int cidx = col0 + tx4 + v;
            if (cidx < N) Cm[(long)r * ldc + cidx] = acc[u][v] + bz;
        }
    }
}

__global__ void __launch_bounds__(256) sgemm128_kernel(
    const float* __restrict__ Aex, long offA, int lda,
    long offB, int ldb, long sBb,
    long offC, int ldc, long sCb,
    int N, int K, int kChunk, int splitK,
    const float* __restrict__ bias)
{
    __shared__ float As[2][8][132];
    __shared__ float Bs[2][8][132];

    const int z = blockIdx.z;
    const int b = z / splitK;
    const int ks = z - b * splitK;
    const int kBeg = ks * kChunk;
    const int kEnd = min(K, kBeg + kChunk);
    const int nk = (kEnd - kBeg) >> 3;

    const float* A = Aex + offA;
    const float* B = g_buf + offB + (long)b * sBb;
    float* C = g_buf + offC + (long)z * sCb;

    const int t = threadIdx.x;
    const int row0 = blockIdx.y * 128, col0 = blockIdx.x * 128;
    const int arow = t >> 1, akq = (t & 1) << 2;
    const int brow = t >> 5, bcol = (t & 31) << 2;
    const int tx = t & 15, ty = t >> 4;

    const float* aPtr = A + (long)(row0 + arow) * lda + kBeg + akq;
    const float* bPtr = B + (long)(kBeg + brow) * ldb + col0 + bcol;
    const bool bIn = (col0 + bcol + 3) < N;

    float4 pa = *(const float4*)aPtr;
    float4 pb;
    if (bIn) {
        pb = *(const float4*)bPtr;
    } else {
        pb.x = (col0 + bcol + 0 < N) ? bPtr[0] : 0.0f;
        pb.y = (col0 + bcol + 1 < N) ? bPtr[1] : 0.0f;
        pb.z = (col0 + bcol + 2 < N) ? bPtr[2] : 0.0f;
        pb.w = 0.0f;
    }
    As[0][akq + 0][arow] = pa.x; As[0][akq + 1][arow] = pa.y;
    As[0][akq + 2][arow] = pa.z; As[0][akq + 3][arow] = pa.w;
    *(float4*)&Bs[0][brow][bcol] = pb;
    __syncthreads();

    float acc[8][8] = {};

    for (int kt = 0; kt < nk; kt++) {
        const int buf = kt & 1;
        if (kt + 1 < nk) {
            pa = *(const float4*)(aPtr + (kt + 1) * 8);
            const float* bp = bPtr + (long)(kt + 1) * 8 * ldb;
            if (bIn) {
                pb = *(const float4*)bp;
            } else {
                pb.x = (col0 + bcol + 0 < N) ? bp[0] : 0.0f;
                pb.y = (col0 + bcol + 1 < N) ? bp[1] : 0.0f;
                pb.z = (col0 + bcol + 2 < N) ? bp[2] : 0.0f;
                pb.w = 0.0f;
            }
        }
#pragma unroll
        for (int kk = 0; kk < 8; kk++) {
            float4 a0 = *(const float4*)&As[buf][kk][ty * 4];
            float4 a1 = *(const float4*)&As[buf][kk][64 + ty * 4];
            float4 b0 = *(const float4*)&Bs[buf][kk][tx * 4];
            float4 b1 = *(const float4*)&Bs[buf][kk][64 + tx * 4];
            float av[8] = {a0.x, a0.y, a0.z, a0.w, a1.x, a1.y, a1.z, a1.w};
            float bv[8] = {b0.x, b0.y, b0.z, b0.w, b1.x, b1.y, b1.z, b1.w};
#pragma unroll
            for (int u = 0; u < 8; u++)
#pragma unroll
                for (int v = 0; v < 8; v++)
                    acc[u][v] += av[u] * bv[v];
        }
        if (kt + 1 < nk) {
            const int nb = buf ^ 1;
            As[nb][akq + 0][arow] = pa.x; As[nb][akq + 1][arow] = pa.y;
            As[nb][akq + 2][arow] = pa.z; As[nb][akq + 3][arow] = pa.w;
            *(float4*)&Bs[nb][brow][bcol] = pb;
            __syncthreads();
        }
    }

#pragma unroll
    for (int u = 0; u < 8; u++) {
        int r = row0 + ((u < 4) ? ty * 4 + u : 64 + ty * 4 + (u - 4));
        float bz = bias ? bias[r] : 0.0f;
#pragma unroll
        for (int v = 0; v < 8; v++) {
            int c = col0 + ((v < 4) ? tx * 4 + v : 64 + tx * 4 + (v - 4));
            if (c < N) C[(long)r * ldc + c] = acc[u][v] + bz;
        }
    }
}

// ================ HMMA (mma.sync) bf16-split GEMM ==========================
// C[z] = split(A) x split(B^T)^T with 3 terms (hh, hl, lh).
// A: [M][lda] bf16 hi/lo; BT: [N][ldb] bf16 hi/lo. Tile 128x128, kstep 32.
// batchB=1: z indexes images (B, C strided). batchB=0: z = split-K chunk.
// M = grid.y*128 rows, N = grid.x*128 cols (both exact multiples).
__global__ void __launch_bounds__(256) hmma_gemm_kernel(
    long offAhi, long offAlo, int lda,
    long offBhi, long offBlo, int ldb, long sBz,
    long offC, int ldc, long sCz,
    int kChunk, int batchB)
{
    extern __shared__ __nv_bfloat16 smb[];
    constexpr int STR = 48;                    // row stride (bf16): 96B, 16B-aligned
    __nv_bfloat16* As = smb;                   // [2][128][STR]
    __nv_bfloat16* Bs = smb + 2 * 128 * STR;   // [2][128][STR]

    const int tid = threadIdx.x;
    const int warp = tid >> 5, lane = tid & 31;
    const int z = blockIdx.z;
    const int row0 = blockIdx.y * 128, col0 = blockIdx.x * 128;
    const long kBeg = batchB ? 0 : (long)z * kChunk;
    const int S = (kChunk / 32) * 3;

    const __nv_bfloat16* Ahi = (const __nv_bfloat16*)(g_buf + offAhi);
    const __nv_bfloat16* Alo = (const __nv_bfloat16*)(g_buf + offAlo);
    const __nv_bfloat16* Bhi = (const __nv_bfloat16*)(g_buf + offBhi) + (batchB ? (long)z * sBz : 0);
    const __nv_bfloat16* Blo = (const __nv_bfloat16*)(g_buf + offBlo) + (batchB ? (long)z * sBz : 0);
    float* C = g_buf + offC + (long)z * sCz;

    const int wm = (warp >> 2) * 64;          // 2x4 warp grid: 64x32 per warp
    const int wn = (warp & 3) * 32;

    float acc[4][4][4];
#pragma unroll
    for (int a = 0; a < 4; a++)
#pragma unroll
        for (int b = 0; b < 4; b++)
#pragma unroll
            for (int c = 0; c < 4; c++) acc[a][b][c] = 0.0f;

    const uint32_t asm_base = smem_u32(As);
    const uint32_t bsm_base = smem_u32(Bs);

    auto issue_load = [&](int s, int buf) {
        int c = s / 3, term = s - c * 3;
        const __nv_bfloat16* Ab = (term == 2) ? Alo : Ahi;
        const __nv_bfloat16* Bb = (term == 1) ? Blo : Bhi;
        long koff = kBeg + (long)c * 32;
#pragma unroll
        for (int i = 0; i < 2; i++) {
            int idx = tid + i * 256;
            int r = idx >> 2, cg = (idx & 3) * 8;
            cp_async16(asm_base + ((buf * 128 + r) * STR + cg) * 2,
                       Ab + (long)(row0 + r) * lda + koff + cg);
            cp_async16(bsm_base + ((buf * 128 + r) * STR + cg) * 2,
                       Bb + (long)(col0 + r) * ldb + koff + cg);
        }
        cp_commit();
    };

    issue_load(0, 0);

    for (int s = 0; s < S; s++) {
        if (s + 1 < S) {
            issue_load(s + 1, (s + 1) & 1);
            asm volatile("cp.async.wait_group 1;" ::: "memory");
        } else {
            asm volatile("cp.async.wait_group 0;" ::: "memory");
        }
        __syncthreads();

        const int buf = s & 1;
        const uint32_t aB = asm_base + (uint32_t)buf * 128 * STR * 2;
        const uint32_t bB = bsm_base + (uint32_t)buf * 128 * STR * 2;
        const int lr = lane & 15;
#pragma unroll
        for (int k16 = 0; k16 < 2; k16++) {
            uint32_t af[4][4], bf[4][2];
#pragma unroll
            for (int mi = 0; mi < 4; mi++) {
                uint32_t addr = aB + (((wm + mi * 16 + (lane & 15)) * STR)
                                      + k16 * 16 + (lane >> 4) * 8) * 2;
                ldsm4(af[mi], addr);
            }
#pragma unroll
            for (int ni = 0; ni < 4; ni++) {
                uint32_t addr = bB + (((wn + ni * 8 + (lr & 7)) * STR)
                                      + k16 * 16 + (lr >> 3) * 8) * 2;
                ldsm2(bf[ni], addr);
            }
#pragma unroll
            for (int mi = 0; mi < 4; mi++)
#pragma unroll
                for (int ni = 0; ni < 4; ni++)
                    mma16816(acc[mi][ni], af[mi], bf[ni]);
        }
        __syncthreads();
    }

#pragma unroll
    for (int mi = 0; mi < 4; mi++) {
        int r = row0 + wm + mi * 16 + (lane >> 2);
#pragma unroll
        for (int ni = 0; ni < 4; ni++) {
            int cc = col0 + wn + ni * 8 + (lane & 3) * 2;
            *(float2*)&C[(long)r * ldc + cc] = make_float2(acc[mi][ni][0], acc[mi][ni][1]);
            *(float2*)&C[(long)(r + 8) * ldc + cc] = make_float2(acc[mi][ni][2], acc[mi][ni][3]);
        }
    }
}

// ==================== misc data-movement / pooling =========================
__global__ void transpose_kernel(const float* __restrict__ srcExt,
                                 long offSrc, long offDst, int R, int C)
{
    __shared__ float tile[32][33];
    int b = blockIdx.z;
    const float* src = (srcExt ? srcExt : (const float*)g_buf + offSrc) + (long)b * R * C;
    float* dst = g_buf + offDst + (long)b * R * C;
    int c0 = blockIdx.x * 32, r0 = blockIdx.y * 32;
    int tx = threadIdx.x, ty = threadIdx.y;
#pragma unroll
    for (int k = 0; k < 32; k += 8)
        tile[ty + k][tx] = src[(long)(r0 + ty + k) * C + c0 + tx];
    __syncthreads();
#pragma unroll
    for (int k = 0; k < 32; k += 8)
        dst[(long)(c0 + ty + k) * R + r0 + tx] = tile[tx][ty + k];
}

__global__ void __launch_bounds__(256) pool_obj_kernel(const float* __restrict__ boxes)
{
    using namespace sg;
    int b = blockIdx.y, n = blockIdx.x, tid = threadIdx.x;
    const float* bx = boxes + ((long)b * Nn + n) * 4;
    float x1 = bx[0], y1 = bx[1], x2 = bx[2], y2 = bx[3];
    float sx1 = x1 * SCALE, sy1 = y1 * SCALE, sx2 = x2 * SCALE, sy2 = y2 * SCALE;

    __shared__ float wy[7][16], wx[7][24];
    __shared__ int h0[7], h1[7], w0[7], w1[7];
    compute_weights(sx1, sy1, sx2, sy2, wy, wx, h0, h1, w0, w1, tid);

    if (tid < 49) {
        int p = tid / 7, q = tid % 7;
        float ye0 = IMGH * (float)p * (1.0f / 7.0f), ye1 = IMGH * (float)(p + 1) * (1.0f / 7.0f);
        float xe0 = IMGW * (float)q * (1.0f / 7.0f), xe1 = IMGW * (float)(q + 1) * (1.0f / 7.0f);
        float oy = fmaxf(fminf(ye1, y2) - fmaxf(ye0, y1), 0.0f);
        float ox = fmaxf(fminf(xe1, x2) - fmaxf(xe0, x1), 0.0f);
        float ch = IMGH * (1.0f / 7.0f), cw = IMGW * (1.0f / 7.0f);
        g_buf[OF_BIMAP + ((long)b * Nn + n) * PP + tid] = (oy / ch) * (ox / cw);
    }
    __syncthreads();

    float area = (sx2 - sx1) * (sy2 - sy1) * (1.0f / 49.0f);
    float inv = (area > 0.0f) ? 1.0f / fmaxf(area, 1e-9f) : 0.0f;

    int c = tid;
    const float* fb = g_buf + OF_FEATT + (long)b * HW * Cc + c;
    float acc[49];
#pragma unroll
    for (int s = 0; s < 49; s++) acc[s] = 0.0f;
    pool_channel_acc(fb, Cc, wy, wx, h0, h1, w0, w1, acc);

    float* X = g_buf + OF_XOBJ + ((long)b * 512 + c) * 784 + (long)n * 49;
#pragma unroll
    for (int s = 0; s < 49; s++) X[s] = acc[s] * inv;
}

__global__ void __launch_bounds__(256) pool_ctx_kernel()
{
    using namespace sg;
    int b = blockIdx.x, tid = threadIdx.x;
    __shared__ float wy[7][16], wx[7][24];
    __shared__ int h0[7], h1[7], w0[7], w1[7];
    compute_weights(0.0f, 0.0f, 24.0f, 16.0f, wy, wx, h0, h1, w0, w1, tid);
    __syncthreads();

    float inv = 49.0f / (24.0f * 16.0f);
    int c = tid;
    const float* fb = g_buf + OF_CTXF + ((long)b * Cc + c) * HW;
    float acc[49];
#pragma unroll
    for (int s = 0; s < 49; s++) acc[s] = 0.0f;
    pool_channel_acc(fb, 1, wy, wx, h0, h1, w0, w1, acc);
    float* X = g_buf + OF_PCTX + ((long)b * Cc + c) * PP;
#pragma unroll
    for (int s = 0; s < 49; s++) X[s] = acc[s] * inv;
}

__global__ void pack_xobj_kernel()
{
    using namespace sg;
    int b = blockIdx.y;
    int base = blockIdx.x * blockDim.x + threadIdx.x;
    int stride = gridDim.x * blockDim.x;
    for (int idx = base; idx < 256 * 784; idx += stride) {
        int cc = idx / 784, rem = idx - cc * 784;
        int n = rem / 49, s = rem - n * 49;
        float v = g_buf[OF_PCTX + ((long)b * Cc + cc) * PP + s];
        if (cc >= 128) v *= g_buf[OF_BIMAP + ((long)b * Nn + n) * PP + s];
        g_buf[OF_XOBJ + ((long)b * 512 + 256 + cc) * 784 + rem] = v;
    }
}

// pool rel feats over union boxes -> XrelT hi/lo [b][pair*49+s][384] bf16
__global__ void __launch_bounds__(384) pool_rel_kernel(const float* __restrict__ boxes)
{
    using namespace sg;
    extern __shared__ float stage[];
    int b = blockIdx.y, pair = blockIdx.x, tid = threadIdx.x;
    int i = pair >> 4, j = pair & 15;
    const float* bi = boxes + ((long)b * Nn + i) * 4;
    const float* bj = boxes + ((long)b * Nn + j) * 4;
    float ix1 = bi[0], iy1 = bi[1], ix2 = bi[2], iy2 = bi[3];
    float jx1 = bj[0], jy1 = bj[1], jx2 = bj[2], jy2 = bj[3];
    float ux1 = fminf(ix1, jx1), uy1 = fminf(iy1, jy1);
    float ux2 = fmaxf(ix2, jx2), uy2 = fmaxf(iy2, jy2);
    float sx1 = ux1 * SCALE, sy1 = uy1 * SCALE, sx2 = ux2 * SCALE, sy2 = uy2 * SCALE;

    __shared__ float wy[7][16], wx[7][24];
    __shared__ int h0[7], h1[7], w0[7], w1[7];
    __shared__ float subm[49], objm[49];
    compute_weights(sx1, sy1, sx2, sy2, wy, wx, h0, h1, w0, w1, tid);

    if (tid < 49) {
        int p = tid / 7, q = tid - p * 7;
        float ye0 = uy1 + (uy2 - uy1) * (float)p * (1.0f / 7.0f);
        float ye1 = uy1 + (uy2 - uy1) * (float)(p + 1) * (1.0f / 7.0f);
        float xe0 = ux1 + (ux2 - ux1) * (float)q * (1.0f / 7.0f);
        float xe1 = ux1 + (ux2 - ux1) * (float)(q + 1) * (1.0f / 7.0f);
        float ch = fmaxf((uy2 - uy1) * (1.0f / 7.0f), 1e-9f);
        float cw = fmaxf((ux2 - ux1) * (1.0f / 7.0f), 1e-9f);
        float oy = fmaxf(fminf(ye1, iy2) - fmaxf(ye0, iy1), 0.0f);
        float ox = fmaxf(fminf(xe1, ix2) - fmaxf(xe0, ix1), 0.0f);
        subm[tid] = (oy / ch) * (ox / cw);
        oy = fmaxf(fminf(ye1, jy2) - fmaxf(ye0, jy1), 0.0f);
        ox = fmaxf(fminf(xe1, jx2) - fmaxf(xe0, jx1), 0.0f);
        objm[tid] = (oy / ch) * (ox / cw);
    }
    __syncthreads();

    float area = (sx2 - sx1) * (sy2 - sy1) * (1.0f / 49.0f);
    float inv = (area > 0.0f) ? 1.0f / fmaxf(area, 1e-9f) : 0.0f;

    int c = tid;
    const float* fb = g_buf + OF_RELFT + (long)b * HW * C32 + c;
    float acc[49];
#pragma unroll
    for (int s = 0; s < 49; s++) acc[s] = 0.0f;
    pool_channel_acc(fb, C32, wy, wx, h0, h1, w0, w1, acc);

#pragma unroll
    for (int s = 0; s < 49; s++) {
        float mk = (c < 128) ? 1.0f : (c < 256 ? subm[s] : objm[s]);
        stage[c * 49 + s] = acc[s] * inv * mk;
    }
    __syncthreads();

    __nv_bfloat16* xh = (__nv_bfloat16*)(g_buf + OF_XRTH);
    __nv_bfloat16* xl = (__nv_bfloat16*)(g_buf + OF_XRTL);
    long rowBase = ((long)b * KFC + (long)pair * 49) * 384;
    for (int idx = tid; idx < 49 * 384; idx += 384) {
        int s = idx / 384, cc = idx - s * 384;
        __nv_bfloat16 h, l;
        split_bf16(stage[cc * 49 + s], h, l);
        xh[rowBase + (long)s * 384 + cc] = h;
        xl[rowBase + (long)s * 384 + cc] = l;
    }
}

// relu(rel5 + Asub[i] + Aobj[j] + bias) -> R^T hi/lo [2048][12544]
__global__ void __launch_bounds__(256) combine_rel_kernel(const float* __restrict__ brf)
{
    using namespace sg;
    int b = blockIdx.y, pair = blockIdx.x, tid = threadIdx.x;
    int i = pair >> 4, j = pair & 15;
    const float* rel5 = g_buf + OF_REL5 + (long)b * 256 * KFC;
    const float* A1 = g_buf + OF_ASUB + (long)b * 256 * 784 + (long)i * 49;
    const float* A2 = g_buf + OF_AOBJ + (long)b * 256 * 784 + (long)j * 49;
    __nv_bfloat16* rh = (__nv_bfloat16*)(g_buf + OF_RTH) + ((long)b * 256 + pair) * KFC;
    __nv_bfloat16* rl = (__nv_bfloat16*)(g_buf + OF_RTL) + ((long)b * 256 + pair) * KFC;
    for (int idx = tid; idx < KFC; idx += 256) {
        int o = idx / 49, s = idx - o * 49;
        float v = rel5[(long)o * KFC + pair * 49 + s] + A1[(long)o * 784 + s]
                + A2[(long)o * 784 + s] + brf[o];
        v = fmaxf(v, 0.0f);
        __nv_bfloat16 h, l;
        split_bf16(v, h, l);
        rh[idx] = h; rl[idx] = l;
    }
}

// relu(obj) -> Robj^T hi/lo [128][12544]
__global__ void __launch_bounds__(256) combine_obj_kernel()
{
    using namespace sg;
    int row = blockIdx.x;                 // b*16 + i
    int b = row >> 4, i = row & 15;
    const float* obj = g_buf + OF_OBJ + (long)b * 256 * 784 + (long)i * 49;
    __nv_bfloat16* rh = (__nv_bfloat16*)(g_buf + OF_ROH) + (long)row * KFC;
    __nv_bfloat16* rl = (__nv_bfloat16*)(g_buf + OF_ROL) + (long)row * KFC;
    for (int idx = threadIdx.x; idx < KFC; idx += 256) {
        int o = idx / 49, s = idx - o * 49;
        float v = fmaxf(obj[(long)o * 784 + s], 0.0f);
        __nv_bfloat16 h, l;
        split_bf16(v, h, l);
        rh[idx] = h; rl[idx] = l;
    }
}

// fp32 weight matrix (slice) -> contiguous bf16 hi/lo
__global__ void convert_w_kernel(const float* __restrict__ W, int lda, int colOff,
                                 long offHi, long offLo, long total, int Kout)
{
    __nv_bfloat16* ph = (__nv_bfloat16*)(g_buf + offHi);
    __nv_bfloat16* pl = (__nv_bfloat16*)(g_buf + offLo);
    for (long idx = (long)blockIdx.x * blockDim.x + threadIdx.x; idx < total;
         idx += (long)gridDim.x * blockDim.x) {
        long m = idx / Kout;
        int k = (int)(idx - m * Kout);
        float x = W[m * lda + colOff + k];
        __nv_bfloat16 h, l;
        split_bf16(x, h, l);
        ph[idx] = h; pl[idx] = l;
    }
}

__global__ void reduce_split_kernel(long offP, long offO, long MN, int Ncols,
                                    int S, const float* __restrict__ bias)
{
    long idx = (long)blockIdx.x * blockDim.x + threadIdx.x;
    if (idx >= MN) return;
    float s = 0.0f;
    for (int i = 0; i < S; i++) s += g_buf[offP + (long)i * MN + idx];
    int m = (int)(idx / Ncols);
    g_buf[offO + idx] = s + bias[m];
}

__global__ void finalize_kernel(long srcOff, int ncols, float* __restrict__ out)
{
    int col = blockIdx.x, n = threadIdx.x;
    float v = g_buf[srcOff + (long)n * ncols + col];
    float s = v * v;
#pragma unroll
    for (int o = 16; o > 0; o >>= 1) s += __shfl_xor_sync(0xffffffffu, s, o);
    __shared__ float red[8];
    if ((n & 31) == 0) red[n >> 5] = s;
    __syncthreads();
    float tot = red[0] + red[1] + red[2] + red[3] + red[4] + red[5] + red[6] + red[7];
    out[(long)col * 256 + n] = v / sqrtf(tot);
}

// ===========================================================================
extern "C" void kernel_launch(void* const* d_in, const int* in_sizes, int n_in,
                              void* d_out, int out_size)
{
    using namespace sg;
    const float* input = (const float*)d_in[0];
    const float* boxes = (const float*)d_in[1];
    const float* W_ctx = (const float*)d_in[3];
    const float* b_ctx = (const float*)d_in[4];
    const float* W_rel = (const float*)d_in[5];
    const float* b_rel = (const float*)d_in[6];
    const float* W_of  = (const float*)d_in[7];
    const float* b_of  = (const float*)d_in[8];
    const float* W_rf  = (const float*)d_in[9];
    const float* b_rf  = (const float*)d_in[10];
    const float* W_ofc = (const float*)d_in[11];
    const float* b_ofc = (const float*)d_in[12];
    const float* W_rfc = (const float*)d_in[13];
    const float* b_rfc = (const float*)d_in[14];
    float* out = (float*)d_out;

    const long sFeat = (long)Cc * HW;
    const long sRelf = (long)C32 * HW;
    const long s784  = 256L * 784;
    const int SMEM_HMMA = 2 * 2 * 128 * 48 * 2;   // 49152 bytes

    cudaFuncSetAttribute(hmma_gemm_kernel, cudaFuncAttributeMaxDynamicSharedMemorySize, SMEM_HMMA);
    cudaFuncSetAttribute(pool_rel_kernel, cudaFuncAttributeMaxDynamicSharedMemorySize, 384 * 49 * 4);

    // Weight conversions (independent of data path)
    convert_w_kernel<<<384, 256>>>(W_rf, 896, 512, OF_WPH, OF_WPL, 256L * 384, 384);
    convert_w_kernel<<<4096, 256>>>(W_rfc, KFC, 0, OF_WRH, OF_WRL, 256L * KFC, KFC);
    convert_w_kernel<<<4096, 256>>>(W_ofc, KFC, 0, OF_WOH, OF_WOL, 256L * KFC, KFC);

    // 1-2. 1x1 convs (fp32)
    sgemm_kernel<<<dim3(6, 4, 8), 256>>>(W_ctx, 0, 256, 0, input, 0, 384, sFeat,
                                         OF_CTXF, 384, sFeat, 256, 384, 256, b_ctx);
    sgemm_kernel<<<dim3(6, 6, 8), 256>>>(W_rel, 0, 256, 0, input, 0, 384, sFeat,
                                         OF_RELF, 384, sRelf, 384, 384, 256, b_rel);
    // 3-4. transposes to [hw][c]
    transpose_kernel<<<dim3(12, 8, 8), dim3(32, 8)>>>(input, 0, OF_FEATT, 256, 384);
    transpose_kernel<<<dim3(12, 12, 8), dim3(32, 8)>>>(nullptr, OF_RELF, OF_RELFT, 384, 384);
    // 5-7. pooling + obj conv input assembly
    pool_ctx_kernel<<<8, 256>>>();
    pool_obj_kernel<<<dim3(16, 8), 256>>>(boxes);
    pack_xobj_kernel<<<dim3(16, 8), 256>>>();
    // 8. obj conv (fp32)
    sgemm128_kernel<<<dim3(7, 2, 8), 256>>>(W_of, 0, 512, OF_XOBJ, 784, 512L * 784,
                                            OF_OBJ, 784, s784, 784, 512, 512, 1, b_of);
    // 9-10. pair decomposition terms (fp32)
    sgemm128_kernel<<<dim3(7, 2, 8), 256>>>(W_rf, 0, 896, OF_OBJ, 784, s784,
                                            OF_ASUB, 784, s784, 784, 256, 256, 1, nullptr);
    sgemm128_kernel<<<dim3(7, 2, 8), 256>>>(W_rf, 256, 896, OF_OBJ, 784, s784,
                                            OF_AOBJ, 784, s784, 784, 256, 256, 1, nullptr);
    // 11. pool rel feats -> XrelT bf16 hi/lo
    pool_rel_kernel<<<dim3(256, 8), 384, 384 * 49 * 4>>>(boxes);
    // 12. pair GEMM (HMMA, batched over images): rel5 = Wp x XrelT^T
    hmma_gemm_kernel<<<dim3(98, 2, 8), 256, SMEM_HMMA>>>(
        OF_WPH, OF_WPL, 384, OF_XRTH, OF_XRTL, 384, (long)KFC * 384,
        OF_REL5, KFC, 256L * KFC, 384, 1);
    // 13. combine + relu -> R^T bf16 hi/lo [2048][12544]
    combine_rel_kernel<<<dim3(256, 8), 256>>>(b_rf);
    // 14. rel FC (HMMA, split-K 14) + reduce
    hmma_gemm_kernel<<<dim3(16, 2, SPLK), 256, SMEM_HMMA>>>(
        OF_WRH, OF_WRL, KFC, OF_RTH, OF_RTL, KFC, 0,
        OF_FP, 2048, 256L * 2048, KFC / SPLK, 0);
    reduce_split_kernel<<<2048, 256>>>(OF_FP, OF_FREL, 256L * 2048, 2048, SPLK, b_rfc);
    // 15. relu(obj) -> Robj^T bf16 hi/lo [128][12544]
    combine_obj_kernel<<<128, 256>>>();
    // 16. obj FC (HMMA, split-K 49) + reduce
    hmma_gemm_kernel<<<dim3(1, 2, SPLKO), 256, SMEM_HMMA>>>(
        OF_WOH, OF_WOL, KFC, OF_ROH, OF_ROL, KFC, 0,
        OF_FPO, 128, 256L * 128, KFC / SPLKO, 0);
    reduce_split_kernel<<<128, 256>>>(OF_FPO, OF_FOBJ, 256L * 128, 128, SPLKO, b_ofc);
    // 17-18. l2norm heads
    finalize_kernel<<<128, 256>>>(OF_FOBJ, 128, out);
    finalize_kernel<<<2048, 256>>>(OF_FREL, 2048, out + 32768);
}

// round 6
// speedup vs baseline: 2.9349x; 1.4784x over previous
#include <cuda_runtime.h>
#include <cuda_bf16.h>
#include <math.h>
#include <stdint.h>

namespace sg {
constexpr int Bn = 8, Cc = 256, Nn = 16;
constexpr int HW = 384;
constexpr int C32 = 384;
constexpr float SCALE = 1.0f / 16.0f;
constexpr float IMGW = 384.0f, IMGH = 256.0f;
constexpr int PP = 49;
constexpr int KFC = 12544;            // 256*49
constexpr int SPLK = 14;              // rel FC split-K  (14*896 = 12544)
constexpr int SPLKO = 49;             // obj FC split-K  (49*256 = 12544)

constexpr long SZ_CTXF  = (long)Bn * Cc * HW;
constexpr long SZ_RELF  = (long)Bn * C32 * HW;
constexpr long SZ_FEATT = SZ_CTXF;
constexpr long SZ_RELFT = SZ_RELF;
constexpr long SZ_PCTX  = (long)Bn * Cc * PP;
constexpr long SZ_BIMAP = (long)Bn * Nn * PP;
constexpr long SZ_XOBJ  = (long)Bn * 512 * 784;
constexpr long SZ_OBJ   = (long)Bn * 256 * 784;
constexpr long SZ_ASUB  = SZ_OBJ;
constexpr long SZ_AOBJ  = SZ_OBJ;
constexpr long SZ_REL5  = (long)Bn * 256 * KFC;
constexpr long SZ_FREL  = 256L * 2048;
constexpr long SZ_FOBJ  = 256L * 128;
constexpr long SZ_FP    = (long)SPLK * 256 * 2048;
constexpr long SZ_FPO   = (long)SPLKO * 256 * 128;
// bf16 buffers (sizes in float units = bf16count/2)
constexpr long FU_WP  = 256L * 384 / 2;
constexpr long FU_XRT = (long)Bn * KFC * 384 / 2;
constexpr long FU_WR  = 256L * KFC / 2;
constexpr long FU_RT  = 2048L * KFC / 2;
constexpr long FU_WO  = FU_WR;
constexpr long FU_RO  = 128L * KFC / 2;

constexpr long OF_CTXF  = 0;
constexpr long OF_RELF  = OF_CTXF  + SZ_CTXF;
constexpr long OF_FEATT = OF_RELF  + SZ_RELF;
constexpr long OF_RELFT = OF_FEATT + SZ_FEATT;
constexpr long OF_PCTX  = OF_RELFT + SZ_RELFT;
constexpr long OF_BIMAP = OF_PCTX  + SZ_PCTX;
constexpr long OF_XOBJ  = OF_BIMAP + SZ_BIMAP;
constexpr long OF_OBJ   = OF_XOBJ  + SZ_XOBJ;
constexpr long OF_ASUB  = OF_OBJ   + SZ_OBJ;
constexpr long OF_AOBJ  = OF_ASUB  + SZ_ASUB;
constexpr long OF_REL5  = OF_AOBJ  + SZ_AOBJ;
constexpr long OF_FREL  = OF_REL5  + SZ_REL5;
constexpr long OF_FOBJ  = OF_FREL  + SZ_FREL;
constexpr long OF_FP    = OF_FOBJ  + SZ_FOBJ;
constexpr long OF_FPO   = OF_FP    + SZ_FP;
constexpr long OF_WPH   = OF_FPO   + SZ_FPO;
constexpr long OF_WPL   = OF_WPH   + FU_WP;
constexpr long OF_XRTH  = OF_WPL   + FU_WP;
constexpr long OF_XRTL  = OF_XRTH  + FU_XRT;
constexpr long OF_WRH   = OF_XRTL  + FU_XRT;
constexpr long OF_WRL   = OF_WRH   + FU_WR;
constexpr long OF_RTH   = OF_WRL   + FU_WR;
constexpr long OF_RTL   = OF_RTH   + FU_RT;
constexpr long OF_WOH   = OF_RTL   + FU_RT;
constexpr long OF_WOL   = OF_WOH   + FU_WO;
constexpr long OF_ROH   = OF_WOL   + FU_WO;
constexpr long OF_ROL   = OF_ROH   + FU_RO;
constexpr long TOTAL    = OF_ROL   + FU_RO;
}  // namespace sg

__device__ float g_buf[sg::TOTAL];

// ========================= low-level helpers ===============================
__device__ __forceinline__ uint32_t smem_u32(const void* p) {
    uint32_t a;
    asm("{ .reg .u64 t; cvta.to.shared.u64 t, %1; cvt.u32.u64 %0, t; }" : "=r"(a) : "l"(p));
    return a;
}
__device__ __forceinline__ void cp_async16(uint32_t dst, const void* src) {
    asm volatile("cp.async.cg.shared.global [%0], [%1], 16;" :: "r"(dst), "l"(src));
}
__device__ __forceinline__ void cp_commit() {
    asm volatile("cp.async.commit_group;" ::: "memory");
}
__device__ __forceinline__ void ldsm4(uint32_t* a, uint32_t addr) {
    asm volatile("ldmatrix.sync.aligned.m8n8.x4.shared.b16 {%0,%1,%2,%3}, [%4];"
        : "=r"(a[0]), "=r"(a[1]), "=r"(a[2]), "=r"(a[3]) : "r"(addr));
}
__device__ __forceinline__ void ldsm2(uint32_t* b, uint32_t addr) {
    asm volatile("ldmatrix.sync.aligned.m8n8.x2.shared.b16 {%0,%1}, [%2];"
        : "=r"(b[0]), "=r"(b[1]) : "r"(addr));
}
__device__ __forceinline__ void mma16816(float* d, const uint32_t* a, const uint32_t* b) {
    asm volatile("mma.sync.aligned.m16n8k16.row.col.f32.bf16.bf16.f32 "
        "{%0,%1,%2,%3}, {%4,%5,%6,%7}, {%8,%9}, {%0,%1,%2,%3};"
        : "+f"(d[0]), "+f"(d[1]), "+f"(d[2]), "+f"(d[3])
        : "r"(a[0]), "r"(a[1]), "r"(a[2]), "r"(a[3]), "r"(b[0]), "r"(b[1]));
}
__device__ __forceinline__ void split_bf16(float x, __nv_bfloat16& h, __nv_bfloat16& l) {
    h = __float2bfloat16(x);
    l = __float2bfloat16(x - __bfloat162float(h));
}

// ========================= PrRoI pooling helpers ===========================
static __device__ __forceinline__ float hatG(float t) {
    float tl = fminf(fmaxf(t, -1.0f), 0.0f);
    float tr = fminf(fmaxf(t, 0.0f), 1.0f);
    return 0.5f * (tl + 1.0f) * (tl + 1.0f) + 0.5f - 0.5f * (1.0f - tr) * (1.0f - tr);
}

// Bin weights + TIGHT active index ranges (weight support is (e0-1, e1+1)).
static __device__ __forceinline__ void compute_weights(
    float x1, float y1, float x2, float y2,
    float (*wy)[16], float (*wx)[24],
    int* h0, int* h1, int* w0, int* w1, int tid)
{
    if (tid < 112) {
        int p = tid / 16, i = tid % 16;
        float e0 = y1 + (y2 - y1) * (float)p * (1.0f / 7.0f);
        float e1 = y1 + (y2 - y1) * (float)(p + 1) * (1.0f / 7.0f);
        wy[p][i] = hatG(e1 - (float)i) - hatG(e0 - (float)i);
    }
    if (tid < 168) {
        int q = tid / 24, i = tid % 24;
        float e0 = x1 + (x2 - x1) * (float)q * (1.0f / 7.0f);
        float e1 = x1 + (x2 - x1) * (float)(q + 1) * (1.0f / 7.0f);
        wx[q][i] = hatG(e1 - (float)i) - hatG(e0 - (float)i);
    }
    if (tid < 7) {
        float e0 = y1 + (y2 - y1) * (float)tid * (1.0f / 7.0f);
        float e1 = y1 + (y2 - y1) * (float)(tid + 1) * (1.0f / 7.0f);
        h0[tid] = max(0, (int)ceilf(e0) - 1);
        h1[tid] = min(16, (int)floorf(e1) + 2);
    }
    if (tid >= 32 && tid < 39) {
        int q = tid - 32;
        float e0 = x1 + (x2 - x1) * (float)q * (1.0f / 7.0f);
        float e1 = x1 + (x2 - x1) * (float)(q + 1) * (1.0f / 7.0f);
        w0[q] = max(0, (int)ceilf(e0) - 1);
        w1[q] = min(24, (int)floorf(e1) + 2);
    }
}

static __device__ __forceinline__ void pool_channel_acc(
    const float* __restrict__ fb, int ps,
    const float (*wy)[16], const float (*wx)[24],
    const int* h0, const int* h1, const int* w0, const int* w1,
    float* acc)
{
#pragma unroll
    for (int p = 0; p < 7; p++) {
        for (int h = h0[p]; h < h1[p]; h++) {
            float wyv = wy[p][h];
            const float* row = fb + (long)h * 24 * ps;
#pragma unroll
            for (int q = 0; q < 7; q++) {
                float a = 0.0f;
                for (int w = w0[q]; w < w1[q]; w++)
                    a += wx[q][w] * row[(long)w * ps];
                acc[p * 7 + q] += wyv * a;
            }
        }
    }
}

// ============================ fp32 GEMM paths ==============================
__global__ void __launch_bounds__(256) sgemm_kernel(
    const float* __restrict__ Aext, long offA, int lda, long sAb,
    const float* __restrict__ Bext, long offB, int ldb, long sBb,
    long offC, int ldc, long sCb,
    int M, int N, int K, const float* __restrict__ bias)
{
    const int b = blockIdx.z;
    const float* A  = (Aext ? Aext + offA : g_buf + offA) + (long)b * sAb;
    const float* Bm = (Bext ? Bext + offB : g_buf + offB) + (long)b * sBb;
    float* Cm = g_buf + offC + (long)b * sCb;

    __shared__ float As[16][65];
    __shared__ float Bs[16][68];

    const int tid = threadIdx.x;
    const int row0 = blockIdx.y * 64;
    const int col0 = blockIdx.x * 64;
    const int ty = tid >> 4, tx = tid & 15;
    const int ty4 = ty * 4, tx4 = tx * 4;
    const int ar = tid >> 2;
    const int ak = (tid & 3) << 2;
    const int br = tid >> 4;
    const int bc = (tid & 15) << 2;

    float acc[4][4] = {};

    for (int k0 = 0; k0 < K; k0 += 16) {
        float4 av = *(const float4*)(A + (long)(row0 + ar) * lda + k0 + ak);
        As[ak + 0][ar] = av.x; As[ak + 1][ar] = av.y;
        As[ak + 2][ar] = av.z; As[ak + 3][ar] = av.w;

        const float* bp = Bm + (long)(k0 + br) * ldb + col0 + bc;
        float4 bv;
        if (col0 + bc + 3 < N) {
            bv = *(const float4*)bp;
        } else {
            bv.x = (col0 + bc + 0 < N) ? bp[0] : 0.0f;
            bv.y = (col0 + bc + 1 < N) ? bp[1] : 0.0f;
            bv.z = (col0 + bc + 2 < N) ? bp[2] : 0.0f;
            bv.w = 0.0f;
        }
        *(float4*)&Bs[br][bc] = bv;
        __syncthreads();

#pragma unroll
        for (int k = 0; k < 16; k++) {
            float a0 = As[k][ty4 + 0], a1 = As[k][ty4 + 1];
            float a2 = As[k][ty4 + 2], a3 = As[k][ty4 + 3];
            float4 b4 = *(const float4*)&Bs[k][tx4];
            acc[0][0] += a0 * b4.x; acc[0][1] += a0 * b4.y; acc[0][2] += a0 * b4.z; acc[0][3] += a0 * b4.w;
            acc[1][0] += a1 * b4.x; acc[1][1] += a1 * b4.y; acc[1][2] += a1 * b4.z; acc[1][3] += a1 * b4.w;
            acc[2][0] += a2 * b4.x; acc[2][1] += a2 * b4.y; acc[2][2] += a2 * b4.z; acc[2][3] += a2 * b4.w;
            acc[3][0] += a3 * b4.x; acc[3][1] += a3 * b4.y; acc[3][2] += a3 * b4.z; acc[3][3] += a3 * b4.w;
        }
        __syncthreads();
    }

#pragma unroll
    for (int u = 0; u < 4; u++) {
        int r = row0 + ty4 + u;
        float bz = bias ? bias[r] : 0.0f;
#pragma unroll
        for (int v = 0; v < 4; v++) {
            int cidx = col0 + tx4 + v;
            if (cidx < N) Cm[(long)r * ldc + cidx] = acc[u][v] + bz;
        }
    }
}

__global__ void __launch_bounds__(256) sgemm128_kernel(
    const float* __restrict__ Aex, long offA, int lda,
    long offB, int ldb, long sBb,
    long offC, int ldc, long sCb,
    int N, int K, int kChunk, int splitK,
    const float* __restrict__ bias)
{
    __shared__ float As[2][8][132];
    __shared__ float Bs[2][8][132];

    const int z = blockIdx.z;
    const int b = z / splitK;
    const int ks = z - b * splitK;
    const int kBeg = ks * kChunk;
    const int kEnd = min(K, kBeg + kChunk);
    const int nk = (kEnd - kBeg) >> 3;

    const float* A = Aex + offA;
    const float* B = g_buf + offB + (long)b * sBb;
    float* C = g_buf + offC + (long)z * sCb;

    const int t = threadIdx.x;
    const int row0 = blockIdx.y * 128, col0 = blockIdx.x * 128;
    const int arow = t >> 1, akq = (t & 1) << 2;
    const int brow = t >> 5, bcol = (t & 31) << 2;
    const int tx = t & 15, ty = t >> 4;

    const float* aPtr = A + (long)(row0 + arow) * lda + kBeg + akq;
    const float* bPtr = B + (long)(kBeg + brow) * ldb + col0 + bcol;
    const bool bIn = (col0 + bcol + 3) < N;

    float4 pa = *(const float4*)aPtr;
    float4 pb;
    if (bIn) {
        pb = *(const float4*)bPtr;
    } else {
        pb.x = (col0 + bcol + 0 < N) ? bPtr[0] : 0.0f;
        pb.y = (col0 + bcol + 1 < N) ? bPtr[1] : 0.0f;
        pb.z = (col0 + bcol + 2 < N) ? bPtr[2] : 0.0f;
        pb.w = 0.0f;
    }
    As[0][akq + 0][arow] = pa.x; As[0][akq + 1][arow] = pa.y;
    As[0][akq + 2][arow] = pa.z; As[0][akq + 3][arow] = pa.w;
    *(float4*)&Bs[0][brow][bcol] = pb;
    __syncthreads();

    float acc[8][8] = {};

    for (int kt = 0; kt < nk; kt++) {
        const int buf = kt & 1;
        if (kt + 1 < nk) {
            pa = *(const float4*)(aPtr + (kt + 1) * 8);
            const float* bp = bPtr + (long)(kt + 1) * 8 * ldb;
            if (bIn) {
                pb = *(const float4*)bp;
            } else {
                pb.x = (col0 + bcol + 0 < N) ? bp[0] : 0.0f;
                pb.y = (col0 + bcol + 1 < N) ? bp[1] : 0.0f;
                pb.z = (col0 + bcol + 2 < N) ? bp[2] : 0.0f;
                pb.w = 0.0f;
            }
        }
#pragma unroll
        for (int kk = 0; kk < 8; kk++) {
            float4 a0 = *(const float4*)&As[buf][kk][ty * 4];
            float4 a1 = *(const float4*)&As[buf][kk][64 + ty * 4];
            float4 b0 = *(const float4*)&Bs[buf][kk][tx * 4];
            float4 b1 = *(const float4*)&Bs[buf][kk][64 + tx * 4];
            float av[8] = {a0.x, a0.y, a0.z, a0.w, a1.x, a1.y, a1.z, a1.w};
            float bv[8] = {b0.x, b0.y, b0.z, b0.w, b1.x, b1.y, b1.z, b1.w};
#pragma unroll
            for (int u = 0; u < 8; u++)
#pragma unroll
                for (int v = 0; v < 8; v++)
                    acc[u][v] += av[u] * bv[v];
        }
        if (kt + 1 < nk) {
            const int nb = buf ^ 1;
            As[nb][akq + 0][arow] = pa.x; As[nb][akq + 1][arow] = pa.y;
            As[nb][akq + 2][arow] = pa.z; As[nb][akq + 3][arow] = pa.w;
            *(float4*)&Bs[nb][brow][bcol] = pb;
            __syncthreads();
        }
    }

#pragma unroll
    for (int u = 0; u < 8; u++) {
        int r = row0 + ((u < 4) ? ty * 4 + u : 64 + ty * 4 + (u - 4));
        float bz = bias ? bias[r] : 0.0f;
#pragma unroll
        for (int v = 0; v < 8; v++) {
            int c = col0 + ((v < 4) ? tx * 4 + v : 64 + tx * 4 + (v - 4));
            if (c < N) C[(long)r * ldc + c] = acc[u][v] + bz;
        }
    }
}

// ================ HMMA (mma.sync) bf16-split GEMM ==========================
// C[z] = split(A) x split(B^T)^T with 3 terms (hh + hl + lh), single fp32 acc.
// Per 32-k step: load Ahi/Alo/Bhi/Blo tiles once (4 tiles, STR=40 conflict-free),
// compute 96 MMA from them. Tile 128x128, 8 warps (2x4, 64x32 each).
__global__ void __launch_bounds__(256) hmma_gemm_kernel(
    long offAhi, long offAlo, int lda,
    long offBhi, long offBlo, int ldb, long sBz,
    long offC, int ldc, long sCz,
    int kChunk, int batchB)
{
    extern __shared__ __nv_bfloat16 smb[];
    constexpr int STR = 40;               // 80B rows: 8-row ldmatrix conflict-free
    constexpr int TILEE = 128 * STR;      // elements per tile

    const int tid = threadIdx.x;
    const int warp = tid >> 5, lane = tid & 31;
    const int z = blockIdx.z;
    const int row0 = blockIdx.y * 128, col0 = blockIdx.x * 128;
    const long kBeg = batchB ? 0 : (long)z * kChunk;
    const int S = kChunk / 32;

    const __nv_bfloat16* Ahi = (const __nv_bfloat16*)(g_buf + offAhi);
    const __nv_bfloat16* Alo = (const __nv_bfloat16*)(g_buf + offAlo);
    const __nv_bfloat16* Bhi = (const __nv_bfloat16*)(g_buf + offBhi) + (batchB ? (long)z * sBz : 0);
    const __nv_bfloat16* Blo = (const __nv_bfloat16*)(g_buf + offBlo) + (batchB ? (long)z * sBz : 0);
    float* C = g_buf + offC + (long)z * sCz;

    const int wm = (warp >> 2) * 64;      // 2x4 warp grid: 64x32 per warp
    const int wn = (warp & 3) * 32;

    float acc[4][4][4] = {};

    const uint32_t smem_base = smem_u32(smb);

    auto issue_load = [&](int s, int buf) {
        long koff = kBeg + (long)s * 32;
        uint32_t dstBase = smem_base + (uint32_t)buf * 4 * TILEE * 2;
#pragma unroll
        for (int t = 0; t < 4; t++) {
            const __nv_bfloat16* src = (t == 0) ? Ahi : (t == 1) ? Alo
                                      : (t == 2) ? Bhi : Blo;
            const int base0 = (t < 2) ? row0 : col0;
            const int ld = (t < 2) ? lda : ldb;
#pragma unroll
            for (int i = 0; i < 2; i++) {
                int idx = tid + i * 256;          // 0..511
                int r = idx >> 2;
                int cg = (idx & 3) * 8;
                cp_async16(dstBase + (uint32_t)((t * TILEE + r * STR + cg) * 2),
                           src + (long)(base0 + r) * ld + koff + cg);
            }
        }
        cp_commit();
    };

    issue_load(0, 0);

    for (int s = 0; s < S; s++) {
        if (s + 1 < S) {
            issue_load(s + 1, (s + 1) & 1);
            asm volatile("cp.async.wait_group 1;" ::: "memory");
        } else {
            asm volatile("cp.async.wait_group 0;" ::: "memory");
        }
        __syncthreads();

        const int buf = s & 1;
        const uint32_t tb = smem_base + (uint32_t)buf * 4 * TILEE * 2;
        const uint32_t aHiB = tb;
        const uint32_t aLoB = tb + TILEE * 2;
        const uint32_t bHiB = tb + 2 * TILEE * 2;
        const uint32_t bLoB = tb + 3 * TILEE * 2;
        const int lr = lane & 15;
        const int kofA = (lane >> 4) * 8;
        const int kofB = ((lane & 15) >> 3) * 8;

#pragma unroll
        for (int k16 = 0; k16 < 2; k16++) {
            uint32_t af[4][4], bh[4][2], bl[4][2];
#pragma unroll
            for (int mi = 0; mi < 4; mi++)
                ldsm4(af[mi], aHiB + (uint32_t)(((wm + mi * 16 + lr) * STR)
                                               + k16 * 16 + kofA) * 2);
#pragma unroll
            for (int ni = 0; ni < 4; ni++) {
                uint32_t ro = (uint32_t)(((wn + ni * 8 + (lr & 7)) * STR)
                                         + k16 * 16 + kofB) * 2;
                ldsm2(bh[ni], bHiB + ro);
                ldsm2(bl[ni], bLoB + ro);
            }
#pragma unroll
            for (int mi = 0; mi < 4; mi++)
#pragma unroll
                for (int ni = 0; ni < 4; ni++) {
                    mma16816(acc[mi][ni], af[mi], bh[ni]);   // hh
                    mma16816(acc[mi][ni], af[mi], bl[ni]);   // hl
                }
#pragma unroll
            for (int mi = 0; mi < 4; mi++)
                ldsm4(af[mi], aLoB + (uint32_t)(((wm + mi * 16 + lr) * STR)
                                               + k16 * 16 + kofA) * 2);
#pragma unroll
            for (int mi = 0; mi < 4; mi++)
#pragma unroll
                for (int ni = 0; ni < 4; ni++)
                    mma16816(acc[mi][ni], af[mi], bh[ni]);   // lh
        }
        __syncthreads();
    }

#pragma unroll
    for (int mi = 0; mi < 4; mi++) {
        int r = row0 + wm + mi * 16 + (lane >> 2);
#pragma unroll
        for (int ni = 0; ni < 4; ni++) {
            int cc = col0 + wn + ni * 8 + (lane & 3) * 2;
            *(float2*)&C[(long)r * ldc + cc] = make_float2(acc[mi][ni][0], acc[mi][ni][1]);
            *(float2*)&C[(long)(r + 8) * ldc + cc] = make_float2(acc[mi][ni][2], acc[mi][ni][3]);
        }
    }
}

// ==================== misc data-movement / pooling =========================
__global__ void transpose_kernel(const float* __restrict__ srcExt,
                                 long offSrc, long offDst, int R, int C)
{
    __shared__ float tile[32][33];
    int b = blockIdx.z;
    const float* src = (srcExt ? srcExt : (const float*)g_buf + offSrc) + (long)b * R * C;
    float* dst = g_buf + offDst + (long)b * R * C;
    int c0 = blockIdx.x * 32, r0 = blockIdx.y * 32;
    int tx = threadIdx.x, ty = threadIdx.y;
#pragma unroll
    for (int k = 0; k < 32; k += 8)
        tile[ty + k][tx] = src[(long)(r0 + ty + k) * C + c0 + tx];
    __syncthreads();
#pragma unroll
    for (int k = 0; k < 32; k += 8)
        dst[(long)(c0 + ty + k) * R + r0 + tx] = tile[tx][ty + k];
}

__global__ void __launch_bounds__(256) pool_obj_kernel(const float* __restrict__ boxes)
{
    using namespace sg;
    int b = blockIdx.y, n = blockIdx.x, tid = threadIdx.x;
    const float* bx = boxes + ((long)b * Nn + n) * 4;
    float x1 = bx[0], y1 = bx[1], x2 = bx[2], y2 = bx[3];
    float sx1 = x1 * SCALE, sy1 = y1 * SCALE, sx2 = x2 * SCALE, sy2 = y2 * SCALE;

    __shared__ float wy[7][16], wx[7][24];
    __shared__ int h0[7], h1[7], w0[7], w1[7];
    compute_weights(sx1, sy1, sx2, sy2, wy, wx, h0, h1, w0, w1, tid);

    if (tid < 49) {
        int p = tid / 7, q = tid % 7;
        float ye0 = IMGH * (float)p * (1.0f / 7.0f), ye1 = IMGH * (float)(p + 1) * (1.0f / 7.0f);
        float xe0 = IMGW * (float)q * (1.0f / 7.0f), xe1 = IMGW * (float)(q + 1) * (1.0f / 7.0f);
        float oy = fmaxf(fminf(ye1, y2) - fmaxf(ye0, y1), 0.0f);
        float ox = fmaxf(fminf(xe1, x2) - fmaxf(xe0, x1), 0.0f);
        float ch = IMGH * (1.0f / 7.0f), cw = IMGW * (1.0f / 7.0f);
        g_buf[OF_BIMAP + ((long)b * Nn + n) * PP + tid] = (oy / ch) * (ox / cw);
    }
    __syncthreads();

    float area = (sx2 - sx1) * (sy2 - sy1) * (1.0f / 49.0f);
    float inv = (area > 0.0f) ? 1.0f / fmaxf(area, 1e-9f) : 0.0f;

    int c = tid;
    const float* fb = g_buf + OF_FEATT + (long)b * HW * Cc + c;
    float acc[49];
#pragma unroll
    for (int s = 0; s < 49; s++) acc[s] = 0.0f;
    pool_channel_acc(fb, Cc, wy, wx, h0, h1, w0, w1, acc);

    float* X = g_buf + OF_XOBJ + ((long)b * 512 + c) * 784 + (long)n * 49;
#pragma unroll
    for (int s = 0; s < 49; s++) X[s] = acc[s] * inv;
}

__global__ void __launch_bounds__(256) pool_ctx_kernel()
{
    using namespace sg;
    int b = blockIdx.x, tid = threadIdx.x;
    __shared__ float wy[7][16], wx[7][24];
    __shared__ int h0[7], h1[7], w0[7], w1[7];
    compute_weights(0.0f, 0.0f, 24.0f, 16.0f, wy, wx, h0, h1, w0, w1, tid);
    __syncthreads();

    float inv = 49.0f / (24.0f * 16.0f);
    int c = tid;
    const float* fb = g_buf + OF_CTXF + ((long)b * Cc + c) * HW;
    float acc[49];
#pragma unroll
    for (int s = 0; s < 49; s++) acc[s] = 0.0f;
    pool_channel_acc(fb, 1, wy, wx, h0, h1, w0, w1, acc);
    float* X = g_buf + OF_PCTX + ((long)b * Cc + c) * PP;
#pragma unroll
    for (int s = 0; s < 49; s++) X[s] = acc[s] * inv;
}

__global__ void pack_xobj_kernel()
{
    using namespace sg;
    int b = blockIdx.y;
    int base = blockIdx.x * blockDim.x + threadIdx.x;
    int stride = gridDim.x * blockDim.x;
    for (int idx = base; idx < 256 * 784; idx += stride) {
        int cc = idx / 784, rem = idx - cc * 784;
        int n = rem / 49, s = rem - n * 49;
        float v = g_buf[OF_PCTX + ((long)b * Cc + cc) * PP + s];
        if (cc >= 128) v *= g_buf[OF_BIMAP + ((long)b * Nn + n) * PP + s];
        g_buf[OF_XOBJ + ((long)b * 512 + 256 + cc) * 784 + rem] = v;
    }
}

// pool rel feats over union boxes -> XrelT hi/lo [b][pair*49+s][384] bf16
__global__ void __launch_bounds__(384) pool_rel_kernel(const float* __restrict__ boxes)
{
    using namespace sg;
    extern __shared__ float stage[];
    int b = blockIdx.y, pair = blockIdx.x, tid = threadIdx.x;
    int i = pair >> 4, j = pair & 15;
    const float* bi = boxes + ((long)b * Nn + i) * 4;
    const float* bj = boxes + ((long)b * Nn + j) * 4;
    float ix1 = bi[0], iy1 = bi[1], ix2 = bi[2], iy2 = bi[3];
    float jx1 = bj[0], jy1 = bj[1], jx2 = bj[2], jy2 = bj[3];
    float ux1 = fminf(ix1, jx1), uy1 = fminf(iy1, jy1);
    float ux2 = fmaxf(ix2, jx2), uy2 = fmaxf(iy2, jy2);
    float sx1 = ux1 * SCALE, sy1 = uy1 * SCALE, sx2 = ux2 * SCALE, sy2 = uy2 * SCALE;

    __shared__ float wy[7][16], wx[7][24];
    __shared__ int h0[7], h1[7], w0[7], w1[7];
    __shared__ float subm[49], objm[49];
    compute_weights(sx1, sy1, sx2, sy2, wy, wx, h0, h1, w0, w1, tid);

    if (tid < 49) {
        int p = tid / 7, q = tid - p * 7;
        float ye0 = uy1 + (uy2 - uy1) * (float)p * (1.0f / 7.0f);
        float ye1 = uy1 + (uy2 - uy1) * (float)(p + 1) * (1.0f / 7.0f);
        float xe0 = ux1 + (ux2 - ux1) * (float)q * (1.0f / 7.0f);
        float xe1 = ux1 + (ux2 - ux1) * (float)(q + 1) * (1.0f / 7.0f);
        float ch = fmaxf((uy2 - uy1) * (1.0f / 7.0f), 1e-9f);
        float cw = fmaxf((ux2 - ux1) * (1.0f / 7.0f), 1e-9f);
        float oy = fmaxf(fminf(ye1, iy2) - fmaxf(ye0, iy1), 0.0f);
        float ox = fmaxf(fminf(xe1, ix2) - fmaxf(xe0, ix1), 0.0f);
        subm[tid] = (oy / ch) * (ox / cw);
        oy = fmaxf(fminf(ye1, jy2) - fmaxf(ye0, jy1), 0.0f);
        ox = fmaxf(fminf(xe1, jx2) - fmaxf(xe0, jx1), 0.0f);
        objm[tid] = (oy / ch) * (ox / cw);
    }
    __syncthreads();

    float area = (sx2 - sx1) * (sy2 - sy1) * (1.0f / 49.0f);
    float inv = (area > 0.0f) ? 1.0f / fmaxf(area, 1e-9f) : 0.0f;

    int c = tid;
    const float* fb = g_buf + OF_RELFT + (long)b * HW * C32 + c;
    float acc[49];
#pragma unroll
    for (int s = 0; s < 49; s++) acc[s] = 0.0f;
    pool_channel_acc(fb, C32, wy, wx, h0, h1, w0, w1, acc);

#pragma unroll
    for (int s = 0; s < 49; s++) {
        float mk = (c < 128) ? 1.0f : (c < 256 ? subm[s] : objm[s]);
        stage[c * 49 + s] = acc[s] * inv * mk;
    }
    __syncthreads();

    __nv_bfloat16* xh = (__nv_bfloat16*)(g_buf + OF_XRTH);
    __nv_bfloat16* xl = (__nv_bfloat16*)(g_buf + OF_XRTL);
    long rowBase = ((long)b * KFC + (long)pair * 49) * 384;
    for (int idx = tid; idx < 49 * 384; idx += 384) {
        int s = idx / 384, cc = idx - s * 384;
        __nv_bfloat16 h, l;
        split_bf16(stage[cc * 49 + s], h, l);
        xh[rowBase + (long)s * 384 + cc] = h;
        xl[rowBase + (long)s * 384 + cc] = l;
    }
}

// relu(rel5 + Asub[i] + Aobj[j] + bias) -> R^T hi/lo [2048][12544]
__global__ void __launch_bounds__(256) combine_rel_kernel(const float* __restrict__ brf)
{
    using namespace sg;
    int b = blockIdx.y, pair = blockIdx.x, tid = threadIdx.x;
    int i = pair >> 4, j = pair & 15;
    const float* rel5 = g_buf + OF_REL5 + (long)b * 256 * KFC;
    const float* A1 = g_buf + OF_ASUB + (long)b * 256 * 784 + (long)i * 49;
    const float* A2 = g_buf + OF_AOBJ + (long)b * 256 * 784 + (long)j * 49;
    __nv_bfloat16* rh = (__nv_bfloat16*)(g_buf + OF_RTH) + ((long)b * 256 + pair) * KFC;
    __nv_bfloat16* rl = (__nv_bfloat16*)(g_buf + OF_RTL) + ((long)b * 256 + pair) * KFC;
    for (int idx = tid; idx < KFC; idx += 256) {
        int o = idx / 49, s = idx - o * 49;
        float v = rel5[(long)o * KFC + pair * 49 + s] + A1[(long)o * 784 + s]
                + A2[(long)o * 784 + s] + brf[o];
        v = fmaxf(v, 0.0f);
        __nv_bfloat16 h, l;
        split_bf16(v, h, l);
        rh[idx] = h; rl[idx] = l;
    }
}

// relu(obj) -> Robj^T hi/lo [128][12544]
__global__ void __launch_bounds__(256) combine_obj_kernel()
{
    using namespace sg;
    int row = blockIdx.x;                 // b*16 + i
    int b = row >> 4, i = row & 15;
    const float* obj = g_buf + OF_OBJ + (long)b * 256 * 784 + (long)i * 49;
    __nv_bfloat16* rh = (__nv_bfloat16*)(g_buf + OF_ROH) + (long)row * KFC;
    __nv_bfloat16* rl = (__nv_bfloat16*)(g_buf + OF_ROL) + (long)row * KFC;
    for (int idx = threadIdx.x; idx < KFC; idx += 256) {
        int o = idx / 49, s = idx - o * 49;
        float v = fmaxf(obj[(long)o * 784 + s], 0.0f);
        __nv_bfloat16 h, l;
        split_bf16(v, h, l);
        rh[idx] = h; rl[idx] = l;
    }
}

// fp32 weight matrix (slice) -> contiguous bf16 hi/lo
__global__ void convert_w_kernel(const float* __restrict__ W, int lda, int colOff,
                                 long offHi, long offLo, long total, int Kout)
{
    __nv_bfloat16* ph = (__nv_bfloat16*)(g_buf + offHi);
    __nv_bfloat16* pl = (__nv_bfloat16*)(g_buf + offLo);
    for (long idx = (long)blockIdx.x * blockDim.x + threadIdx.x; idx < total;
         idx += (long)gridDim.x * blockDim.x) {
        long m = idx / Kout;
        int k = (int)(idx - m * Kout);
        float x = W[m * lda + colOff + k];
        __nv_bfloat16 h, l;
        split_bf16(x, h, l);
        ph[idx] = h; pl[idx] = l;
    }
}

__global__ void reduce_split_kernel(long offP, long offO, long MN, int Ncols,
                                    int S, const float* __restrict__ bias)
{
    long idx = (long)blockIdx.x * blockDim.x + threadIdx.x;
    if (idx >= MN) return;
    float s = 0.0f;
    for (int i = 0; i < S; i++) s += g_buf[offP + (long)i * MN + idx];
    int m = (int)(idx / Ncols);
    g_buf[offO + idx] = s + bias[m];
}

__global__ void finalize_kernel(long srcOff, int ncols, float* __restrict__ out)
{
    int col = blockIdx.x, n = threadIdx.x;
    float v = g_buf[srcOff + (long)n * ncols + col];
    float s = v * v;
#pragma unroll
    for (int o = 16; o > 0; o >>= 1) s += __shfl_xor_sync(0xffffffffu, s, o);
    __shared__ float red[8];
    if ((n & 31) == 0) red[n >> 5] = s;
    __syncthreads();
    float tot = red[0] + red[1] + red[2] + red[3] + red[4] + red[5] + red[6] + red[7];
    out[(long)col * 256 + n] = v / sqrtf(tot);
}

// ===========================================================================
extern "C" void kernel_launch(void* const* d_in, const int* in_sizes, int n_in,
                              void* d_out, int out_size)
{
    using namespace sg;
    const float* input = (const float*)d_in[0];
    const float* boxes = (const float*)d_in[1];
    const float* W_ctx = (const float*)d_in[3];
    const float* b_ctx = (const float*)d_in[4];
    const float* W_rel = (const float*)d_in[5];
    const float* b_rel = (const float*)d_in[6];
    const float* W_of  = (const float*)d_in[7];
    const float* b_of  = (const float*)d_in[8];
    const float* W_rf  = (const float*)d_in[9];
    const float* b_rf  = (const float*)d_in[10];
    const float* W_ofc = (const float*)d_in[11];
    const float* b_ofc = (const float*)d_in[12];
    const float* W_rfc = (const float*)d_in[13];
    const float* b_rfc = (const float*)d_in[14];
    float* out = (float*)d_out;

    const long sFeat = (long)Cc * HW;
    const long sRelf = (long)C32 * HW;
    const long s784  = 256L * 784;
    const int SMEM_HMMA = 2 * 4 * 128 * 40 * 2;   // 81920 bytes

    cudaFuncSetAttribute(hmma_gemm_kernel, cudaFuncAttributeMaxDynamicSharedMemorySize, SMEM_HMMA);
    cudaFuncSetAttribute(pool_rel_kernel, cudaFuncAttributeMaxDynamicSharedMemorySize, 384 * 49 * 4);

    // Weight conversions (independent of data path)
    convert_w_kernel<<<384, 256>>>(W_rf, 896, 512, OF_WPH, OF_WPL, 256L * 384, 384);
    convert_w_kernel<<<4096, 256>>>(W_rfc, KFC, 0, OF_WRH, OF_WRL, 256L * KFC, KFC);
    convert_w_kernel<<<4096, 256>>>(W_ofc, KFC, 0, OF_WOH, OF_WOL, 256L * KFC, KFC);

    // 1-2. 1x1 convs (fp32)
    sgemm_kernel<<<dim3(6, 4, 8), 256>>>(W_ctx, 0, 256, 0, input, 0, 384, sFeat,
                                         OF_CTXF, 384, sFeat, 256, 384, 256, b_ctx);
    sgemm_kernel<<<dim3(6, 6, 8), 256>>>(W_rel, 0, 256, 0, input, 0, 384, sFeat,
                                         OF_RELF, 384, sRelf, 384, 384, 256, b_rel);
    // 3-4. transposes to [hw][c]
    transpose_kernel<<<dim3(12, 8, 8), dim3(32, 8)>>>(input, 0, OF_FEATT, 256, 384);
    transpose_kernel<<<dim3(12, 12, 8), dim3(32, 8)>>>(nullptr, OF_RELF, OF_RELFT, 384, 384);
    // 5-7. pooling + obj conv input assembly
    pool_ctx_kernel<<<8, 256>>>();
    pool_obj_kernel<<<dim3(16, 8), 256>>>(boxes);
    pack_xobj_kernel<<<dim3(16, 8), 256>>>();
    // 8. obj conv (fp32)
    sgemm128_kernel<<<dim3(7, 2, 8), 256>>>(W_of, 0, 512, OF_XOBJ, 784, 512L * 784,
                                            OF_OBJ, 784, s784, 784, 512, 512, 1, b_of);
    // 9-10. pair decomposition terms (fp32)
    sgemm128_kernel<<<dim3(7, 2, 8), 256>>>(W_rf, 0, 896, OF_OBJ, 784, s784,
                                            OF_ASUB, 784, s784, 784, 256, 256, 1, nullptr);
    sgemm128_kernel<<<dim3(7, 2, 8), 256>>>(W_rf, 256, 896, OF_OBJ, 784, s784,
                                            OF_AOBJ, 784, s784, 784, 256, 256, 1, nullptr);
    // 11. pool rel feats -> XrelT bf16 hi/lo
    pool_rel_kernel<<<dim3(256, 8), 384, 384 * 49 * 4>>>(boxes);
    // 12. pair GEMM (HMMA, batched over images): rel5 = Wp x XrelT^T
    hmma_gemm_kernel<<<dim3(98, 2, 8), 256, SMEM_HMMA>>>(
        OF_WPH, OF_WPL, 384, OF_XRTH, OF_XRTL, 384, (long)KFC * 384,
        OF_REL5, KFC, 256L * KFC, 384, 1);
    // 13. combine + relu -> R^T bf16 hi/lo [2048][12544]
    combine_rel_kernel<<<dim3(256, 8), 256>>>(b_rf);
    // 14. rel FC (HMMA, split-K 14) + reduce
    hmma_gemm_kernel<<<dim3(16, 2, SPLK), 256, SMEM_HMMA>>>(
        OF_WRH, OF_WRL, KFC, OF_RTH, OF_RTL, KFC, 0,
        OF_FP, 2048, 256L * 2048, KFC / SPLK, 0);
    reduce_split_kernel<<<2048, 256>>>(OF_FP, OF_FREL, 256L * 2048, 2048, SPLK, b_rfc);
    // 15. relu(obj) -> Robj^T bf16 hi/lo [128][12544]
    combine_obj_kernel<<<128, 256>>>();
    // 16. obj FC (HMMA, split-K 49) + reduce
    hmma_gemm_kernel<<<dim3(1, 2, SPLKO), 256, SMEM_HMMA>>>(
        OF_WOH, OF_WOL, KFC, OF_ROH, OF_ROL, KFC, 0,
        OF_FPO, 128, 256L * 128, KFC / SPLKO, 0);
    reduce_split_kernel<<<128, 256>>>(OF_FPO, OF_FOBJ, 256L * 128, 128, SPLKO, b_ofc);
    // 17-18. l2norm heads
    finalize_kernel<<<128, 256>>>(OF_FOBJ, 128, out);
    finalize_kernel<<<2048, 256>>>(OF_FREL, 2048, out + 32768);
}

// round 7
// speedup vs baseline: 3.0310x; 1.0327x over previous
#include <cuda_runtime.h>
#include <cuda_bf16.h>
#include <math.h>
#include <stdint.h>

namespace sg {
constexpr int Bn = 8, Cc = 256, Nn = 16;
constexpr int HW = 384;
constexpr int C32 = 384;
constexpr float SCALE = 1.0f / 16.0f;
constexpr float IMGW = 384.0f, IMGH = 256.0f;
constexpr int PP = 49;
constexpr int KFC = 12544;            // 256*49
constexpr int SPLK = 14;              // rel FC split-K  (14*896 = 12544)
constexpr int SPLKO = 49;             // obj FC split-K  (49*256 = 12544)

constexpr long SZ_CTXF  = (long)Bn * Cc * HW;
constexpr long SZ_RELF  = (long)Bn * C32 * HW;
constexpr long SZ_FEATT = SZ_CTXF;
constexpr long SZ_RELFT = SZ_RELF;
constexpr long SZ_PCTX  = (long)Bn * Cc * PP;
constexpr long SZ_BIMAP = (long)Bn * Nn * PP;
constexpr long SZ_XOBJ  = (long)Bn * 512 * 784;
constexpr long SZ_OBJ   = (long)Bn * 256 * 784;
constexpr long SZ_ASUB  = SZ_OBJ;
constexpr long SZ_AOBJ  = SZ_OBJ;
constexpr long SZ_FREL  = 256L * 2048;
constexpr long SZ_FOBJ  = 256L * 128;
constexpr long SZ_FP    = (long)SPLK * 256 * 2048;
constexpr long SZ_FPO   = (long)SPLKO * 256 * 128;
// bf16 buffers (sizes in float units = bf16count/2)
constexpr long FU_WP  = 256L * 384 / 2;
constexpr long FU_XRT = (long)Bn * KFC * 384 / 2;
constexpr long FU_WR  = 256L * KFC / 2;
constexpr long FU_RT  = 2048L * KFC / 2;
constexpr long FU_WO  = FU_WR;
constexpr long FU_RO  = 128L * KFC / 2;

constexpr long OF_CTXF  = 0;
constexpr long OF_RELF  = OF_CTXF  + SZ_CTXF;
constexpr long OF_FEATT = OF_RELF  + SZ_RELF;
constexpr long OF_RELFT = OF_FEATT + SZ_FEATT;
constexpr long OF_PCTX  = OF_RELFT + SZ_RELFT;
constexpr long OF_BIMAP = OF_PCTX  + SZ_PCTX;
constexpr long OF_XOBJ  = OF_BIMAP + SZ_BIMAP;
constexpr long OF_OBJ   = OF_XOBJ  + SZ_XOBJ;
constexpr long OF_ASUB  = OF_OBJ   + SZ_OBJ;
constexpr long OF_AOBJ  = OF_ASUB  + SZ_ASUB;
constexpr long OF_FREL  = OF_AOBJ  + SZ_AOBJ;
constexpr long OF_FOBJ  = OF_FREL  + SZ_FREL;
constexpr long OF_FP    = OF_FOBJ  + SZ_FOBJ;
constexpr long OF_FPO   = OF_FP    + SZ_FP;
constexpr long OF_WPH   = OF_FPO   + SZ_FPO;
constexpr long OF_WPL   = OF_WPH   + FU_WP;
constexpr long OF_XRTH  = OF_WPL   + FU_WP;
constexpr long OF_XRTL  = OF_XRTH  + FU_XRT;
constexpr long OF_WRH   = OF_XRTL  + FU_XRT;
constexpr long OF_WRL   = OF_WRH   + FU_WR;
constexpr long OF_RTH   = OF_WRL   + FU_WR;
constexpr long OF_RTL   = OF_RTH   + FU_RT;
constexpr long OF_WOH   = OF_RTL   + FU_RT;
constexpr long OF_WOL   = OF_WOH   + FU_WO;
constexpr long OF_ROH   = OF_WOL   + FU_WO;
constexpr long OF_ROL   = OF_ROH   + FU_RO;
constexpr long TOTAL    = OF_ROL   + FU_RO;
}  // namespace sg

__device__ float g_buf[sg::TOTAL];

// ========================= low-level helpers ===============================
__device__ __forceinline__ uint32_t smem_u32(const void* p) {
    uint32_t a;
    asm("{ .reg .u64 t; cvta.to.shared.u64 t, %1; cvt.u32.u64 %0, t; }" : "=r"(a) : "l"(p));
    return a;
}
__device__ __forceinline__ void cp_async16(uint32_t dst, const void* src) {
    asm volatile("cp.async.cg.shared.global [%0], [%1], 16;" :: "r"(dst), "l"(src));
}
__device__ __forceinline__ void cp_commit() {
    asm volatile("cp.async.commit_group;" ::: "memory");
}
__device__ __forceinline__ void ldsm4(uint32_t* a, uint32_t addr) {
    asm volatile("ldmatrix.sync.aligned.m8n8.x4.shared.b16 {%0,%1,%2,%3}, [%4];"
        : "=r"(a[0]), "=r"(a[1]), "=r"(a[2]), "=r"(a[3]) : "r"(addr));
}
__device__ __forceinline__ void ldsm2(uint32_t* b, uint32_t addr) {
    asm volatile("ldmatrix.sync.aligned.m8n8.x2.shared.b16 {%0,%1}, [%2];"
        : "=r"(b[0]), "=r"(b[1]) : "r"(addr));
}
__device__ __forceinline__ void mma16816(float* d, const uint32_t* a, const uint32_t* b) {
    asm volatile("mma.sync.aligned.m16n8k16.row.col.f32.bf16.bf16.f32 "
        "{%0,%1,%2,%3}, {%4,%5,%6,%7}, {%8,%9}, {%0,%1,%2,%3};"
        : "+f"(d[0]), "+f"(d[1]), "+f"(d[2]), "+f"(d[3])
        : "r"(a[0]), "r"(a[1]), "r"(a[2]), "r"(a[3]), "r"(b[0]), "r"(b[1]));
}
__device__ __forceinline__ void split_bf16(float x, __nv_bfloat16& h, __nv_bfloat16& l) {
    h = __float2bfloat16(x);
    l = __float2bfloat16(x - __bfloat162float(h));
}

// ========================= PrRoI pooling helpers ===========================
static __device__ __forceinline__ float hatG(float t) {
    float tl = fminf(fmaxf(t, -1.0f), 0.0f);
    float tr = fminf(fmaxf(t, 0.0f), 1.0f);
    return 0.5f * (tl + 1.0f) * (tl + 1.0f) + 0.5f - 0.5f * (1.0f - tr) * (1.0f - tr);
}

static __device__ __forceinline__ void compute_weights(
    float x1, float y1, float x2, float y2,
    float (*wy)[16], float (*wx)[24],
    int* h0, int* h1, int* w0, int* w1, int tid)
{
    if (tid < 112) {
        int p = tid / 16, i = tid % 16;
        float e0 = y1 + (y2 - y1) * (float)p * (1.0f / 7.0f);
        float e1 = y1 + (y2 - y1) * (float)(p + 1) * (1.0f / 7.0f);
        wy[p][i] = hatG(e1 - (float)i) - hatG(e0 - (float)i);
    }
    if (tid < 168) {
        int q = tid / 24, i = tid % 24;
        float e0 = x1 + (x2 - x1) * (float)q * (1.0f / 7.0f);
        float e1 = x1 + (x2 - x1) * (float)(q + 1) * (1.0f / 7.0f);
        wx[q][i] = hatG(e1 - (float)i) - hatG(e0 - (float)i);
    }
    if (tid < 7) {
        float e0 = y1 + (y2 - y1) * (float)tid * (1.0f / 7.0f);
        float e1 = y1 + (y2 - y1) * (float)(tid + 1) * (1.0f / 7.0f);
        h0[tid] = max(0, (int)ceilf(e0) - 1);
        h1[tid] = min(16, (int)floorf(e1) + 2);
    }
    if (tid >= 32 && tid < 39) {
        int q = tid - 32;
        float e0 = x1 + (x2 - x1) * (float)q * (1.0f / 7.0f);
        float e1 = x1 + (x2 - x1) * (float)(q + 1) * (1.0f / 7.0f);
        w0[q] = max(0, (int)ceilf(e0) - 1);
        w1[q] = min(24, (int)floorf(e1) + 2);
    }
}

static __device__ __forceinline__ void pool_channel_acc(
    const float* __restrict__ fb, int ps,
    const float (*wy)[16], const float (*wx)[24],
    const int* h0, const int* h1, const int* w0, const int* w1,
    float* acc)
{
#pragma unroll
    for (int p = 0; p < 7; p++) {
        for (int h = h0[p]; h < h1[p]; h++) {
            float wyv = wy[p][h];
            const float* row = fb + (long)h * 24 * ps;
#pragma unroll
            for (int q = 0; q < 7; q++) {
                float a = 0.0f;
                for (int w = w0[q]; w < w1[q]; w++)
                    a += wx[q][w] * row[(long)w * ps];
                acc[p * 7 + q] += wyv * a;
            }
        }
    }
}

// ===================== dual 1x1 conv (ctx + rel in one launch) =============
// Rows [0,256): C_ctx = W_ctx x feat; rows [256,640): C_rel = W_rel x feat.
// grid(6, 10, 8), block 256. K=256, N=384 exact.
__global__ void __launch_bounds__(256) conv_dual_kernel(
    const float* __restrict__ input,
    const float* __restrict__ Wctx, const float* __restrict__ bctx,
    const float* __restrict__ Wrel, const float* __restrict__ brel)
{
    using namespace sg;
    __shared__ float As[16][65];
    __shared__ float Bs[16][68];

    const int b = blockIdx.z;
    const int tid = threadIdx.x;
    const int row0 = blockIdx.y * 64;
    const int col0 = blockIdx.x * 64;
    const bool isCtx = row0 < 256;
    const float* A = isCtx ? (Wctx + (long)row0 * 256)
                           : (Wrel + (long)(row0 - 256) * 256);
    const float* bias = isCtx ? bctx : brel;
    const int biasBase = isCtx ? row0 : row0 - 256;
    const float* Bm = input + (long)b * Cc * HW;
    float* Cm = isCtx ? (g_buf + OF_CTXF + (long)b * Cc * HW + (long)row0 * 384)
                      : (g_buf + OF_RELF + (long)b * C32 * HW + (long)(row0 - 256) * 384);

    const int ty = tid >> 4, tx = tid & 15;
    const int ty4 = ty * 4, tx4 = tx * 4;
    const int ar = tid >> 2, ak = (tid & 3) << 2;
    const int br = tid >> 4, bc = (tid & 15) << 2;

    float acc[4][4] = {};

    for (int k0 = 0; k0 < 256; k0 += 16) {
        float4 av = *(const float4*)(A + (long)ar * 256 + k0 + ak);
        As[ak + 0][ar] = av.x; As[ak + 1][ar] = av.y;
        As[ak + 2][ar] = av.z; As[ak + 3][ar] = av.w;
        float4 bv = *(const float4*)(Bm + (long)(k0 + br) * 384 + col0 + bc);
        *(float4*)&Bs[br][bc] = bv;
        __syncthreads();

#pragma unroll
        for (int k = 0; k < 16; k++) {
            float a0 = As[k][ty4 + 0], a1 = As[k][ty4 + 1];
            float a2 = As[k][ty4 + 2], a3 = As[k][ty4 + 3];
            float4 b4 = *(const float4*)&Bs[k][tx4];
            acc[0][0] += a0 * b4.x; acc[0][1] += a0 * b4.y; acc[0][2] += a0 * b4.z; acc[0][3] += a0 * b4.w;
            acc[1][0] += a1 * b4.x; acc[1][1] += a1 * b4.y; acc[1][2] += a1 * b4.z; acc[1][3] += a1 * b4.w;
            acc[2][0] += a2 * b4.x; acc[2][1] += a2 * b4.y; acc[2][2] += a2 * b4.z; acc[2][3] += a2 * b4.w;
            acc[3][0] += a3 * b4.x; acc[3][1] += a3 * b4.y; acc[3][2] += a3 * b4.z; acc[3][3] += a3 * b4.w;
        }
        __syncthreads();
    }

#pragma unroll
    for (int u = 0; u < 4; u++) {
        float bz = bias[biasBase + ty4 + u];
#pragma unroll
        for (int v = 0; v < 4; v++)
            Cm[(long)(ty4 + u) * 384 + col0 + tx4 + v] = acc[u][v] + bz;
    }
}

// fp32 128x128 GEMM, optional multi-term (nTerm>1: blockIdx.y folds term idx;
// A offset += term*dAoff, C offset += term*dCoff).
__global__ void __launch_bounds__(256) sgemm128_kernel(
    const float* __restrict__ Aex, long offA, int lda,
    long offB, int ldb, long sBb,
    long offC, int ldc, long sCb,
    int N, int K, int kChunk, int splitK,
    const float* __restrict__ bias,
    int nTerm, long dAoff, long dCoff)
{
    __shared__ float As[2][8][132];
    __shared__ float Bs[2][8][132];

    const int z = blockIdx.z;
    const int b = z / splitK;
    const int ks = z - b * splitK;
    const int kBeg = ks * kChunk;
    const int kEnd = min(K, kBeg + kChunk);
    const int nk = (kEnd - kBeg) >> 3;

    const int rowTiles = gridDim.y / nTerm;
    const int term = blockIdx.y / rowTiles;
    const int row0 = (blockIdx.y - term * rowTiles) * 128;
    const int col0 = blockIdx.x * 128;

    const float* A = Aex + offA + (long)term * dAoff;
    const float* B = g_buf + offB + (long)b * sBb;
    float* C = g_buf + offC + (long)term * dCoff + (long)z * sCb;

    const int t = threadIdx.x;
    const int arow = t >> 1, akq = (t & 1) << 2;
    const int brow = t >> 5, bcol = (t & 31) << 2;
    const int tx = t & 15, ty = t >> 4;

    const float* aPtr = A + (long)(row0 + arow) * lda + kBeg + akq;
    const float* bPtr = B + (long)(kBeg + brow) * ldb + col0 + bcol;
    const bool bIn = (col0 + bcol + 3) < N;

    float4 pa = *(const float4*)aPtr;
    float4 pb;
    if (bIn) {
        pb = *(const float4*)bPtr;
    } else {
        pb.x = (col0 + bcol + 0 < N) ? bPtr[0] : 0.0f;
        pb.y = (col0 + bcol + 1 < N) ? bPtr[1] : 0.0f;
        pb.z = (col0 + bcol + 2 < N) ? bPtr[2] : 0.0f;
        pb.w = 0.0f;
    }
    As[0][akq + 0][arow] = pa.x; As[0][akq + 1][arow] = pa.y;
    As[0][akq + 2][arow] = pa.z; As[0][akq + 3][arow] = pa.w;
    *(float4*)&Bs[0][brow][bcol] = pb;
    __syncthreads();

    float acc[8][8] = {};

    for (int kt = 0; kt < nk; kt++) {
        const int buf = kt & 1;
        if (kt + 1 < nk) {
            pa = *(const float4*)(aPtr + (kt + 1) * 8);
            const float* bp = bPtr + (long)(kt + 1) * 8 * ldb;
            if (bIn) {
                pb = *(const float4*)bp;
            } else {
                pb.x = (col0 + bcol + 0 < N) ? bp[0] : 0.0f;
                pb.y = (col0 + bcol + 1 < N) ? bp[1] : 0.0f;
                pb.z = (col0 + bcol + 2 < N) ? bp[2] : 0.0f;
                pb.w = 0.0f;
            }
        }
#pragma unroll
        for (int kk = 0; kk < 8; kk++) {
            float4 a0 = *(const float4*)&As[buf][kk][ty * 4];
            float4 a1 = *(const float4*)&As[buf][kk][64 + ty * 4];
            float4 b0 = *(const float4*)&Bs[buf][kk][tx * 4];
            float4 b1 = *(const float4*)&Bs[buf][kk][64 + tx * 4];
            float av[8] = {a0.x, a0.y, a0.z, a0.w, a1.x, a1.y, a1.z, a1.w};
            float bv[8] = {b0.x, b0.y, b0.z, b0.w, b1.x, b1.y, b1.z, b1.w};
#pragma unroll
            for (int u = 0; u < 8; u++)
#pragma unroll
                for (int v = 0; v < 8; v++)
                    acc[u][v] += av[u] * bv[v];
        }
        if (kt + 1 < nk) {
            const int nb = buf ^ 1;
            As[nb][akq + 0][arow] = pa.x; As[nb][akq + 1][arow] = pa.y;
            As[nb][akq + 2][arow] = pa.z; As[nb][akq + 3][arow] = pa.w;
            *(float4*)&Bs[nb][brow][bcol] = pb;
            __syncthreads();
        }
    }

#pragma unroll
    for (int u = 0; u < 8; u++) {
        int r = row0 + ((u < 4) ? ty * 4 + u : 64 + ty * 4 + (u - 4));
        float bz = bias ? bias[r] : 0.0f;
#pragma unroll
        for (int v = 0; v < 8; v++) {
            int c = col0 + ((v < 4) ? tx * 4 + v : 64 + tx * 4 + (v - 4));
            if (c < N) C[(long)r * ldc + c] = acc[u][v] + bz;
        }
    }
}

// ================ HMMA (mma.sync) bf16-split GEMM ==========================
// 3 terms (hh + hl + lh), fp32 acc. Tile 128x128, 8 warps (2x4, 64x32 each).
// epiMode 0: plain fp32 store to C.
// epiMode 1: rel-combine: relu(acc + Asub[b][o][i*49+s] + Aobj[b][o][j*49+s]
//            + brf[o]) -> bf16 hi/lo R^T at [(b*256+pair)][o*49+s].
__global__ void __launch_bounds__(256) hmma_gemm_kernel(
    long offAhi, long offAlo, int lda,
    long offBhi, long offBlo, int ldb, long sBz,
    long offC, int ldc, long sCz,
    int kChunk, int batchB, int epiMode,
    long offAsub, long offAobj, const float* __restrict__ brf,
    long offRh, long offRl)
{
    extern __shared__ __nv_bfloat16 smb[];
    constexpr int STR = 40;
    constexpr int TILEE = 128 * STR;

    const int tid = threadIdx.x;
    const int warp = tid >> 5, lane = tid & 31;
    const int z = blockIdx.z;
    const int row0 = blockIdx.y * 128, col0 = blockIdx.x * 128;
    const long kBeg = batchB ? 0 : (long)z * kChunk;
    const int S = kChunk / 32;

    const __nv_bfloat16* Ahi = (const __nv_bfloat16*)(g_buf + offAhi);
    const __nv_bfloat16* Alo = (const __nv_bfloat16*)(g_buf + offAlo);
    const __nv_bfloat16* Bhi = (const __nv_bfloat16*)(g_buf + offBhi) + (batchB ? (long)z * sBz : 0);
    const __nv_bfloat16* Blo = (const __nv_bfloat16*)(g_buf + offBlo) + (batchB ? (long)z * sBz : 0);

    const int wm = (warp >> 2) * 64;
    const int wn = (warp & 3) * 32;

    float acc[4][4][4] = {};

    const uint32_t smem_base = smem_u32(smb);

    auto issue_load = [&](int s, int buf) {
        long koff = kBeg + (long)s * 32;
        uint32_t dstBase = smem_base + (uint32_t)buf * 4 * TILEE * 2;
#pragma unroll
        for (int t = 0; t < 4; t++) {
            const __nv_bfloat16* src = (t == 0) ? Ahi : (t == 1) ? Alo
                                      : (t == 2) ? Bhi : Blo;
            const int base0 = (t < 2) ? row0 : col0;
            const int ld = (t < 2) ? lda : ldb;
#pragma unroll
            for (int i = 0; i < 2; i++) {
                int idx = tid + i * 256;
                int r = idx >> 2;
                int cg = (idx & 3) * 8;
                cp_async16(dstBase + (uint32_t)((t * TILEE + r * STR + cg) * 2),
                           src + (long)(base0 + r) * ld + koff + cg);
            }
        }
        cp_commit();
    };

    issue_load(0, 0);

    for (int s = 0; s < S; s++) {
        if (s + 1 < S) {
            issue_load(s + 1, (s + 1) & 1);
            asm volatile("cp.async.wait_group 1;" ::: "memory");
        } else {
            asm volatile("cp.async.wait_group 0;" ::: "memory");
        }
        __syncthreads();

        const int buf = s & 1;
        const uint32_t tb = smem_base + (uint32_t)buf * 4 * TILEE * 2;
        const uint32_t aHiB = tb;
        const uint32_t aLoB = tb + TILEE * 2;
        const uint32_t bHiB = tb + 2 * TILEE * 2;
        const uint32_t bLoB = tb + 3 * TILEE * 2;
        const int lr = lane & 15;
        const int kofA = (lane >> 4) * 8;
        const int kofB = ((lane & 15) >> 3) * 8;

#pragma unroll
        for (int k16 = 0; k16 < 2; k16++) {
            uint32_t af[4][4], bh[4][2], bl[4][2];
#pragma unroll
            for (int mi = 0; mi < 4; mi++)
                ldsm4(af[mi], aHiB + (uint32_t)(((wm + mi * 16 + lr) * STR)
                                               + k16 * 16 + kofA) * 2);
#pragma unroll
            for (int ni = 0; ni < 4; ni++) {
                uint32_t ro = (uint32_t)(((wn + ni * 8 + (lr & 7)) * STR)
                                         + k16 * 16 + kofB) * 2;
                ldsm2(bh[ni], bHiB + ro);
                ldsm2(bl[ni], bLoB + ro);
            }
#pragma unroll
            for (int mi = 0; mi < 4; mi++)
#pragma unroll
                for (int ni = 0; ni < 4; ni++) {
                    mma16816(acc[mi][ni], af[mi], bh[ni]);   // hh
                    mma16816(acc[mi][ni], af[mi], bl[ni]);   // hl
                }
#pragma unroll
            for (int mi = 0; mi < 4; mi++)
                ldsm4(af[mi], aLoB + (uint32_t)(((wm + mi * 16 + lr) * STR)
                                               + k16 * 16 + kofA) * 2);
#pragma unroll
            for (int mi = 0; mi < 4; mi++)
#pragma unroll
                for (int ni = 0; ni < 4; ni++)
                    mma16816(acc[mi][ni], af[mi], bh[ni]);   // lh
        }
        __syncthreads();
    }

    if (epiMode == 0) {
        float* C = g_buf + offC + (long)z * sCz;
#pragma unroll
        for (int mi = 0; mi < 4; mi++) {
            int r = row0 + wm + mi * 16 + (lane >> 2);
#pragma unroll
            for (int ni = 0; ni < 4; ni++) {
                int cc = col0 + wn + ni * 8 + (lane & 3) * 2;
                *(float2*)&C[(long)r * ldc + cc] = make_float2(acc[mi][ni][0], acc[mi][ni][1]);
                *(float2*)&C[(long)(r + 8) * ldc + cc] = make_float2(acc[mi][ni][2], acc[mi][ni][3]);
            }
        }
    } else {
        using namespace sg;
        const float* A1b = g_buf + offAsub + (long)z * 256 * 784;
        const float* A2b = g_buf + offAobj + (long)z * 256 * 784;
        __nv_bfloat16* rh = (__nv_bfloat16*)(g_buf + offRh) + (long)z * 256 * KFC;
        __nv_bfloat16* rl = (__nv_bfloat16*)(g_buf + offRl) + (long)z * 256 * KFC;
#pragma unroll
        for (int mi = 0; mi < 4; mi++) {
#pragma unroll
            for (int half = 0; half < 2; half++) {
                int o = row0 + wm + mi * 16 + (lane >> 2) + half * 8;
                float bz = brf[o];
#pragma unroll
                for (int ni = 0; ni < 4; ni++) {
#pragma unroll
                    for (int e = 0; e < 2; e++) {
                        int cc = col0 + wn + ni * 8 + (lane & 3) * 2 + e;
                        int pair = cc / 49;
                        int s = cc - pair * 49;
                        int io = (pair >> 4) * 49 + s;
                        int jo = (pair & 15) * 49 + s;
                        float v = acc[mi][ni][half * 2 + e]
                                + A1b[(long)o * 784 + io]
                                + A2b[(long)o * 784 + jo] + bz;
                        v = fmaxf(v, 0.0f);
                        __nv_bfloat16 h, l;
                        split_bf16(v, h, l);
                        long di = (long)pair * KFC + o * 49 + s;
                        rh[di] = h;
                        rl[di] = l;
                    }
                }
            }
        }
    }
}

// ==================== misc data-movement / pooling =========================
__global__ void transpose_kernel(const float* __restrict__ srcExt,
                                 long offSrc, long offDst, int R, int C)
{
    __shared__ float tile[32][33];
    int b = blockIdx.z;
    const float* src = (srcExt ? srcExt : (const float*)g_buf + offSrc) + (long)b * R * C;
    float* dst = g_buf + offDst + (long)b * R * C;
    int c0 = blockIdx.x * 32, r0 = blockIdx.y * 32;
    int tx = threadIdx.x, ty = threadIdx.y;
#pragma unroll
    for (int k = 0; k < 32; k += 8)
        tile[ty + k][tx] = src[(long)(r0 + ty + k) * C + c0 + tx];
    __syncthreads();
#pragma unroll
    for (int k = 0; k < 32; k += 8)
        dst[(long)(c0 + ty + k) * R + r0 + tx] = tile[tx][ty + k];
}

__global__ void __launch_bounds__(256) pool_obj_kernel(const float* __restrict__ boxes)
{
    using namespace sg;
    int b = blockIdx.y, n = blockIdx.x, tid = threadIdx.x;
    const float* bx = boxes + ((long)b * Nn + n) * 4;
    float x1 = bx[0], y1 = bx[1], x2 = bx[2], y2 = bx[3];
    float sx1 = x1 * SCALE, sy1 = y1 * SCALE, sx2 = x2 * SCALE, sy2 = y2 * SCALE;

    __shared__ float wy[7][16], wx[7][24];
    __shared__ int h0[7], h1[7], w0[7], w1[7];
    compute_weights(sx1, sy1, sx2, sy2, wy, wx, h0, h1, w0, w1, tid);

    if (tid < 49) {
        int p = tid / 7, q = tid % 7;
        float ye0 = IMGH * (float)p * (1.0f / 7.0f), ye1 = IMGH * (float)(p + 1) * (1.0f / 7.0f);
        float xe0 = IMGW * (float)q * (1.0f / 7.0f), xe1 = IMGW * (float)(q + 1) * (1.0f / 7.0f);
        float oy = fmaxf(fminf(ye1, y2) - fmaxf(ye0, y1), 0.0f);
        float ox = fmaxf(fminf(xe1, x2) - fmaxf(xe0, x1), 0.0f);
        float ch = IMGH * (1.0f / 7.0f), cw = IMGW * (1.0f / 7.0f);
        g_buf[OF_BIMAP + ((long)b * Nn + n) * PP + tid] = (oy / ch) * (ox / cw);
    }
    __syncthreads();

    float area = (sx2 - sx1) * (sy2 - sy1) * (1.0f / 49.0f);
    float inv = (area > 0.0f) ? 1.0f / fmaxf(area, 1e-9f) : 0.0f;

    int c = tid;
    const float* fb = g_buf + OF_FEATT + (long)b * HW * Cc + c;
    float acc[49];
#pragma unroll
    for (int s = 0; s < 49; s++) acc[s] = 0.0f;
    pool_channel_acc(fb, Cc, wy, wx, h0, h1, w0, w1, acc);

    float* X = g_buf + OF_XOBJ + ((long)b * 512 + c) * 784 + (long)n * 49;
#pragma unroll
    for (int s = 0; s < 49; s++) X[s] = acc[s] * inv;
}

__global__ void __launch_bounds__(256) pool_ctx_kernel()
{
    using namespace sg;
    int b = blockIdx.x, tid = threadIdx.x;
    __shared__ float wy[7][16], wx[7][24];
    __shared__ int h0[7], h1[7], w0[7], w1[7];
    compute_weights(0.0f, 0.0f, 24.0f, 16.0f, wy, wx, h0, h1, w0, w1, tid);
    __syncthreads();

    float inv = 49.0f / (24.0f * 16.0f);
    int c = tid;
    const float* fb = g_buf + OF_CTXF + ((long)b * Cc + c) * HW;
    float acc[49];
#pragma unroll
    for (int s = 0; s < 49; s++) acc[s] = 0.0f;
    pool_channel_acc(fb, 1, wy, wx, h0, h1, w0, w1, acc);
    float* X = g_buf + OF_PCTX + ((long)b * Cc + c) * PP;
#pragma unroll
    for (int s = 0; s < 49; s++) X[s] = acc[s] * inv;
}

__global__ void pack_xobj_kernel()
{
    using namespace sg;
    int b = blockIdx.y;
    int base = blockIdx.x * blockDim.x + threadIdx.x;
    int stride = gridDim.x * blockDim.x;
    for (int idx = base; idx < 256 * 784; idx += stride) {
        int cc = idx / 784, rem = idx - cc * 784;
        int n = rem / 49, s = rem - n * 49;
        float v = g_buf[OF_PCTX + ((long)b * Cc + cc) * PP + s];
        if (cc >= 128) v *= g_buf[OF_BIMAP + ((long)b * Nn + n) * PP + s];
        g_buf[OF_XOBJ + ((long)b * 512 + 256 + cc) * 784 + rem] = v;
    }
}

// pool rel feats over union boxes -> XrelT hi/lo [b][pair*49+s][384] bf16
__global__ void __launch_bounds__(384) pool_rel_kernel(const float* __restrict__ boxes)
{
    using namespace sg;
    extern __shared__ float stage[];
    int b = blockIdx.y, pair = blockIdx.x, tid = threadIdx.x;
    int i = pair >> 4, j = pair & 15;
    const float* bi = boxes + ((long)b * Nn + i) * 4;
    const float* bj = boxes + ((long)b * Nn + j) * 4;
    float ix1 = bi[0], iy1 = bi[1], ix2 = bi[2], iy2 = bi[3];
    float jx1 = bj[0], jy1 = bj[1], jx2 = bj[2], jy2 = bj[3];
    float ux1 = fminf(ix1, jx1), uy1 = fminf(iy1, jy1);
    float ux2 = fmaxf(ix2, jx2), uy2 = fmaxf(iy2, jy2);
    float sx1 = ux1 * SCALE, sy1 = uy1 * SCALE, sx2 = ux2 * SCALE, sy2 = uy2 * SCALE;

    __shared__ float wy[7][16], wx[7][24];
    __shared__ int h0[7], h1[7], w0[7], w1[7];
    __shared__ float subm[49], objm[49];
    compute_weights(sx1, sy1, sx2, sy2, wy, wx, h0, h1, w0, w1, tid);

    if (tid < 49) {
        int p = tid / 7, q = tid - p * 7;
        float ye0 = uy1 + (uy2 - uy1) * (float)p * (1.0f / 7.0f);
        float ye1 = uy1 + (uy2 - uy1) * (float)(p + 1) * (1.0f / 7.0f);
        float xe0 = ux1 + (ux2 - ux1) * (float)q * (1.0f / 7.0f);
        float xe1 = ux1 + (ux2 - ux1) * (float)(q + 1) * (1.0f / 7.0f);
        float ch = fmaxf((uy2 - uy1) * (1.0f / 7.0f), 1e-9f);
        float cw = fmaxf((ux2 - ux1) * (1.0f / 7.0f), 1e-9f);
        float oy = fmaxf(fminf(ye1, iy2) - fmaxf(ye0, iy1), 0.0f);
        float ox = fmaxf(fminf(xe1, ix2) - fmaxf(xe0, ix1), 0.0f);
        subm[tid] = (oy / ch) * (ox / cw);
        oy = fmaxf(fminf(ye1, jy2) - fmaxf(ye0, jy1), 0.0f);
        ox = fmaxf(fminf(xe1, jx2) - fmaxf(xe0, jx1), 0.0f);
        objm[tid] = (oy / ch) * (ox / cw);
    }
    __syncthreads();

    float area = (sx2 - sx1) * (sy2 - sy1) * (1.0f / 49.0f);
    float inv = (area > 0.0f) ? 1.0f / fmaxf(area, 1e-9f) : 0.0f;

    int c = tid;
    const float* fb = g_buf + OF_RELFT + (long)b * HW * C32 + c;
    float acc[49];
#pragma unroll
    for (int s = 0; s < 49; s++) acc[s] = 0.0f;
    pool_channel_acc(fb, C32, wy, wx, h0, h1, w0, w1, acc);

#pragma unroll
    for (int s = 0; s < 49; s++) {
        float mk = (c < 128) ? 1.0f : (c < 256 ? subm[s] : objm[s]);
        stage[c * 49 + s] = acc[s] * inv * mk;
    }
    __syncthreads();

    __nv_bfloat16* xh = (__nv_bfloat16*)(g_buf + OF_XRTH);
    __nv_bfloat16* xl = (__nv_bfloat16*)(g_buf + OF_XRTL);
    long rowBase = ((long)b * KFC + (long)pair * 49) * 384;
    for (int idx = tid; idx < 49 * 384; idx += 384) {
        int s = idx / 384, cc = idx - s * 384;
        __nv_bfloat16 h, l;
        split_bf16(stage[cc * 49 + s], h, l);
        xh[rowBase + (long)s * 384 + cc] = h;
        xl[rowBase + (long)s * 384 + cc] = l;
    }
}

// relu(obj) -> Robj^T hi/lo [128][12544]
__global__ void __launch_bounds__(256) combine_obj_kernel()
{
    using namespace sg;
    int row = blockIdx.x;                 // b*16 + i
    int b = row >> 4, i = row & 15;
    const float* obj = g_buf + OF_OBJ + (long)b * 256 * 784 + (long)i * 49;
    __nv_bfloat16* rh = (__nv_bfloat16*)(g_buf + OF_ROH) + (long)row * KFC;
    __nv_bfloat16* rl = (__nv_bfloat16*)(g_buf + OF_ROL) + (long)row * KFC;
    for (int idx = threadIdx.x; idx < KFC; idx += 256) {
        int o = idx / 49, s = idx - o * 49;
        float v = fmaxf(obj[(long)o * 784 + s], 0.0f);
        __nv_bfloat16 h, l;
        split_bf16(v, h, l);
        rh[idx] = h; rl[idx] = l;
    }
}

// fp32 weight matrix (slice) -> contiguous bf16 hi/lo
__global__ void convert_w_kernel(const float* __restrict__ W, int lda, int colOff,
                                 long offHi, long offLo, long total, int Kout)
{
    __nv_bfloat16* ph = (__nv_bfloat16*)(g_buf + offHi);
    __nv_bfloat16* pl = (__nv_bfloat16*)(g_buf + offLo);
    for (long idx = (long)blockIdx.x * blockDim.x + threadIdx.x; idx < total;
         idx += (long)gridDim.x * blockDim.x) {
        long m = idx / Kout;
        int k = (int)(idx - m * Kout);
        float x = W[m * lda + colOff + k];
        __nv_bfloat16 h, l;
        split_bf16(x, h, l);
        ph[idx] = h; pl[idx] = l;
    }
}

__global__ void reduce_split_kernel(long offP, long offO, long MN, int Ncols,
                                    int S, const float* __restrict__ bias)
{
    long idx = (long)blockIdx.x * blockDim.x + threadIdx.x;
    if (idx >= MN) return;
    float s = 0.0f;
    for (int i = 0; i < S; i++) s += g_buf[offP + (long)i * MN + idx];
    int m = (int)(idx / Ncols);
    g_buf[offO + idx] = s + bias[m];
}

__global__ void finalize_kernel(long srcOff, int ncols, float* __restrict__ out)
{
    int col = blockIdx.x, n = threadIdx.x;
    float v = g_buf[srcOff + (long)n * ncols + col];
    float s = v * v;
#pragma unroll
    for (int o = 16; o > 0; o >>= 1) s += __shfl_xor_sync(0xffffffffu, s, o);
    __shared__ float red[8];
    if ((n & 31) == 0) red[n >> 5] = s;
    __syncthreads();
    float tot = red[0] + red[1] + red[2] + red[3] + red[4] + red[5] + red[6] + red[7];
    out[(long)col * 256 + n] = v / sqrtf(tot);
}

// ===========================================================================
extern "C" void kernel_launch(void* const* d_in, const int* in_sizes, int n_in,
                              void* d_out, int out_size)
{
    using namespace sg;
    const float* input = (const float*)d_in[0];
    const float* boxes = (const float*)d_in[1];
    const float* W_ctx = (const float*)d_in[3];
    const float* b_ctx = (const float*)d_in[4];
    const float* W_rel = (const float*)d_in[5];
    const float* b_rel = (const float*)d_in[6];
    const float* W_of  = (const float*)d_in[7];
    const float* b_of  = (const float*)d_in[8];
    const float* W_rf  = (const float*)d_in[9];
    const float* b_rf  = (const float*)d_in[10];
    const float* W_ofc = (const float*)d_in[11];
    const float* b_ofc = (const float*)d_in[12];
    const float* W_rfc = (const float*)d_in[13];
    const float* b_rfc = (const float*)d_in[14];
    float* out = (float*)d_out;

    const long s784  = 256L * 784;
    const int SMEM_HMMA = 2 * 4 * 128 * 40 * 2;   // 81920 bytes

    cudaFuncSetAttribute(hmma_gemm_kernel, cudaFuncAttributeMaxDynamicSharedMemorySize, SMEM_HMMA);
    cudaFuncSetAttribute(pool_rel_kernel, cudaFuncAttributeMaxDynamicSharedMemorySize, 384 * 49 * 4);

    // Weight conversions (independent of data path)
    convert_w_kernel<<<384, 256>>>(W_rf, 896, 512, OF_WPH, OF_WPL, 256L * 384, 384);
    convert_w_kernel<<<4096, 256>>>(W_rfc, KFC, 0, OF_WRH, OF_WRL, 256L * KFC, KFC);
    convert_w_kernel<<<4096, 256>>>(W_ofc, KFC, 0, OF_WOH, OF_WOL, 256L * KFC, KFC);

    // 1. fused ctx + rel 1x1 convs (fp32)
    conv_dual_kernel<<<dim3(6, 10, 8), 256>>>(input, W_ctx, b_ctx, W_rel, b_rel);
    // 2-3. transposes to [hw][c]
    transpose_kernel<<<dim3(12, 8, 8), dim3(32, 8)>>>(input, 0, OF_FEATT, 256, 384);
    transpose_kernel<<<dim3(12, 12, 8), dim3(32, 8)>>>(nullptr, OF_RELF, OF_RELFT, 384, 384);
    // 4-6. pooling + obj conv input assembly
    pool_ctx_kernel<<<8, 256>>>();
    pool_obj_kernel<<<dim3(16, 8), 256>>>(boxes);
    pack_xobj_kernel<<<dim3(16, 8), 256>>>();
    // 7. obj conv (fp32)
    sgemm128_kernel<<<dim3(7, 2, 8), 256>>>(W_of, 0, 512, OF_XOBJ, 784, 512L * 784,
                                            OF_OBJ, 784, s784, 784, 512, 512, 1, b_of,
                                            1, 0, 0);
    // 8. Asub + Aobj in ONE launch (term folded into grid.y)
    sgemm128_kernel<<<dim3(7, 4, 8), 256>>>(W_rf, 0, 896, OF_OBJ, 784, s784,
                                            OF_ASUB, 784, s784, 784, 256, 256, 1, nullptr,
                                            2, 256, OF_AOBJ - OF_ASUB);
    // 9. pool rel feats -> XrelT bf16 hi/lo
    pool_rel_kernel<<<dim3(256, 8), 384, 384 * 49 * 4>>>(boxes);
    // 10. pair GEMM (HMMA, batched) + FUSED combine/relu/split epilogue -> R^T
    hmma_gemm_kernel<<<dim3(98, 2, 8), 256, SMEM_HMMA>>>(
        OF_WPH, OF_WPL, 384, OF_XRTH, OF_XRTL, 384, (long)KFC * 384,
        0, 0, 0, 384, 1, 1, OF_ASUB, OF_AOBJ, b_rf, OF_RTH, OF_RTL);
    // 11. rel FC (HMMA, split-K 14) + reduce
    hmma_gemm_kernel<<<dim3(16, 2, SPLK), 256, SMEM_HMMA>>>(
        OF_WRH, OF_WRL, KFC, OF_RTH, OF_RTL, KFC, 0,
        OF_FP, 2048, 256L * 2048, KFC / SPLK, 0, 0, 0, 0, nullptr, 0, 0);
    reduce_split_kernel<<<2048, 256>>>(OF_FP, OF_FREL, 256L * 2048, 2048, SPLK, b_rfc);
    // 12. relu(obj) -> Robj^T bf16 hi/lo [128][12544]
    combine_obj_kernel<<<128, 256>>>();
    // 13. obj FC (HMMA, split-K 49) + reduce
    hmma_gemm_kernel<<<dim3(1, 2, SPLKO), 256, SMEM_HMMA>>>(
        OF_WOH, OF_WOL, KFC, OF_ROH, OF_ROL, KFC, 0,
        OF_FPO, 128, 256L * 128, KFC / SPLKO, 0, 0, 0, 0, nullptr, 0, 0);
    reduce_split_kernel<<<128, 256>>>(OF_FPO, OF_FOBJ, 256L * 128, 128, SPLKO, b_ofc);
    // 14-15. l2norm heads
    finalize_kernel<<<128, 256>>>(OF_FOBJ, 128, out);
    finalize_kernel<<<2048, 256>>>(OF_FREL, 2048, out + 32768);
}

// round 8
// speedup vs baseline: 4.5178x; 1.4906x over previous
#include <cuda_runtime.h>
#include <cuda_bf16.h>
#include <math.h>
#include <stdint.h>

namespace sg {
constexpr int Bn = 8, Cc = 256, Nn = 16;
constexpr int HW = 384;
constexpr int C32 = 384;
constexpr float SCALE = 1.0f / 16.0f;
constexpr float IMGW = 384.0f, IMGH = 256.0f;
constexpr int PP = 49;
constexpr int KFC = 12544;            // 256*49
constexpr int SPLK = 14;              // rel FC split-K  (14*896 = 12544)
constexpr int SPLKO = 49;             // obj FC split-K  (49*256 = 12544)

constexpr long SZ_CTXF  = (long)Bn * Cc * HW;
constexpr long SZ_RELF  = (long)Bn * C32 * HW;
constexpr long SZ_FEATT = SZ_CTXF;
constexpr long SZ_RELFT = SZ_RELF;
constexpr long SZ_PCTX  = (long)Bn * Cc * PP;
constexpr long SZ_BIMAP = (long)Bn * Nn * PP;
constexpr long SZ_XOBJ  = (long)Bn * 512 * 784;
constexpr long SZ_OBJ   = (long)Bn * 256 * 784;
constexpr long SZ_ASUB  = SZ_OBJ;
constexpr long SZ_AOBJ  = SZ_OBJ;
constexpr long SZ_FREL  = 256L * 2048;
constexpr long SZ_FOBJ  = 256L * 128;
constexpr long SZ_FP    = (long)SPLK * 256 * 2048;
constexpr long SZ_FPO   = (long)SPLKO * 256 * 128;
constexpr long FU_WP  = 256L * 384 / 2;
constexpr long FU_XRT = (long)Bn * KFC * 384 / 2;
constexpr long FU_WR  = 256L * KFC / 2;
constexpr long FU_RT  = 2048L * KFC / 2;
constexpr long FU_WO  = FU_WR;
constexpr long FU_RO  = 128L * KFC / 2;

constexpr long OF_CTXF  = 0;
constexpr long OF_RELF  = OF_CTXF  + SZ_CTXF;
constexpr long OF_FEATT = OF_RELF  + SZ_RELF;
constexpr long OF_RELFT = OF_FEATT + SZ_FEATT;
constexpr long OF_PCTX  = OF_RELFT + SZ_RELFT;
constexpr long OF_BIMAP = OF_PCTX  + SZ_PCTX;
constexpr long OF_XOBJ  = OF_BIMAP + SZ_BIMAP;
constexpr long OF_OBJ   = OF_XOBJ  + SZ_XOBJ;
constexpr long OF_ASUB  = OF_OBJ   + SZ_OBJ;
constexpr long OF_AOBJ  = OF_ASUB  + SZ_ASUB;
constexpr long OF_FREL  = OF_AOBJ  + SZ_AOBJ;
constexpr long OF_FOBJ  = OF_FREL  + SZ_FREL;
constexpr long OF_FP    = OF_FOBJ  + SZ_FOBJ;
constexpr long OF_FPO   = OF_FP    + SZ_FP;
constexpr long OF_WPH   = OF_FPO   + SZ_FPO;
constexpr long OF_WPL   = OF_WPH   + FU_WP;
constexpr long OF_XRTH  = OF_WPL   + FU_WP;
constexpr long OF_XRTL  = OF_XRTH  + FU_XRT;
constexpr long OF_WRH   = OF_XRTL  + FU_XRT;
constexpr long OF_WRL   = OF_WRH   + FU_WR;
constexpr long OF_RTH   = OF_WRL   + FU_WR;
constexpr long OF_RTL   = OF_RTH   + FU_RT;
constexpr long OF_WOH   = OF_RTL   + FU_RT;
constexpr long OF_WOL   = OF_WOH   + FU_WO;
constexpr long OF_ROH   = OF_WOL   + FU_WO;
constexpr long OF_ROL   = OF_ROH   + FU_RO;
constexpr long TOTAL    = OF_ROL   + FU_RO;
}  // namespace sg

__device__ float g_buf[sg::TOTAL];

// ========================= low-level helpers ===============================
__device__ __forceinline__ uint32_t smem_u32(const void* p) {
    uint32_t a;
    asm("{ .reg .u64 t; cvta.to.shared.u64 t, %1; cvt.u32.u64 %0, t; }" : "=r"(a) : "l"(p));
    return a;
}
__device__ __forceinline__ void cp_async16(uint32_t dst, const void* src) {
    asm volatile("cp.async.cg.shared.global [%0], [%1], 16;" :: "r"(dst), "l"(src));
}
__device__ __forceinline__ void cp_commit() {
    asm volatile("cp.async.commit_group;" ::: "memory");
}
__device__ __forceinline__ void ldsm4(uint32_t* a, uint32_t addr) {
    asm volatile("ldmatrix.sync.aligned.m8n8.x4.shared.b16 {%0,%1,%2,%3}, [%4];"
        : "=r"(a[0]), "=r"(a[1]), "=r"(a[2]), "=r"(a[3]) : "r"(addr));
}
__device__ __forceinline__ void ldsm2(uint32_t* b, uint32_t addr) {
    asm volatile("ldmatrix.sync.aligned.m8n8.x2.shared.b16 {%0,%1}, [%2];"
        : "=r"(b[0]), "=r"(b[1]) : "r"(addr));
}
__device__ __forceinline__ void mma16816(float* d, const uint32_t* a, const uint32_t* b) {
    asm volatile("mma.sync.aligned.m16n8k16.row.col.f32.bf16.bf16.f32 "
        "{%0,%1,%2,%3}, {%4,%5,%6,%7}, {%8,%9}, {%0,%1,%2,%3};"
        : "+f"(d[0]), "+f"(d[1]), "+f"(d[2]), "+f"(d[3])
        : "r"(a[0]), "r"(a[1]), "r"(a[2]), "r"(a[3]), "r"(b[0]), "r"(b[1]));
}
__device__ __forceinline__ void split_bf16(float x, __nv_bfloat16& h, __nv_bfloat16& l) {
    h = __float2bfloat16(x);
    l = __float2bfloat16(x - __bfloat162float(h));
}

// ========================= PrRoI pooling helpers ===========================
static __device__ __forceinline__ float hatG(float t) {
    float tl = fminf(fmaxf(t, -1.0f), 0.0f);
    float tr = fminf(fmaxf(t, 0.0f), 1.0f);
    return 0.5f * (tl + 1.0f) * (tl + 1.0f) + 0.5f - 0.5f * (1.0f - tr) * (1.0f - tr);
}

static __device__ __forceinline__ void compute_weights(
    float x1, float y1, float x2, float y2,
    float (*wy)[16], float (*wx)[24],
    int* h0, int* h1, int* w0, int* w1, int tid)
{
    if (tid < 112) {
        int p = tid / 16, i = tid % 16;
        float e0 = y1 + (y2 - y1) * (float)p * (1.0f / 7.0f);
        float e1 = y1 + (y2 - y1) * (float)(p + 1) * (1.0f / 7.0f);
        wy[p][i] = hatG(e1 - (float)i) - hatG(e0 - (float)i);
    }
    if (tid < 168) {
        int q = tid / 24, i = tid % 24;
        float e0 = x1 + (x2 - x1) * (float)q * (1.0f / 7.0f);
        float e1 = x1 + (x2 - x1) * (float)(q + 1) * (1.0f / 7.0f);
        wx[q][i] = hatG(e1 - (float)i) - hatG(e0 - (float)i);
    }
    if (tid < 7) {
        float e0 = y1 + (y2 - y1) * (float)tid * (1.0f / 7.0f);
        float e1 = y1 + (y2 - y1) * (float)(tid + 1) * (1.0f / 7.0f);
        h0[tid] = max(0, (int)ceilf(e0) - 1);
        h1[tid] = min(16, (int)floorf(e1) + 2);
    }
    if (tid >= 32 && tid < 39) {
        int q = tid - 32;
        float e0 = x1 + (x2 - x1) * (float)q * (1.0f / 7.0f);
        float e1 = x1 + (x2 - x1) * (float)(q + 1) * (1.0f / 7.0f);
        w0[q] = max(0, (int)ceilf(e0) - 1);
        w1[q] = min(24, (int)floorf(e1) + 2);
    }
}

// Separable pooling: each (h,w) pixel loaded once; colsum per q, then rank-1
// update into acc. Identical summation order per (p,q) as the naive version.
static __device__ __forceinline__ void pool_channel_acc(
    const float* __restrict__ fb, int ps,
    const float (*wy)[16], const float (*wx)[24],
    const int* h0, const int* h1, const int* w0, const int* w1,
    float* acc)
{
    const int hmin = h0[0], hmax = h1[6];   // edges monotone: box has y2>y1
    for (int h = hmin; h < hmax; h++) {
        const float* row = fb + (long)h * 24 * ps;
        float colsum[7];
#pragma unroll
        for (int q = 0; q < 7; q++) {
            float a = 0.0f;
            for (int w = w0[q]; w < w1[q]; w++)
                a += wx[q][w] * row[(long)w * ps];
            colsum[q] = a;
        }
#pragma unroll
        for (int p = 0; p < 7; p++) {
            float wv = wy[p][h];
#pragma unroll
            for (int q = 0; q < 7; q++)
                acc[p * 7 + q] += wv * colsum[q];
        }
    }
}

// ===================== dual 1x1 conv (ctx + rel in one launch) =============
__global__ void __launch_bounds__(256) conv_dual_kernel(
    const float* __restrict__ input,
    const float* __restrict__ Wctx, const float* __restrict__ bctx,
    const float* __restrict__ Wrel, const float* __restrict__ brel)
{
    using namespace sg;
    __shared__ float As[16][65];
    __shared__ float Bs[16][68];

    const int b = blockIdx.z;
    const int tid = threadIdx.x;
    const int row0 = blockIdx.y * 64;
    const int col0 = blockIdx.x * 64;
    const bool isCtx = row0 < 256;
    const float* A = isCtx ? (Wctx + (long)row0 * 256)
                           : (Wrel + (long)(row0 - 256) * 256);
    const float* bias = isCtx ? bctx : brel;
    const int biasBase = isCtx ? row0 : row0 - 256;
    const float* Bm = input + (long)b * Cc * HW;
    float* Cm = isCtx ? (g_buf + OF_CTXF + (long)b * Cc * HW + (long)row0 * 384)
                      : (g_buf + OF_RELF + (long)b * C32 * HW + (long)(row0 - 256) * 384);

    const int ty = tid >> 4, tx = tid & 15;
    const int ty4 = ty * 4, tx4 = tx * 4;
    const int ar = tid >> 2, ak = (tid & 3) << 2;
    const int br = tid >> 4, bc = (tid & 15) << 2;

    float acc[4][4] = {};

    for (int k0 = 0; k0 < 256; k0 += 16) {
        float4 av = *(const float4*)(A + (long)ar * 256 + k0 + ak);
        As[ak + 0][ar] = av.x; As[ak + 1][ar] = av.y;
        As[ak + 2][ar] = av.z; As[ak + 3][ar] = av.w;
        float4 bv = *(const float4*)(Bm + (long)(k0 + br) * 384 + col0 + bc);
        *(float4*)&Bs[br][bc] = bv;
        __syncthreads();

#pragma unroll
        for (int k = 0; k < 16; k++) {
            float a0 = As[k][ty4 + 0], a1 = As[k][ty4 + 1];
            float a2 = As[k][ty4 + 2], a3 = As[k][ty4 + 3];
            float4 b4 = *(const float4*)&Bs[k][tx4];
            acc[0][0] += a0 * b4.x; acc[0][1] += a0 * b4.y; acc[0][2] += a0 * b4.z; acc[0][3] += a0 * b4.w;
            acc[1][0] += a1 * b4.x; acc[1][1] += a1 * b4.y; acc[1][2] += a1 * b4.z; acc[1][3] += a1 * b4.w;
            acc[2][0] += a2 * b4.x; acc[2][1] += a2 * b4.y; acc[2][2] += a2 * b4.z; acc[2][3] += a2 * b4.w;
            acc[3][0] += a3 * b4.x; acc[3][1] += a3 * b4.y; acc[3][2] += a3 * b4.z; acc[3][3] += a3 * b4.w;
        }
        __syncthreads();
    }

#pragma unroll
    for (int u = 0; u < 4; u++) {
        float bz = bias[biasBase + ty4 + u];
#pragma unroll
        for (int v = 0; v < 4; v++)
            Cm[(long)(ty4 + u) * 384 + col0 + tx4 + v] = acc[u][v] + bz;
    }
}

// fp32 128x128 GEMM, optional multi-term via grid.y folding.
__global__ void __launch_bounds__(256) sgemm128_kernel(
    const float* __restrict__ Aex, long offA, int lda,
    long offB, int ldb, long sBb,
    long offC, int ldc, long sCb,
    int N, int K, int kChunk, int splitK,
    const float* __restrict__ bias,
    int nTerm, long dAoff, long dCoff)
{
    __shared__ float As[2][8][132];
    __shared__ float Bs[2][8][132];

    const int z = blockIdx.z;
    const int b = z / splitK;
    const int ks = z - b * splitK;
    const int kBeg = ks * kChunk;
    const int kEnd = min(K, kBeg + kChunk);
    const int nk = (kEnd - kBeg) >> 3;

    const int rowTiles = gridDim.y / nTerm;
    const int term = blockIdx.y / rowTiles;
    const int row0 = (blockIdx.y - term * rowTiles) * 128;
    const int col0 = blockIdx.x * 128;

    const float* A = Aex + offA + (long)term * dAoff;
    const float* B = g_buf + offB + (long)b * sBb;
    float* C = g_buf + offC + (long)term * dCoff + (long)z * sCb;

    const int t = threadIdx.x;
    const int arow = t >> 1, akq = (t & 1) << 2;
    const int brow = t >> 5, bcol = (t & 31) << 2;
    const int tx = t & 15, ty = t >> 4;

    const float* aPtr = A + (long)(row0 + arow) * lda + kBeg + akq;
    const float* bPtr = B + (long)(kBeg + brow) * ldb + col0 + bcol;
    const bool bIn = (col0 + bcol + 3) < N;

    float4 pa = *(const float4*)aPtr;
    float4 pb;
    if (bIn) {
        pb = *(const float4*)bPtr;
    } else {
        pb.x = (col0 + bcol + 0 < N) ? bPtr[0] : 0.0f;
        pb.y = (col0 + bcol + 1 < N) ? bPtr[1] : 0.0f;
        pb.z = (col0 + bcol + 2 < N) ? bPtr[2] : 0.0f;
        pb.w = 0.0f;
    }
    As[0][akq + 0][arow] = pa.x; As[0][akq + 1][arow] = pa.y;
    As[0][akq + 2][arow] = pa.z; As[0][akq + 3][arow] = pa.w;
    *(float4*)&Bs[0][brow][bcol] = pb;
    __syncthreads();

    float acc[8][8] = {};

    for (int kt = 0; kt < nk; kt++) {
        const int buf = kt & 1;
        if (kt + 1 < nk) {
            pa = *(const float4*)(aPtr + (kt + 1) * 8);
            const float* bp = bPtr + (long)(kt + 1) * 8 * ldb;
            if (bIn) {
                pb = *(const float4*)bp;
            } else {
                pb.x = (col0 + bcol + 0 < N) ? bp[0] : 0.0f;
                pb.y = (col0 + bcol + 1 < N) ? bp[1] : 0.0f;
                pb.z = (col0 + bcol + 2 < N) ? bp[2] : 0.0f;
                pb.w = 0.0f;
            }
        }
#pragma unroll
        for (int kk = 0; kk < 8; kk++) {
            float4 a0 = *(const float4*)&As[buf][kk][ty * 4];
            float4 a1 = *(const float4*)&As[buf][kk][64 + ty * 4];
            float4 b0 = *(const float4*)&Bs[buf][kk][tx * 4];
            float4 b1 = *(const float4*)&Bs[buf][kk][64 + tx * 4];
            float av[8] = {a0.x, a0.y, a0.z, a0.w, a1.x, a1.y, a1.z, a1.w};
            float bv[8] = {b0.x, b0.y, b0.z, b0.w, b1.x, b1.y, b1.z, b1.w};
#pragma unroll
            for (int u = 0; u < 8; u++)
#pragma unroll
                for (int v = 0; v < 8; v++)
                    acc[u][v] += av[u] * bv[v];
        }
        if (kt + 1 < nk) {
            const int nb = buf ^ 1;
            As[nb][akq + 0][arow] = pa.x; As[nb][akq + 1][arow] = pa.y;
            As[nb][akq + 2][arow] = pa.z; As[nb][akq + 3][arow] = pa.w;
            *(float4*)&Bs[nb][brow][bcol] = pb;
            __syncthreads();
        }
    }

#pragma unroll
    for (int u = 0; u < 8; u++) {
        int r = row0 + ((u < 4) ? ty * 4 + u : 64 + ty * 4 + (u - 4));
        float bz = bias ? bias[r] : 0.0f;
#pragma unroll
        for (int v = 0; v < 8; v++) {
            int c = col0 + ((v < 4) ? tx * 4 + v : 64 + tx * 4 + (v - 4));
            if (c < N) C[(long)r * ldc + c] = acc[u][v] + bz;
        }
    }
}

// ================ HMMA (mma.sync) bf16-split GEMM ==========================
__global__ void __launch_bounds__(256) hmma_gemm_kernel(
    long offAhi, long offAlo, int lda,
    long offBhi, long offBlo, int ldb, long sBz,
    long offC, int ldc, long sCz,
    int kChunk, int batchB, int epiMode,
    long offAsub, long offAobj, const float* __restrict__ brf,
    long offRh, long offRl)
{
    extern __shared__ __nv_bfloat16 smb[];
    constexpr int STR = 40;
    constexpr int TILEE = 128 * STR;

    const int tid = threadIdx.x;
    const int warp = tid >> 5, lane = tid & 31;
    const int z = blockIdx.z;
    const int row0 = blockIdx.y * 128, col0 = blockIdx.x * 128;
    const long kBeg = batchB ? 0 : (long)z * kChunk;
    const int S = kChunk / 32;

    const __nv_bfloat16* Ahi = (const __nv_bfloat16*)(g_buf + offAhi);
    const __nv_bfloat16* Alo = (const __nv_bfloat16*)(g_buf + offAlo);
    const __nv_bfloat16* Bhi = (const __nv_bfloat16*)(g_buf + offBhi) + (batchB ? (long)z * sBz : 0);
    const __nv_bfloat16* Blo = (const __nv_bfloat16*)(g_buf + offBlo) + (batchB ? (long)z * sBz : 0);

    const int wm = (warp >> 2) * 64;
    const int wn = (warp & 3) * 32;

    float acc[4][4][4] = {};

    const uint32_t smem_base = smem_u32(smb);

    auto issue_load = [&](int s, int buf) {
        long koff = kBeg + (long)s * 32;
        uint32_t dstBase = smem_base + (uint32_t)buf * 4 * TILEE * 2;
#pragma unroll
        for (int t = 0; t < 4; t++) {
            const __nv_bfloat16* src = (t == 0) ? Ahi : (t == 1) ? Alo
                                      : (t == 2) ? Bhi : Blo;
            const int base0 = (t < 2) ? row0 : col0;
            const int ld = (t < 2) ? lda : ldb;
#pragma unroll
            for (int i = 0; i < 2; i++) {
                int idx = tid + i * 256;
                int r = idx >> 2;
                int cg = (idx & 3) * 8;
                cp_async16(dstBase + (uint32_t)((t * TILEE + r * STR + cg) * 2),
                           src + (long)(base0 + r) * ld + koff + cg);
            }
        }
        cp_commit();
    };

    issue_load(0, 0);

    for (int s = 0; s < S; s++) {
        if (s + 1 < S) {
            issue_load(s + 1, (s + 1) & 1);
            asm volatile("cp.async.wait_group 1;" ::: "memory");
        } else {
            asm volatile("cp.async.wait_group 0;" ::: "memory");
        }
        __syncthreads();

        const int buf = s & 1;
        const uint32_t tb = smem_base + (uint32_t)buf * 4 * TILEE * 2;
        const uint32_t aHiB = tb;
        const uint32_t aLoB = tb + TILEE * 2;
        const uint32_t bHiB = tb + 2 * TILEE * 2;
        const uint32_t bLoB = tb + 3 * TILEE * 2;
        const int lr = lane & 15;
        const int kofA = (lane >> 4) * 8;
        const int kofB = ((lane & 15) >> 3) * 8;

#pragma unroll
        for (int k16 = 0; k16 < 2; k16++) {
            uint32_t af[4][4], bh[4][2], bl[4][2];
#pragma unroll
            for (int mi = 0; mi < 4; mi++)
                ldsm4(af[mi], aHiB + (uint32_t)(((wm + mi * 16 + lr) * STR)
                                               + k16 * 16 + kofA) * 2);
#pragma unroll
            for (int ni = 0; ni < 4; ni++) {
                uint32_t ro = (uint32_t)(((wn + ni * 8 + (lr & 7)) * STR)
                                         + k16 * 16 + kofB) * 2;
                ldsm2(bh[ni], bHiB + ro);
                ldsm2(bl[ni], bLoB + ro);
            }
#pragma unroll
            for (int mi = 0; mi < 4; mi++)
#pragma unroll
                for (int ni = 0; ni < 4; ni++) {
                    mma16816(acc[mi][ni], af[mi], bh[ni]);   // hh
                    mma16816(acc[mi][ni], af[mi], bl[ni]);   // hl
                }
#pragma unroll
            for (int mi = 0; mi < 4; mi++)
                ldsm4(af[mi], aLoB + (uint32_t)(((wm + mi * 16 + lr) * STR)
                                               + k16 * 16 + kofA) * 2);
#pragma unroll
            for (int mi = 0; mi < 4; mi++)
#pragma unroll
                for (int ni = 0; ni < 4; ni++)
                    mma16816(acc[mi][ni], af[mi], bh[ni]);   // lh
        }
        __syncthreads();
    }

    if (epiMode == 0) {
        float* C = g_buf + offC + (long)z * sCz;
#pragma unroll
        for (int mi = 0; mi < 4; mi++) {
            int r = row0 + wm + mi * 16 + (lane >> 2);
#pragma unroll
            for (int ni = 0; ni < 4; ni++) {
                int cc = col0 + wn + ni * 8 + (lane & 3) * 2;
                *(float2*)&C[(long)r * ldc + cc] = make_float2(acc[mi][ni][0], acc[mi][ni][1]);
                *(float2*)&C[(long)(r + 8) * ldc + cc] = make_float2(acc[mi][ni][2], acc[mi][ni][3]);
            }
        }
    } else {
        using namespace sg;
        const float* A1b = g_buf + offAsub + (long)z * 256 * 784;
        const float* A2b = g_buf + offAobj + (long)z * 256 * 784;
        __nv_bfloat16* rh = (__nv_bfloat16*)(g_buf + offRh) + (long)z * 256 * KFC;
        __nv_bfloat16* rl = (__nv_bfloat16*)(g_buf + offRl) + (long)z * 256 * KFC;
#pragma unroll
        for (int mi = 0; mi < 4; mi++) {
#pragma unroll
            for (int half = 0; half < 2; half++) {
                int o = row0 + wm + mi * 16 + (lane >> 2) + half * 8;
                float bz = brf[o];
#pragma unroll
                for (int ni = 0; ni < 4; ni++) {
#pragma unroll
                    for (int e = 0; e < 2; e++) {
                        int cc = col0 + wn + ni * 8 + (lane & 3) * 2 + e;
                        int pair = cc / 49;
                        int s = cc - pair * 49;
                        int io = (pair >> 4) * 49 + s;
                        int jo = (pair & 15) * 49 + s;
                        float v = acc[mi][ni][half * 2 + e]
                                + A1b[(long)o * 784 + io]
                                + A2b[(long)o * 784 + jo] + bz;
                        v = fmaxf(v, 0.0f);
                        __nv_bfloat16 h, l;
                        split_bf16(v, h, l);
                        long di = (long)pair * KFC + o * 49 + s;
                        rh[di] = h;
                        rl[di] = l;
                    }
                }
            }
        }
    }
}

// ==================== misc data-movement / pooling =========================
__global__ void transpose_kernel(const float* __restrict__ srcExt,
                                 long offSrc, long offDst, int R, int C)
{
    __shared__ float tile[32][33];
    int b = blockIdx.z;
    const float* src = (srcExt ? srcExt : (const float*)g_buf + offSrc) + (long)b * R * C;
    float* dst = g_buf + offDst + (long)b * R * C;
    int c0 = blockIdx.x * 32, r0 = blockIdx.y * 32;
    int tx = threadIdx.x, ty = threadIdx.y;
#pragma unroll
    for (int k = 0; k < 32; k += 8)
        tile[ty + k][tx] = src[(long)(r0 + ty + k) * C + c0 + tx];
    __syncthreads();
#pragma unroll
    for (int k = 0; k < 32; k += 8)
        dst[(long)(c0 + ty + k) * R + r0 + tx] = tile[tx][ty + k];
}

__global__ void __launch_bounds__(256) pool_obj_kernel(const float* __restrict__ boxes)
{
    using namespace sg;
    int b = blockIdx.y, n = blockIdx.x, tid = threadIdx.x;
    const float* bx = boxes + ((long)b * Nn + n) * 4;
    float x1 = bx[0], y1 = bx[1], x2 = bx[2], y2 = bx[3];
    float sx1 = x1 * SCALE, sy1 = y1 * SCALE, sx2 = x2 * SCALE, sy2 = y2 * SCALE;

    __shared__ float wy[7][16], wx[7][24];
    __shared__ int h0[7], h1[7], w0[7], w1[7];
    compute_weights(sx1, sy1, sx2, sy2, wy, wx, h0, h1, w0, w1, tid);

    if (tid < 49) {
        int p = tid / 7, q = tid % 7;
        float ye0 = IMGH * (float)p * (1.0f / 7.0f), ye1 = IMGH * (float)(p + 1) * (1.0f / 7.0f);
        float xe0 = IMGW * (float)q * (1.0f / 7.0f), xe1 = IMGW * (float)(q + 1) * (1.0f / 7.0f);
        float oy = fmaxf(fminf(ye1, y2) - fmaxf(ye0, y1), 0.0f);
        float ox = fmaxf(fminf(xe1, x2) - fmaxf(xe0, x1), 0.0f);
        float ch = IMGH * (1.0f / 7.0f), cw = IMGW * (1.0f / 7.0f);
        g_buf[OF_BIMAP + ((long)b * Nn + n) * PP + tid] = (oy / ch) * (ox / cw);
    }
    __syncthreads();

    float area = (sx2 - sx1) * (sy2 - sy1) * (1.0f / 49.0f);
    float inv = (area > 0.0f) ? 1.0f / fmaxf(area, 1e-9f) : 0.0f;

    int c = tid;
    const float* fb = g_buf + OF_FEATT + (long)b * HW * Cc + c;
    float acc[49];
#pragma unroll
    for (int s = 0; s < 49; s++) acc[s] = 0.0f;
    pool_channel_acc(fb, Cc, wy, wx, h0, h1, w0, w1, acc);

    float* X = g_buf + OF_XOBJ + ((long)b * 512 + c) * 784 + (long)n * 49;
#pragma unroll
    for (int s = 0; s < 49; s++) X[s] = acc[s] * inv;
}

__global__ void __launch_bounds__(256) pool_ctx_kernel()
{
    using namespace sg;
    int b = blockIdx.x, tid = threadIdx.x;
    __shared__ float wy[7][16], wx[7][24];
    __shared__ int h0[7], h1[7], w0[7], w1[7];
    compute_weights(0.0f, 0.0f, 24.0f, 16.0f, wy, wx, h0, h1, w0, w1, tid);
    __syncthreads();

    float inv = 49.0f / (24.0f * 16.0f);
    int c = tid;
    const float* fb = g_buf + OF_CTXF + ((long)b * Cc + c) * HW;
    float acc[49];
#pragma unroll
    for (int s = 0; s < 49; s++) acc[s] = 0.0f;
    pool_channel_acc(fb, 1, wy, wx, h0, h1, w0, w1, acc);
    float* X = g_buf + OF_PCTX + ((long)b * Cc + c) * PP;
#pragma unroll
    for (int s = 0; s < 49; s++) X[s] = acc[s] * inv;
}

__global__ void pack_xobj_kernel()
{
    using namespace sg;
    int b = blockIdx.y;
    int base = blockIdx.x * blockDim.x + threadIdx.x;
    int stride = gridDim.x * blockDim.x;
    for (int idx = base; idx < 256 * 784; idx += stride) {
        int cc = idx / 784, rem = idx - cc * 784;
        int n = rem / 49, s = rem - n * 49;
        float v = g_buf[OF_PCTX + ((long)b * Cc + cc) * PP + s];
        if (cc >= 128) v *= g_buf[OF_BIMAP + ((long)b * Nn + n) * PP + s];
        g_buf[OF_XOBJ + ((long)b * 512 + 256 + cc) * 784 + rem] = v;
    }
}

// pool rel feats over union boxes -> XrelT hi/lo [b][pair*49+s][384] bf16
__global__ void __launch_bounds__(384) pool_rel_kernel(const float* __restrict__ boxes)
{
    using namespace sg;
    extern __shared__ float stage[];
    int b = blockIdx.y, pair = blockIdx.x, tid = threadIdx.x;
    int i = pair >> 4, j = pair & 15;
    const float* bi = boxes + ((long)b * Nn + i) * 4;
    const float* bj = boxes + ((long)b * Nn + j) * 4;
    float ix1 = bi[0], iy1 = bi[1], ix2 = bi[2], iy2 = bi[3];
    float jx1 = bj[0], jy1 = bj[1], jx2 = bj[2], jy2 = bj[3];
    float ux1 = fminf(ix1, jx1), uy1 = fminf(iy1, jy1);
    float ux2 = fmaxf(ix2, jx2), uy2 = fmaxf(iy2, jy2);
    float sx1 = ux1 * SCALE, sy1 = uy1 * SCALE, sx2 = ux2 * SCALE, sy2 = uy2 * SCALE;

    __shared__ float wy[7][16], wx[7][24];
    __shared__ int h0[7], h1[7], w0[7], w1[7];
    __shared__ float subm[49], objm[49];
    compute_weights(sx1, sy1, sx2, sy2, wy, wx, h0, h1, w0, w1, tid);

    if (tid < 49) {
        int p = tid / 7, q = tid - p * 7;
        float ye0 = uy1 + (uy2 - uy1) * (float)p * (1.0f / 7.0f);
        float ye1 = uy1 + (uy2 - uy1) * (float)(p + 1) * (1.0f / 7.0f);
        float xe0 = ux1 + (ux2 - ux1) * (float)q * (1.0f / 7.0f);
        float xe1 = ux1 + (ux2 - ux1) * (float)(q + 1) * (1.0f / 7.0f);
        float ch = fmaxf((uy2 - uy1) * (1.0f / 7.0f), 1e-9f);
        float cw = fmaxf((ux2 - ux1) * (1.0f / 7.0f), 1e-9f);
        float oy = fmaxf(fminf(ye1, iy2) - fmaxf(ye0, iy1), 0.0f);
        float ox = fmaxf(fminf(xe1, ix2) - fmaxf(xe0, ix1), 0.0f);
        subm[tid] = (oy / ch) * (ox / cw);
        oy = fmaxf(fminf(ye1, jy2) - fmaxf(ye0, jy1), 0.0f);
        ox = fmaxf(fminf(xe1, jx2) - fmaxf(xe0, jx1), 0.0f);
        objm[tid] = (oy / ch) * (ox / cw);
    }
    __syncthreads();

    float area = (sx2 - sx1) * (sy2 - sy1) * (1.0f / 49.0f);
    float inv = (area > 0.0f) ? 1.0f / fmaxf(area, 1e-9f) : 0.0f;

    int c = tid;
    const float* fb = g_buf + OF_RELFT + (long)b * HW * C32 + c;
    float acc[49];
#pragma unroll
    for (int s = 0; s < 49; s++) acc[s] = 0.0f;
    pool_channel_acc(fb, C32, wy, wx, h0, h1, w0, w1, acc);

#pragma unroll
    for (int s = 0; s < 49; s++) {
        float mk = (c < 128) ? 1.0f : (c < 256 ? subm[s] : objm[s]);
        stage[c * 49 + s] = acc[s] * inv * mk;
    }
    __syncthreads();

    __nv_bfloat16* xh = (__nv_bfloat16*)(g_buf + OF_XRTH);
    __nv_bfloat16* xl = (__nv_bfloat16*)(g_buf + OF_XRTL);
    long rowBase = ((long)b * KFC + (long)pair * 49) * 384;
    for (int idx = tid; idx < 49 * 384; idx += 384) {
        int s = idx / 384, cc = idx - s * 384;
        __nv_bfloat16 h, l;
        split_bf16(stage[cc * 49 + s], h, l);
        xh[rowBase + (long)s * 384 + cc] = h;
        xl[rowBase + (long)s * 384 + cc] = l;
    }
}

// relu(obj) -> Robj^T hi/lo [128][12544]
__global__ void __launch_bounds__(256) combine_obj_kernel()
{
    using namespace sg;
    int row = blockIdx.x >> 3;            // b*16 + i
    int seg = blockIdx.x & 7;             // KFC segment
    int b = row >> 4, i = row & 15;
    const float* obj = g_buf + OF_OBJ + (long)b * 256 * 784 + (long)i * 49;
    __nv_bfloat16* rh = (__nv_bfloat16*)(g_buf + OF_ROH) + (long)row * KFC;
    __nv_bfloat16* rl = (__nv_bfloat16*)(g_buf + OF_ROL) + (long)row * KFC;
    int beg = seg * 1568, end = beg + 1568;
    for (int idx = beg + threadIdx.x; idx < end; idx += 256) {
        int o = idx / 49, s = idx - o * 49;
        float v = fmaxf(obj[(long)o * 784 + s], 0.0f);
        __nv_bfloat16 h, l;
        split_bf16(v, h, l);
        rh[idx] = h; rl[idx] = l;
    }
}

__global__ void convert_w_kernel(const float* __restrict__ W, int lda, int colOff,
                                 long offHi, long offLo, long total, int Kout)
{
    __nv_bfloat16* ph = (__nv_bfloat16*)(g_buf + offHi);
    __nv_bfloat16* pl = (__nv_bfloat16*)(g_buf + offLo);
    for (long idx = (long)blockIdx.x * blockDim.x + threadIdx.x; idx < total;
         idx += (long)gridDim.x * blockDim.x) {
        long m = idx / Kout;
        int k = (int)(idx - m * Kout);
        float x = W[m * lda + colOff + k];
        __nv_bfloat16 h, l;
        split_bf16(x, h, l);
        ph[idx] = h; pl[idx] = l;
    }
}

__global__ void reduce_split_kernel(long offP, long offO, long MN, int Ncols,
                                    int S, const float* __restrict__ bias)
{
    long idx = (long)blockIdx.x * blockDim.x + threadIdx.x;
    if (idx >= MN) return;
    float s = 0.0f;
    for (int i = 0; i < S; i++) s += g_buf[offP + (long)i * MN + idx];
    int m = (int)(idx / Ncols);
    g_buf[offO + idx] = s + bias[m];
}

__global__ void finalize_kernel(long srcOff, int ncols, float* __restrict__ out)
{
    int col = blockIdx.x, n = threadIdx.x;
    float v = g_buf[srcOff + (long)n * ncols + col];
    float s = v * v;
#pragma unroll
    for (int o = 16; o > 0; o >>= 1) s += __shfl_xor_sync(0xffffffffu, s, o);
    __shared__ float red[8];
    if ((n & 31) == 0) red[n >> 5] = s;
    __syncthreads();
    float tot = red[0] + red[1] + red[2] + red[3] + red[4] + red[5] + red[6] + red[7];
    out[(long)col * 256 + n] = v / sqrtf(tot);
}

// ===========================================================================
extern "C" void kernel_launch(void* const* d_in, const int* in_sizes, int n_in,
                              void* d_out, int out_size)
{
    using namespace sg;
    const float* input = (const float*)d_in[0];
    const float* boxes = (const float*)d_in[1];
    const float* W_ctx = (const float*)d_in[3];
    const float* b_ctx = (const float*)d_in[4];
    const float* W_rel = (const float*)d_in[5];
    const float* b_rel = (const float*)d_in[6];
    const float* W_of  = (const float*)d_in[7];
    const float* b_of  = (const float*)d_in[8];
    const float* W_rf  = (const float*)d_in[9];
    const float* b_rf  = (const float*)d_in[10];
    const float* W_ofc = (const float*)d_in[11];
    const float* b_ofc = (const float*)d_in[12];
    const float* W_rfc = (const float*)d_in[13];
    const float* b_rfc = (const float*)d_in[14];
    float* out = (float*)d_out;

    const long s784  = 256L * 784;
    const int SMEM_HMMA = 2 * 4 * 128 * 40 * 2;   // 81920 bytes

    cudaFuncSetAttribute(hmma_gemm_kernel, cudaFuncAttributeMaxDynamicSharedMemorySize, SMEM_HMMA);
    cudaFuncSetAttribute(pool_rel_kernel, cudaFuncAttributeMaxDynamicSharedMemorySize, 384 * 49 * 4);

    // 0. fused ctx + rel 1x1 convs (fp32)
    conv_dual_kernel<<<dim3(6, 10, 8), 256>>>(input, W_ctx, b_ctx, W_rel, b_rel);
    // 1-2. transposes to [hw][c]
    transpose_kernel<<<dim3(12, 8, 8), dim3(32, 8)>>>(input, 0, OF_FEATT, 256, 384);
    transpose_kernel<<<dim3(12, 12, 8), dim3(32, 8)>>>(nullptr, OF_RELF, OF_RELFT, 384, 384);
    // 3-5. pooling (launch idx 5 = pool_rel -> captured by ncu -s 5)
    pool_ctx_kernel<<<8, 256>>>();
    pool_obj_kernel<<<dim3(16, 8), 256>>>(boxes);
    pool_rel_kernel<<<dim3(256, 8), 384, 384 * 49 * 4>>>(boxes);
    // 6. pack ctx-pooled channels into Xobj
    pack_xobj_kernel<<<dim3(16, 8), 256>>>();
    // 7. pair-GEMM weight conversion
    convert_w_kernel<<<384, 256>>>(W_rf, 896, 512, OF_WPH, OF_WPL, 256L * 384, 384);
    // 8. obj conv (fp32)
    sgemm128_kernel<<<dim3(7, 2, 8), 256>>>(W_of, 0, 512, OF_XOBJ, 784, 512L * 784,
                                            OF_OBJ, 784, s784, 784, 512, 512, 1, b_of,
                                            1, 0, 0);
    // 9. Asub + Aobj in ONE launch
    sgemm128_kernel<<<dim3(7, 4, 8), 256>>>(W_rf, 0, 896, OF_OBJ, 784, s784,
                                            OF_ASUB, 784, s784, 784, 256, 256, 1, nullptr,
                                            2, 256, OF_AOBJ - OF_ASUB);
    // 10. pair GEMM (HMMA, batched) + fused combine/relu/split epilogue -> R^T
    hmma_gemm_kernel<<<dim3(98, 2, 8), 256, SMEM_HMMA>>>(
        OF_WPH, OF_WPL, 384, OF_XRTH, OF_XRTL, 384, (long)KFC * 384,
        0, 0, 0, 384, 1, 1, OF_ASUB, OF_AOBJ, b_rf, OF_RTH, OF_RTL);
    // 11. rel FC weight conversion
    convert_w_kernel<<<4096, 256>>>(W_rfc, KFC, 0, OF_WRH, OF_WRL, 256L * KFC, KFC);
    // 12. rel FC (HMMA, split-K 14) + reduce
    hmma_gemm_kernel<<<dim3(16, 2, SPLK), 256, SMEM_HMMA>>>(
        OF_WRH, OF_WRL, KFC, OF_RTH, OF_RTL, KFC, 0,
        OF_FP, 2048, 256L * 2048, KFC / SPLK, 0, 0, 0, 0, nullptr, 0, 0);
    reduce_split_kernel<<<2048, 256>>>(OF_FP, OF_FREL, 256L * 2048, 2048, SPLK, b_rfc);
    // 13. relu(obj) -> Robj^T bf16 hi/lo
    combine_obj_kernel<<<1024, 256>>>();
    // 14. obj FC weight conversion
    convert_w_kernel<<<4096, 256>>>(W_ofc, KFC, 0, OF_WOH, OF_WOL, 256L * KFC, KFC);
    // 15. obj FC (HMMA, split-K 49) + reduce
    hmma_gemm_kernel<<<dim3(1, 2, SPLKO), 256, SMEM_HMMA>>>(
        OF_WOH, OF_WOL, KFC, OF_ROH, OF_ROL, KFC, 0,
        OF_FPO, 128, 256L * 128, KFC / SPLKO, 0, 0, 0, 0, nullptr, 0, 0);
    reduce_split_kernel<<<128, 256>>>(OF_FPO, OF_FOBJ, 256L * 128, 128, SPLKO, b_ofc);
    // 16-17. l2norm heads
    finalize_kernel<<<128, 256>>>(OF_FOBJ, 128, out);
    finalize_kernel<<<2048, 256>>>(OF_FREL, 2048, out + 32768);
}

// round 9
// speedup vs baseline: 4.7604x; 1.0537x over previous
#include <cuda_runtime.h>
#include <cuda_bf16.h>
#include <math.h>
#include <stdint.h>

namespace sg {
constexpr int Bn = 8, Cc = 256, Nn = 16;
constexpr int HW = 384;
constexpr int C32 = 384;
constexpr float SCALE = 1.0f / 16.0f;
constexpr float IMGW = 384.0f, IMGH = 256.0f;
constexpr int PP = 49;
constexpr int KFC = 12544;            // 256*49
constexpr int SPLK = 14;              // rel FC split-K  (14*896 = 12544)
constexpr int SPLKO = 49;             // obj FC split-K  (49*256 = 12544)

constexpr long SZ_CTXF  = (long)Bn * Cc * HW;
constexpr long SZ_RELF  = (long)Bn * C32 * HW;
constexpr long SZ_FEATT = SZ_CTXF;
constexpr long SZ_RELFT = SZ_RELF;
constexpr long SZ_PCTX4 = (long)Bn * 4 * Cc * PP;   // 4 h-quarter partials
constexpr long SZ_BIMAP = (long)Bn * Nn * PP;
constexpr long SZ_XOBJ  = (long)Bn * 512 * 784;
constexpr long SZ_OBJ   = (long)Bn * 256 * 784;
constexpr long SZ_ASUB  = SZ_OBJ;
constexpr long SZ_AOBJ  = SZ_OBJ;
constexpr long SZ_FREL  = 256L * 2048;
constexpr long SZ_FOBJ  = 256L * 128;
constexpr long SZ_FP    = (long)SPLK * 256 * 2048;
constexpr long SZ_FPO   = (long)SPLKO * 256 * 128;
constexpr long FU_WP  = 256L * 384 / 2;
constexpr long FU_XRT = (long)Bn * KFC * 384 / 2;
constexpr long FU_WR  = 256L * KFC / 2;
constexpr long FU_RT  = 2048L * KFC / 2;
constexpr long FU_WO  = FU_WR;
constexpr long FU_RO  = 128L * KFC / 2;

constexpr long OF_CTXF  = 0;
constexpr long OF_RELF  = OF_CTXF  + SZ_CTXF;
constexpr long OF_FEATT = OF_RELF  + SZ_RELF;
constexpr long OF_RELFT = OF_FEATT + SZ_FEATT;
constexpr long OF_PCTX4 = OF_RELFT + SZ_RELFT;
constexpr long OF_BIMAP = OF_PCTX4 + SZ_PCTX4;
constexpr long OF_XOBJ  = OF_BIMAP + SZ_BIMAP;
constexpr long OF_OBJ   = OF_XOBJ  + SZ_XOBJ;
constexpr long OF_ASUB  = OF_OBJ   + SZ_OBJ;
constexpr long OF_AOBJ  = OF_ASUB  + SZ_ASUB;
constexpr long OF_FREL  = OF_AOBJ  + SZ_AOBJ;
constexpr long OF_FOBJ  = OF_FREL  + SZ_FREL;
constexpr long OF_FP    = OF_FOBJ  + SZ_FOBJ;
constexpr long OF_FPO   = OF_FP    + SZ_FP;
constexpr long OF_WPH   = OF_FPO   + SZ_FPO;
constexpr long OF_WPL   = OF_WPH   + FU_WP;
constexpr long OF_XRTH  = OF_WPL   + FU_WP;
constexpr long OF_XRTL  = OF_XRTH  + FU_XRT;
constexpr long OF_WRH   = OF_XRTL  + FU_XRT;
constexpr long OF_WRL   = OF_WRH   + FU_WR;
constexpr long OF_RTH   = OF_WRL   + FU_WR;
constexpr long OF_RTL   = OF_RTH   + FU_RT;
constexpr long OF_WOH   = OF_RTL   + FU_RT;
constexpr long OF_WOL   = OF_WOH   + FU_WO;
constexpr long OF_ROH   = OF_WOL   + FU_WO;
constexpr long OF_ROL   = OF_ROH   + FU_RO;
constexpr long TOTAL    = OF_ROL   + FU_RO;
}  // namespace sg

__device__ float g_buf[sg::TOTAL];

// ========================= low-level helpers ===============================
__device__ __forceinline__ uint32_t smem_u32(const void* p) {
    uint32_t a;
    asm("{ .reg .u64 t; cvta.to.shared.u64 t, %1; cvt.u32.u64 %0, t; }" : "=r"(a) : "l"(p));
    return a;
}
__device__ __forceinline__ void cp_async16(uint32_t dst, const void* src) {
    asm volatile("cp.async.cg.shared.global [%0], [%1], 16;" :: "r"(dst), "l"(src));
}
__device__ __forceinline__ void cp_commit() {
    asm volatile("cp.async.commit_group;" ::: "memory");
}
__device__ __forceinline__ void ldsm4(uint32_t* a, uint32_t addr) {
    asm volatile("ldmatrix.sync.aligned.m8n8.x4.shared.b16 {%0,%1,%2,%3}, [%4];"
        : "=r"(a[0]), "=r"(a[1]), "=r"(a[2]), "=r"(a[3]) : "r"(addr));
}
__device__ __forceinline__ void ldsm2(uint32_t* b, uint32_t addr) {
    asm volatile("ldmatrix.sync.aligned.m8n8.x2.shared.b16 {%0,%1}, [%2];"
        : "=r"(b[0]), "=r"(b[1]) : "r"(addr));
}
__device__ __forceinline__ void mma16816(float* d, const uint32_t* a, const uint32_t* b) {
    asm volatile("mma.sync.aligned.m16n8k16.row.col.f32.bf16.bf16.f32 "
        "{%0,%1,%2,%3}, {%4,%5,%6,%7}, {%8,%9}, {%0,%1,%2,%3};"
        : "+f"(d[0]), "+f"(d[1]), "+f"(d[2]), "+f"(d[3])
        : "r"(a[0]), "r"(a[1]), "r"(a[2]), "r"(a[3]), "r"(b[0]), "r"(b[1]));
}
__device__ __forceinline__ void split_bf16(float x, __nv_bfloat16& h, __nv_bfloat16& l) {
    h = __float2bfloat16(x);
    l = __float2bfloat16(x - __bfloat162float(h));
}

// ========================= PrRoI pooling helpers ===========================
static __device__ __forceinline__ float hatG(float t) {
    float tl = fminf(fmaxf(t, -1.0f), 0.0f);
    float tr = fminf(fmaxf(t, 0.0f), 1.0f);
    return 0.5f * (tl + 1.0f) * (tl + 1.0f) + 0.5f - 0.5f * (1.0f - tr) * (1.0f - tr);
}

static __device__ __forceinline__ void compute_weights(
    float x1, float y1, float x2, float y2,
    float (*wy)[16], float (*wx)[24],
    int* h0, int* h1, int* w0, int* w1, int tid)
{
    if (tid < 112) {
        int p = tid / 16, i = tid % 16;
        float e0 = y1 + (y2 - y1) * (float)p * (1.0f / 7.0f);
        float e1 = y1 + (y2 - y1) * (float)(p + 1) * (1.0f / 7.0f);
        wy[p][i] = hatG(e1 - (float)i) - hatG(e0 - (float)i);
    }
    if (tid < 168) {
        int q = tid / 24, i = tid % 24;
        float e0 = x1 + (x2 - x1) * (float)q * (1.0f / 7.0f);
        float e1 = x1 + (x2 - x1) * (float)(q + 1) * (1.0f / 7.0f);
        wx[q][i] = hatG(e1 - (float)i) - hatG(e0 - (float)i);
    }
    if (tid < 7) {
        float e0 = y1 + (y2 - y1) * (float)tid * (1.0f / 7.0f);
        float e1 = y1 + (y2 - y1) * (float)(tid + 1) * (1.0f / 7.0f);
        h0[tid] = max(0, (int)ceilf(e0) - 1);
        h1[tid] = min(16, (int)floorf(e1) + 2);
    }
    if (tid >= 32 && tid < 39) {
        int q = tid - 32;
        float e0 = x1 + (x2 - x1) * (float)q * (1.0f / 7.0f);
        float e1 = x1 + (x2 - x1) * (float)(q + 1) * (1.0f / 7.0f);
        w0[q] = max(0, (int)ceilf(e0) - 1);
        w1[q] = min(24, (int)floorf(e1) + 2);
    }
}

// Separable pooling over h in [hlo, hhi).
static __device__ __forceinline__ void pool_channel_acc_range(
    const float* __restrict__ fb, int ps,
    const float (*wy)[16], const float (*wx)[24],
    const int* w0, const int* w1,
    int hlo, int hhi, float* acc)
{
    for (int h = hlo; h < hhi; h++) {
        const float* row = fb + (long)h * 24 * ps;
        float colsum[7];
#pragma unroll
        for (int q = 0; q < 7; q++) {
            float a = 0.0f;
            for (int w = w0[q]; w < w1[q]; w++)
                a += wx[q][w] * row[(long)w * ps];
            colsum[q] = a;
        }
#pragma unroll
        for (int p = 0; p < 7; p++) {
            float wv = wy[p][h];
#pragma unroll
            for (int q = 0; q < 7; q++)
                acc[p * 7 + q] += wv * colsum[q];
        }
    }
}

// ===================== dual 1x1 conv (ctx + rel in one launch) =============
__global__ void __launch_bounds__(256) conv_dual_kernel(
    const float* __restrict__ input,
    const float* __restrict__ Wctx, const float* __restrict__ bctx,
    const float* __restrict__ Wrel, const float* __restrict__ brel)
{
    using namespace sg;
    __shared__ float As[16][65];
    __shared__ float Bs[16][68];

    const int b = blockIdx.z;
    const int tid = threadIdx.x;
    const int row0 = blockIdx.y * 64;
    const int col0 = blockIdx.x * 64;
    const bool isCtx = row0 < 256;
    const float* A = isCtx ? (Wctx + (long)row0 * 256)
                           : (Wrel + (long)(row0 - 256) * 256);
    const float* bias = isCtx ? bctx : brel;
    const int biasBase = isCtx ? row0 : row0 - 256;
    const float* Bm = input + (long)b * Cc * HW;
    float* Cm = isCtx ? (g_buf + OF_CTXF + (long)b * Cc * HW + (long)row0 * 384)
                      : (g_buf + OF_RELF + (long)b * C32 * HW + (long)(row0 - 256) * 384);

    const int ty = tid >> 4, tx = tid & 15;
    const int ty4 = ty * 4, tx4 = tx * 4;
    const int ar = tid >> 2, ak = (tid & 3) << 2;
    const int br = tid >> 4, bc = (tid & 15) << 2;

    float acc[4][4] = {};

    for (int k0 = 0; k0 < 256; k0 += 16) {
        float4 av = *(const float4*)(A + (long)ar * 256 + k0 + ak);
        As[ak + 0][ar] = av.x; As[ak + 1][ar] = av.y;
        As[ak + 2][ar] = av.z; As[ak + 3][ar] = av.w;
        float4 bv = *(const float4*)(Bm + (long)(k0 + br) * 384 + col0 + bc);
        *(float4*)&Bs[br][bc] = bv;
        __syncthreads();

#pragma unroll
        for (int k = 0; k < 16; k++) {
            float a0 = As[k][ty4 + 0], a1 = As[k][ty4 + 1];
            float a2 = As[k][ty4 + 2], a3 = As[k][ty4 + 3];
            float4 b4 = *(const float4*)&Bs[k][tx4];
            acc[0][0] += a0 * b4.x; acc[0][1] += a0 * b4.y; acc[0][2] += a0 * b4.z; acc[0][3] += a0 * b4.w;
            acc[1][0] += a1 * b4.x; acc[1][1] += a1 * b4.y; acc[1][2] += a1 * b4.z; acc[1][3] += a1 * b4.w;
            acc[2][0] += a2 * b4.x; acc[2][1] += a2 * b4.y; acc[2][2] += a2 * b4.z; acc[2][3] += a2 * b4.w;
            acc[3][0] += a3 * b4.x; acc[3][1] += a3 * b4.y; acc[3][2] += a3 * b4.z; acc[3][3] += a3 * b4.w;
        }
        __syncthreads();
    }

#pragma unroll
    for (int u = 0; u < 4; u++) {
        float bz = bias[biasBase + ty4 + u];
#pragma unroll
        for (int v = 0; v < 4; v++)
            Cm[(long)(ty4 + u) * 384 + col0 + tx4 + v] = acc[u][v] + bz;
    }
}

// fp32 128x128 GEMM, optional multi-term via grid.y folding.
__global__ void __launch_bounds__(256) sgemm128_kernel(
    const float* __restrict__ Aex, long offA, int lda,
    long offB, int ldb, long sBb,
    long offC, int ldc, long sCb,
    int N, int K, int kChunk, int splitK,
    const float* __restrict__ bias,
    int nTerm, long dAoff, long dCoff)
{
    __shared__ float As[2][8][132];
    __shared__ float Bs[2][8][132];

    const int z = blockIdx.z;
    const int b = z / splitK;
    const int ks = z - b * splitK;
    const int kBeg = ks * kChunk;
    const int kEnd = min(K, kBeg + kChunk);
    const int nk = (kEnd - kBeg) >> 3;

    const int rowTiles = gridDim.y / nTerm;
    const int term = blockIdx.y / rowTiles;
    const int row0 = (blockIdx.y - term * rowTiles) * 128;
    const int col0 = blockIdx.x * 128;

    const float* A = Aex + offA + (long)term * dAoff;
    const float* B = g_buf + offB + (long)b * sBb;
    float* C = g_buf + offC + (long)term * dCoff + (long)z * sCb;

    const int t = threadIdx.x;
    const int arow = t >> 1, akq = (t & 1) << 2;
    const int brow = t >> 5, bcol = (t & 31) << 2;
    const int tx = t & 15, ty = t >> 4;

    const float* aPtr = A + (long)(row0 + arow) * lda + kBeg + akq;
    const float* bPtr = B + (long)(kBeg + brow) * ldb + col0 + bcol;
    const bool bIn = (col0 + bcol + 3) < N;

    float4 pa = *(const float4*)aPtr;
    float4 pb;
    if (bIn) {
        pb = *(const float4*)bPtr;
    } else {
        pb.x = (col0 + bcol + 0 < N) ? bPtr[0] : 0.0f;
        pb.y = (col0 + bcol + 1 < N) ? bPtr[1] : 0.0f;
        pb.z = (col0 + bcol + 2 < N) ? bPtr[2] : 0.0f;
        pb.w = 0.0f;
    }
    As[0][akq + 0][arow] = pa.x; As[0][akq + 1][arow] = pa.y;
    As[0][akq + 2][arow] = pa.z; As[0][akq + 3][arow] = pa.w;
    *(float4*)&Bs[0][brow][bcol] = pb;
    __syncthreads();

    float acc[8][8] = {};

    for (int kt = 0; kt < nk; kt++) {
        const int buf = kt & 1;
        if (kt + 1 < nk) {
            pa = *(const float4*)(aPtr + (kt + 1) * 8);
            const float* bp = bPtr + (long)(kt + 1) * 8 * ldb;
            if (bIn) {
                pb = *(const float4*)bp;
            } else {
                pb.x = (col0 + bcol + 0 < N) ? bp[0] : 0.0f;
                pb.y = (col0 + bcol + 1 < N) ? bp[1] : 0.0f;
                pb.z = (col0 + bcol + 2 < N) ? bp[2] : 0.0f;
                pb.w = 0.0f;
            }
        }
#pragma unroll
        for (int kk = 0; kk < 8; kk++) {
            float4 a0 = *(const float4*)&As[buf][kk][ty * 4];
            float4 a1 = *(const float4*)&As[buf][kk][64 + ty * 4];
            float4 b0 = *(const float4*)&Bs[buf][kk][tx * 4];
            float4 b1 = *(const float4*)&Bs[buf][kk][64 + tx * 4];
            float av[8] = {a0.x, a0.y, a0.z, a0.w, a1.x, a1.y, a1.z, a1.w};
            float bv[8] = {b0.x, b0.y, b0.z, b0.w, b1.x, b1.y, b1.z, b1.w};
#pragma unroll
            for (int u = 0; u < 8; u++)
#pragma unroll
                for (int v = 0; v < 8; v++)
                    acc[u][v] += av[u] * bv[v];
        }
        if (kt + 1 < nk) {
            const int nb = buf ^ 1;
            As[nb][akq + 0][arow] = pa.x; As[nb][akq + 1][arow] = pa.y;
            As[nb][akq + 2][arow] = pa.z; As[nb][akq + 3][arow] = pa.w;
            *(float4*)&Bs[nb][brow][bcol] = pb;
            __syncthreads();
        }
    }

#pragma unroll
    for (int u = 0; u < 8; u++) {
        int r = row0 + ((u < 4) ? ty * 4 + u : 64 + ty * 4 + (u - 4));
        float bz = bias ? bias[r] : 0.0f;
#pragma unroll
        for (int v = 0; v < 8; v++) {
            int c = col0 + ((v < 4) ? tx * 4 + v : 64 + tx * 4 + (v - 4));
            if (c < N) C[(long)r * ldc + c] = acc[u][v] + bz;
        }
    }
}

// ================ HMMA (mma.sync) bf16-split GEMM ==========================
__global__ void __launch_bounds__(256) hmma_gemm_kernel(
    long offAhi, long offAlo, int lda,
    long offBhi, long offBlo, int ldb, long sBz,
    long offC, int ldc, long sCz,
    int kChunk, int batchB, int epiMode,
    long offAsub, long offAobj, const float* __restrict__ brf,
    long offRh, long offRl)
{
    extern __shared__ __nv_bfloat16 smb[];
    constexpr int STR = 40;
    constexpr int TILEE = 128 * STR;

    const int tid = threadIdx.x;
    const int warp = tid >> 5, lane = tid & 31;
    const int z = blockIdx.z;
    const int row0 = blockIdx.y * 128, col0 = blockIdx.x * 128;
    const long kBeg = batchB ? 0 : (long)z * kChunk;
    const int S = kChunk / 32;

    const __nv_bfloat16* Ahi = (const __nv_bfloat16*)(g_buf + offAhi);
    const __nv_bfloat16* Alo = (const __nv_bfloat16*)(g_buf + offAlo);
    const __nv_bfloat16* Bhi = (const __nv_bfloat16*)(g_buf + offBhi) + (batchB ? (long)z * sBz : 0);
    const __nv_bfloat16* Blo = (const __nv_bfloat16*)(g_buf + offBlo) + (batchB ? (long)z * sBz : 0);

    const int wm = (warp >> 2) * 64;
    const int wn = (warp & 3) * 32;

    float acc[4][4][4] = {};

    const uint32_t smem_base = smem_u32(smb);

    auto issue_load = [&](int s, int buf) {
        long koff = kBeg + (long)s * 32;
        uint32_t dstBase = smem_base + (uint32_t)buf * 4 * TILEE * 2;
#pragma unroll
        for (int t = 0; t < 4; t++) {
            const __nv_bfloat16* src = (t == 0) ? Ahi : (t == 1) ? Alo
                                      : (t == 2) ? Bhi : Blo;
            const int base0 = (t < 2) ? row0 : col0;
            const int ld = (t < 2) ? lda : ldb;
#pragma unroll
            for (int i = 0; i < 2; i++) {
                int idx = tid + i * 256;
                int r = idx >> 2;
                int cg = (idx & 3) * 8;
                cp_async16(dstBase + (uint32_t)((t * TILEE + r * STR + cg) * 2),
                           src + (long)(base0 + r) * ld + koff + cg);
            }
        }
        cp_commit();
    };

    issue_load(0, 0);

    for (int s = 0; s < S; s++) {
        if (s + 1 < S) {
            issue_load(s + 1, (s + 1) & 1);
            asm volatile("cp.async.wait_group 1;" ::: "memory");
        } else {
            asm volatile("cp.async.wait_group 0;" ::: "memory");
        }
        __syncthreads();

        const int buf = s & 1;
        const uint32_t tb = smem_base + (uint32_t)buf * 4 * TILEE * 2;
        const uint32_t aHiB = tb;
        const uint32_t aLoB = tb + TILEE * 2;
        const uint32_t bHiB = tb + 2 * TILEE * 2;
        const uint32_t bLoB = tb + 3 * TILEE * 2;
        const int lr = lane & 15;
        const int kofA = (lane >> 4) * 8;
        const int kofB = ((lane & 15) >> 3) * 8;

#pragma unroll
        for (int k16 = 0; k16 < 2; k16++) {
            uint32_t af[4][4], bh[4][2], bl[4][2];
#pragma unroll
            for (int mi = 0; mi < 4; mi++)
                ldsm4(af[mi], aHiB + (uint32_t)(((wm + mi * 16 + lr) * STR)
                                               + k16 * 16 + kofA) * 2);
#pragma unroll
            for (int ni = 0; ni < 4; ni++) {
                uint32_t ro = (uint32_t)(((wn + ni * 8 + (lr & 7)) * STR)
                                         + k16 * 16 + kofB) * 2;
                ldsm2(bh[ni], bHiB + ro);
                ldsm2(bl[ni], bLoB + ro);
            }
#pragma unroll
            for (int mi = 0; mi < 4; mi++)
#pragma unroll
                for (int ni = 0; ni < 4; ni++) {
                    mma16816(acc[mi][ni], af[mi], bh[ni]);   // hh
                    mma16816(acc[mi][ni], af[mi], bl[ni]);   // hl
                }
#pragma unroll
            for (int mi = 0; mi < 4; mi++)
                ldsm4(af[mi], aLoB + (uint32_t)(((wm + mi * 16 + lr) * STR)
                                               + k16 * 16 + kofA) * 2);
#pragma unroll
            for (int mi = 0; mi < 4; mi++)
#pragma unroll
                for (int ni = 0; ni < 4; ni++)
                    mma16816(acc[mi][ni], af[mi], bh[ni]);   // lh
        }
        __syncthreads();
    }

    if (epiMode == 0) {
        float* C = g_buf + offC + (long)z * sCz;
#pragma unroll
        for (int mi = 0; mi < 4; mi++) {
            int r = row0 + wm + mi * 16 + (lane >> 2);
#pragma unroll
            for (int ni = 0; ni < 4; ni++) {
                int cc = col0 + wn + ni * 8 + (lane & 3) * 2;
                *(float2*)&C[(long)r * ldc + cc] = make_float2(acc[mi][ni][0], acc[mi][ni][1]);
                *(float2*)&C[(long)(r + 8) * ldc + cc] = make_float2(acc[mi][ni][2], acc[mi][ni][3]);
            }
        }
    } else {
        using namespace sg;
        const float* A1b = g_buf + offAsub + (long)z * 256 * 784;
        const float* A2b = g_buf + offAobj + (long)z * 256 * 784;
        __nv_bfloat16* rh = (__nv_bfloat16*)(g_buf + offRh) + (long)z * 256 * KFC;
        __nv_bfloat16* rl = (__nv_bfloat16*)(g_buf + offRl) + (long)z * 256 * KFC;
#pragma unroll
        for (int mi = 0; mi < 4; mi++) {
#pragma unroll
            for (int half = 0; half < 2; half++) {
                int o = row0 + wm + mi * 16 + (lane >> 2) + half * 8;
                float bz = brf[o];
#pragma unroll
                for (int ni = 0; ni < 4; ni++) {
#pragma unroll
                    for (int e = 0; e < 2; e++) {
                        int cc = col0 + wn + ni * 8 + (lane & 3) * 2 + e;
                        int pair = cc / 49;
                        int s = cc - pair * 49;
                        int io = (pair >> 4) * 49 + s;
                        int jo = (pair & 15) * 49 + s;
                        float v = acc[mi][ni][half * 2 + e]
                                + A1b[(long)o * 784 + io]
                                + A2b[(long)o * 784 + jo] + bz;
                        v = fmaxf(v, 0.0f);
                        __nv_bfloat16 h, l;
                        split_bf16(v, h, l);
                        long di = (long)pair * KFC + o * 49 + s;
                        rh[di] = h;
                        rl[di] = l;
                    }
                }
            }
        }
    }
}

// ==================== misc data-movement / pooling =========================
// Fused transpose: grid.y < 8 -> feat [256][384], else relf [384][384].
__global__ void transpose_dual_kernel(const float* __restrict__ input)
{
    using namespace sg;
    __shared__ float tile[32][33];
    int b = blockIdx.z;
    const float* src;
    float* dst;
    int R, r0;
    if (blockIdx.y < 8) {
        R = 256; r0 = blockIdx.y * 32;
        src = input + (long)b * 256 * 384;
        dst = g_buf + OF_FEATT + (long)b * 256 * 384;
    } else {
        R = 384; r0 = (blockIdx.y - 8) * 32;
        src = g_buf + OF_RELF + (long)b * 384 * 384;
        dst = g_buf + OF_RELFT + (long)b * 384 * 384;
    }
    int c0 = blockIdx.x * 32;
    int tx = threadIdx.x, ty = threadIdx.y;
#pragma unroll
    for (int k = 0; k < 32; k += 8)
        tile[ty + k][tx] = src[(long)(r0 + ty + k) * 384 + c0 + tx];
    __syncthreads();
#pragma unroll
    for (int k = 0; k < 32; k += 8)
        dst[(long)(c0 + ty + k) * R + r0 + tx] = tile[tx][ty + k];
}

__global__ void __launch_bounds__(256) pool_obj_kernel(const float* __restrict__ boxes)
{
    using namespace sg;
    int b = blockIdx.y, n = blockIdx.x, tid = threadIdx.x;
    const float* bx = boxes + ((long)b * Nn + n) * 4;
    float x1 = bx[0], y1 = bx[1], x2 = bx[2], y2 = bx[3];
    float sx1 = x1 * SCALE, sy1 = y1 * SCALE, sx2 = x2 * SCALE, sy2 = y2 * SCALE;

    __shared__ float wy[7][16], wx[7][24];
    __shared__ int h0[7], h1[7], w0[7], w1[7];
    compute_weights(sx1, sy1, sx2, sy2, wy, wx, h0, h1, w0, w1, tid);

    if (tid < 49) {
        int p = tid / 7, q = tid % 7;
        float ye0 = IMGH * (float)p * (1.0f / 7.0f), ye1 = IMGH * (float)(p + 1) * (1.0f / 7.0f);
        float xe0 = IMGW * (float)q * (1.0f / 7.0f), xe1 = IMGW * (float)(q + 1) * (1.0f / 7.0f);
        float oy = fmaxf(fminf(ye1, y2) - fmaxf(ye0, y1), 0.0f);
        float ox = fmaxf(fminf(xe1, x2) - fmaxf(xe0, x1), 0.0f);
        float ch = IMGH * (1.0f / 7.0f), cw = IMGW * (1.0f / 7.0f);
        g_buf[OF_BIMAP + ((long)b * Nn + n) * PP + tid] = (oy / ch) * (ox / cw);
    }
    __syncthreads();

    float area = (sx2 - sx1) * (sy2 - sy1) * (1.0f / 49.0f);
    float inv = (area > 0.0f) ? 1.0f / fmaxf(area, 1e-9f) : 0.0f;

    int c = tid;
    const float* fb = g_buf + OF_FEATT + (long)b * HW * Cc + c;
    float acc[49];
#pragma unroll
    for (int s = 0; s < 49; s++) acc[s] = 0.0f;
    pool_channel_acc_range(fb, Cc, wy, wx, w0, w1, h0[0], h1[6], acc);

    float* X = g_buf + OF_XOBJ + ((long)b * 512 + c) * 784 + (long)n * 49;
#pragma unroll
    for (int s = 0; s < 49; s++) X[s] = acc[s] * inv;
}

// ctx pooling, 4-way h-split: grid(4 hq, 8 b), block 256 (c = tid).
__global__ void __launch_bounds__(256) pool_ctx_kernel()
{
    using namespace sg;
    int hq = blockIdx.x, b = blockIdx.y, tid = threadIdx.x;
    __shared__ float wy[7][16], wx[7][24];
    __shared__ int h0[7], h1[7], w0[7], w1[7];
    compute_weights(0.0f, 0.0f, 24.0f, 16.0f, wy, wx, h0, h1, w0, w1, tid);
    __syncthreads();

    float inv = 49.0f / (24.0f * 16.0f);
    int c = tid;
    const float* fb = g_buf + OF_CTXF + ((long)b * Cc + c) * HW;
    float acc[49];
#pragma unroll
    for (int s = 0; s < 49; s++) acc[s] = 0.0f;
    pool_channel_acc_range(fb, 1, wy, wx, w0, w1, hq * 4, hq * 4 + 4, acc);
    float* X = g_buf + OF_PCTX4 + (((long)b * 4 + hq) * Cc + c) * PP;
#pragma unroll
    for (int s = 0; s < 49; s++) X[s] = acc[s] * inv;
}

__global__ void pack_xobj_kernel()
{
    using namespace sg;
    int b = blockIdx.y;
    int base = blockIdx.x * blockDim.x + threadIdx.x;
    int stride = gridDim.x * blockDim.x;
    for (int idx = base; idx < 256 * 784; idx += stride) {
        int cc = idx / 784, rem = idx - cc * 784;
        int n = rem / 49, s = rem - n * 49;
        long p0 = OF_PCTX4 + ((long)b * 4 * Cc + cc) * PP + s;
        float v = g_buf[p0] + g_buf[p0 + (long)Cc * PP]
                + g_buf[p0 + 2L * Cc * PP] + g_buf[p0 + 3L * Cc * PP];
        if (cc >= 128) v *= g_buf[OF_BIMAP + ((long)b * Nn + n) * PP + s];
        g_buf[OF_XOBJ + ((long)b * 512 + 256 + cc) * 784 + rem] = v;
    }
}

// pool rel feats over union boxes -> XrelT hi/lo [b][pair*49+s][384] bf16
__global__ void __launch_bounds__(384) pool_rel_kernel(const float* __restrict__ boxes)
{
    using namespace sg;
    extern __shared__ float stage[];
    int b = blockIdx.y, pair = blockIdx.x, tid = threadIdx.x;
    int i = pair >> 4, j = pair & 15;
    const float* bi = boxes + ((long)b * Nn + i) * 4;
    const float* bj = boxes + ((long)b * Nn + j) * 4;
    float ix1 = bi[0], iy1 = bi[1], ix2 = bi[2], iy2 = bi[3];
    float jx1 = bj[0], jy1 = bj[1], jx2 = bj[2], jy2 = bj[3];
    float ux1 = fminf(ix1, jx1), uy1 = fminf(iy1, jy1);
    float ux2 = fmaxf(ix2, jx2), uy2 = fmaxf(iy2, jy2);
    float sx1 = ux1 * SCALE, sy1 = uy1 * SCALE, sx2 = ux2 * SCALE, sy2 = uy2 * SCALE;

    __shared__ float wy[7][16], wx[7][24];
    __shared__ int h0[7], h1[7], w0[7], w1[7];
    __shared__ float subm[49], objm[49];
    compute_weights(sx1, sy1, sx2, sy2, wy, wx, h0, h1, w0, w1, tid);

    if (tid < 49) {
        int p = tid / 7, q = tid - p * 7;
        float ye0 = uy1 + (uy2 - uy1) * (float)p * (1.0f / 7.0f);
        float ye1 = uy1 + (uy2 - uy1) * (float)(p + 1) * (1.0f / 7.0f);
        float xe0 = ux1 + (ux2 - ux1) * (float)q * (1.0f / 7.0f);
        float xe1 = ux1 + (ux2 - ux1) * (float)(q + 1) * (1.0f / 7.0f);
        float ch = fmaxf((uy2 - uy1) * (1.0f / 7.0f), 1e-9f);
        float cw = fmaxf((ux2 - ux1) * (1.0f / 7.0f), 1e-9f);
        float oy = fmaxf(fminf(ye1, iy2) - fmaxf(ye0, iy1), 0.0f);
        float ox = fmaxf(fminf(xe1, ix2) - fmaxf(xe0, ix1), 0.0f);
        subm[tid] = (oy / ch) * (ox / cw);
        oy = fmaxf(fminf(ye1, jy2) - fmaxf(ye0, jy1), 0.0f);
        ox = fmaxf(fminf(xe1, jx2) - fmaxf(xe0, jx1), 0.0f);
        objm[tid] = (oy / ch) * (ox / cw);
    }
    __syncthreads();

    float area = (sx2 - sx1) * (sy2 - sy1) * (1.0f / 49.0f);
    float inv = (area > 0.0f) ? 1.0f / fmaxf(area, 1e-9f) : 0.0f;

    int c = tid;
    const float* fb = g_buf + OF_RELFT + (long)b * HW * C32 + c;
    float acc[49];
#pragma unroll
    for (int s = 0; s < 49; s++) acc[s] = 0.0f;
    pool_channel_acc_range(fb, C32, wy, wx, w0, w1, h0[0], h1[6], acc);

#pragma unroll
    for (int s = 0; s < 49; s++) {
        float mk = (c < 128) ? 1.0f : (c < 256 ? subm[s] : objm[s]);
        stage[c * 49 + s] = acc[s] * inv * mk;
    }
    __syncthreads();

    __nv_bfloat16* xh = (__nv_bfloat16*)(g_buf + OF_XRTH);
    __nv_bfloat16* xl = (__nv_bfloat16*)(g_buf + OF_XRTL);
    long rowBase = ((long)b * KFC + (long)pair * 49) * 384;
    for (int idx = tid; idx < 49 * 384; idx += 384) {
        int s = idx / 384, cc = idx - s * 384;
        __nv_bfloat16 h, l;
        split_bf16(stage[cc * 49 + s], h, l);
        xh[rowBase + (long)s * 384 + cc] = h;
        xl[rowBase + (long)s * 384 + cc] = l;
    }
}

// relu(obj) -> Robj^T hi/lo [128][12544]
__global__ void __launch_bounds__(256) combine_obj_kernel()
{
    using namespace sg;
    int row = blockIdx.x >> 3;
    int seg = blockIdx.x & 7;
    int b = row >> 4, i = row & 15;
    const float* obj = g_buf + OF_OBJ + (long)b * 256 * 784 + (long)i * 49;
    __nv_bfloat16* rh = (__nv_bfloat16*)(g_buf + OF_ROH) + (long)row * KFC;
    __nv_bfloat16* rl = (__nv_bfloat16*)(g_buf + OF_ROL) + (long)row * KFC;
    int beg = seg * 1568, end = beg + 1568;
    for (int idx = beg + threadIdx.x; idx < end; idx += 256) {
        int o = idx / 49, s = idx - o * 49;
        float v = fmaxf(obj[(long)o * 784 + s], 0.0f);
        __nv_bfloat16 h, l;
        split_bf16(v, h, l);
        rh[idx] = h; rl[idx] = l;
    }
}

__global__ void convert_w_kernel(const float* __restrict__ W, int lda, int colOff,
                                 long offHi, long offLo, long total, int Kout)
{
    __nv_bfloat16* ph = (__nv_bfloat16*)(g_buf + offHi);
    __nv_bfloat16* pl = (__nv_bfloat16*)(g_buf + offLo);
    for (long idx = (long)blockIdx.x * blockDim.x + threadIdx.x; idx < total;
         idx += (long)gridDim.x * blockDim.x) {
        long m = idx / Kout;
        int k = (int)(idx - m * Kout);
        float x = W[m * lda + colOff + k];
        __nv_bfloat16 h, l;
        split_bf16(x, h, l);
        ph[idx] = h; pl[idx] = l;
    }
}

__global__ void reduce_split_kernel(long offP, long offO, long MN, int Ncols,
                                    int S, const float* __restrict__ bias)
{
    long idx = (long)blockIdx.x * blockDim.x + threadIdx.x;
    if (idx >= MN) return;
    float s = 0.0f;
    for (int i = 0; i < S; i++) s += g_buf[offP + (long)i * MN + idx];
    int m = (int)(idx / Ncols);
    g_buf[offO + idx] = s + bias[m];
}

__global__ void finalize_kernel(long srcOff, int ncols, float* __restrict__ out)
{
    int col = blockIdx.x, n = threadIdx.x;
    float v = g_buf[srcOff + (long)n * ncols + col];
    float s = v * v;
#pragma unroll
    for (int o = 16; o > 0; o >>= 1) s += __shfl_xor_sync(0xffffffffu, s, o);
    __shared__ float red[8];
    if ((n & 31) == 0) red[n >> 5] = s;
    __syncthreads();
    float tot = red[0] + red[1] + red[2] + red[3] + red[4] + red[5] + red[6] + red[7];
    out[(long)col * 256 + n] = v / sqrtf(tot);
}

// ===========================================================================
extern "C" void kernel_launch(void* const* d_in, const int* in_sizes, int n_in,
                              void* d_out, int out_size)
{
    using namespace sg;
    const float* input = (const float*)d_in[0];
    const float* boxes = (const float*)d_in[1];
    const float* W_ctx = (const float*)d_in[3];
    const float* b_ctx = (const float*)d_in[4];
    const float* W_rel = (const float*)d_in[5];
    const float* b_rel = (const float*)d_in[6];
    const float* W_of  = (const float*)d_in[7];
    const float* b_of  = (const float*)d_in[8];
    const float* W_rf  = (const float*)d_in[9];
    const float* b_rf  = (const float*)d_in[10];
    const float* W_ofc = (const float*)d_in[11];
    const float* b_ofc = (const float*)d_in[12];
    const float* W_rfc = (const float*)d_in[13];
    const float* b_rfc = (const float*)d_in[14];
    float* out = (float*)d_out;

    const long s784  = 256L * 784;
    const int SMEM_HMMA = 2 * 4 * 128 * 40 * 2;   // 81920 bytes

    cudaFuncSetAttribute(hmma_gemm_kernel, cudaFuncAttributeMaxDynamicSharedMemorySize, SMEM_HMMA);
    cudaFuncSetAttribute(pool_rel_kernel, cudaFuncAttributeMaxDynamicSharedMemorySize, 384 * 49 * 4);

    // 0. fused ctx + rel 1x1 convs
    conv_dual_kernel<<<dim3(6, 10, 8), 256>>>(input, W_ctx, b_ctx, W_rel, b_rel);
    // 1. fused transposes (feat + relf)
    transpose_dual_kernel<<<dim3(12, 20, 8), dim3(32, 8)>>>(input);
    // 2. pair-GEMM weight conversion
    convert_w_kernel<<<384, 256>>>(W_rf, 896, 512, OF_WPH, OF_WPL, 256L * 384, 384);
    // 3. pool rel  (index 3 -> ncu capture target)
    pool_rel_kernel<<<dim3(256, 8), 384, 384 * 49 * 4>>>(boxes);
    // 4-5. ctx/obj pooling
    pool_ctx_kernel<<<dim3(4, 8), 256>>>();
    pool_obj_kernel<<<dim3(16, 8), 256>>>(boxes);
    // 6. pack ctx-pooled channels into Xobj (sums 4 ctx partials)
    pack_xobj_kernel<<<dim3(16, 8), 256>>>();
    // 7. obj conv (fp32)
    sgemm128_kernel<<<dim3(7, 2, 8), 256>>>(W_of, 0, 512, OF_XOBJ, 784, 512L * 784,
                                            OF_OBJ, 784, s784, 784, 512, 512, 1, b_of,
                                            1, 0, 0);
    // 8. Asub + Aobj in ONE launch
    sgemm128_kernel<<<dim3(7, 4, 8), 256>>>(W_rf, 0, 896, OF_OBJ, 784, s784,
                                            OF_ASUB, 784, s784, 784, 256, 256, 1, nullptr,
                                            2, 256, OF_AOBJ - OF_ASUB);
    // 9. pair GEMM (HMMA, batched) + fused combine/relu/split epilogue -> R^T
    hmma_gemm_kernel<<<dim3(98, 2, 8), 256, SMEM_HMMA>>>(
        OF_WPH, OF_WPL, 384, OF_XRTH, OF_XRTL, 384, (long)KFC * 384,
        0, 0, 0, 384, 1, 1, OF_ASUB, OF_AOBJ, b_rf, OF_RTH, OF_RTL);
    // 10. rel FC weight conversion
    convert_w_kernel<<<4096, 256>>>(W_rfc, KFC, 0, OF_WRH, OF_WRL, 256L * KFC, KFC);
    // 11. rel FC (HMMA, split-K 14) + reduce
    hmma_gemm_kernel<<<dim3(16, 2, SPLK), 256, SMEM_HMMA>>>(
        OF_WRH, OF_WRL, KFC, OF_RTH, OF_RTL, KFC, 0,
        OF_FP, 2048, 256L * 2048, KFC / SPLK, 0, 0, 0, 0, nullptr, 0, 0);
    reduce_split_kernel<<<2048, 256>>>(OF_FP, OF_FREL, 256L * 2048, 2048, SPLK, b_rfc);
    // 12. relu(obj) -> Robj^T bf16 hi/lo
    combine_obj_kernel<<<1024, 256>>>();
    // 13. obj FC weight conversion
    convert_w_kernel<<<4096, 256>>>(W_ofc, KFC, 0, OF_WOH, OF_WOL, 256L * KFC, KFC);
    // 14. obj FC (HMMA, split-K 49) + reduce
    hmma_gemm_kernel<<<dim3(1, 2, SPLKO), 256, SMEM_HMMA>>>(
        OF_WOH, OF_WOL, KFC, OF_ROH, OF_ROL, KFC, 0,
        OF_FPO, 128, 256L * 128, KFC / SPLKO, 0, 0, 0, 0, nullptr, 0, 0);
    reduce_split_kernel<<<128, 256>>>(OF_FPO, OF_FOBJ, 256L * 128, 128, SPLKO, b_ofc);
    // 15-16. l2norm heads
    finalize_kernel<<<128, 256>>>(OF_FOBJ, 128, out);
    finalize_kernel<<<2048, 256>>>(OF_FREL, 2048, out + 32768);
}

// round 10
// speedup vs baseline: 5.1661x; 1.0852x over previous
#include <cuda_runtime.h>
#include <cuda_bf16.h>
#include <math.h>
#include <stdint.h>

namespace sg {
constexpr int Bn = 8, Cc = 256, Nn = 16;
constexpr int HW = 384;
constexpr int C32 = 384;
constexpr float SCALE = 1.0f / 16.0f;
constexpr float IMGW = 384.0f, IMGH = 256.0f;
constexpr int PP = 49;
constexpr int KFC = 12544;            // 256*49
constexpr int SPLK = 14;
constexpr int SPLKO = 49;
constexpr int NPAIRU = 136;           // 16 diag + 120 upper pairs

constexpr long SZ_CTXF  = (long)Bn * Cc * HW;
constexpr long SZ_RELF  = (long)Bn * C32 * HW;
constexpr long SZ_FEATT = SZ_CTXF;
constexpr long SZ_RELFT = SZ_RELF;
constexpr long SZ_PCTX4 = (long)Bn * 4 * Cc * PP;
constexpr long SZ_BIMAP = (long)Bn * Nn * PP;
constexpr long SZ_XOBJ  = (long)Bn * 512 * 784;
constexpr long SZ_OBJ   = (long)Bn * 256 * 784;
constexpr long SZ_ASUB  = SZ_OBJ;
constexpr long SZ_AOBJ  = SZ_OBJ;
constexpr long SZ_FREL  = 256L * 2048;
constexpr long SZ_FOBJ  = 256L * 128;
constexpr long SZ_FP    = (long)SPLK * 256 * 2048;
constexpr long SZ_FPO   = (long)SPLKO * 256 * 128;
constexpr long FU_WP  = 256L * 384 / 2;
constexpr long FU_XRT = (long)Bn * KFC * 384 / 2;
constexpr long FU_WR  = 256L * KFC / 2;
constexpr long FU_RT  = 2048L * KFC / 2;
constexpr long FU_WO  = FU_WR;
constexpr long FU_RO  = 128L * KFC / 2;

constexpr long OF_CTXF  = 0;
constexpr long OF_RELF  = OF_CTXF  + SZ_CTXF;
constexpr long OF_FEATT = OF_RELF  + SZ_RELF;
constexpr long OF_RELFT = OF_FEATT + SZ_FEATT;
constexpr long OF_PCTX4 = OF_RELFT + SZ_RELFT;
constexpr long OF_BIMAP = OF_PCTX4 + SZ_PCTX4;
constexpr long OF_XOBJ  = OF_BIMAP + SZ_BIMAP;
constexpr long OF_OBJ   = OF_XOBJ  + SZ_XOBJ;
constexpr long OF_ASUB  = OF_OBJ   + SZ_OBJ;
constexpr long OF_AOBJ  = OF_ASUB  + SZ_ASUB;
constexpr long OF_FREL  = OF_AOBJ  + SZ_AOBJ;
constexpr long OF_FOBJ  = OF_FREL  + SZ_FREL;
constexpr long OF_FP    = OF_FOBJ  + SZ_FOBJ;
constexpr long OF_FPO   = OF_FP    + SZ_FP;
constexpr long OF_WPH   = OF_FPO   + SZ_FPO;
constexpr long OF_WPL   = OF_WPH   + FU_WP;
constexpr long OF_XRTH  = OF_WPL   + FU_WP;
constexpr long OF_XRTL  = OF_XRTH  + FU_XRT;
constexpr long OF_WRH   = OF_XRTL  + FU_XRT;
constexpr long OF_WRL   = OF_WRH   + FU_WR;
constexpr long OF_RTH   = OF_WRL   + FU_WR;
constexpr long OF_RTL   = OF_RTH   + FU_RT;
constexpr long OF_WOH   = OF_RTL   + FU_RT;
constexpr long OF_WOL   = OF_WOH   + FU_WO;
constexpr long OF_ROH   = OF_WOL   + FU_WO;
constexpr long OF_ROL   = OF_ROH   + FU_RO;
constexpr long TOTAL    = OF_ROL   + FU_RO;
}  // namespace sg

__device__ float g_buf[sg::TOTAL];

// ========================= low-level helpers ===============================
__device__ __forceinline__ uint32_t smem_u32(const void* p) {
    uint32_t a;
    asm("{ .reg .u64 t; cvta.to.shared.u64 t, %1; cvt.u32.u64 %0, t; }" : "=r"(a) : "l"(p));
    return a;
}
__device__ __forceinline__ void cp_async16(uint32_t dst, const void* src) {
    asm volatile("cp.async.cg.shared.global [%0], [%1], 16;" :: "r"(dst), "l"(src));
}
__device__ __forceinline__ void cp_commit() {
    asm volatile("cp.async.commit_group;" ::: "memory");
}
__device__ __forceinline__ void ldsm4(uint32_t* a, uint32_t addr) {
    asm volatile("ldmatrix.sync.aligned.m8n8.x4.shared.b16 {%0,%1,%2,%3}, [%4];"
        : "=r"(a[0]), "=r"(a[1]), "=r"(a[2]), "=r"(a[3]) : "r"(addr));
}
__device__ __forceinline__ void ldsm2(uint32_t* b, uint32_t addr) {
    asm volatile("ldmatrix.sync.aligned.m8n8.x2.shared.b16 {%0,%1}, [%2];"
        : "=r"(b[0]), "=r"(b[1]) : "r"(addr));
}
__device__ __forceinline__ void mma16816(float* d, const uint32_t* a, const uint32_t* b) {
    asm volatile("mma.sync.aligned.m16n8k16.row.col.f32.bf16.bf16.f32 "
        "{%0,%1,%2,%3}, {%4,%5,%6,%7}, {%8,%9}, {%0,%1,%2,%3};"
        : "+f"(d[0]), "+f"(d[1]), "+f"(d[2]), "+f"(d[3])
        : "r"(a[0]), "r"(a[1]), "r"(a[2]), "r"(a[3]), "r"(b[0]), "r"(b[1]));
}
__device__ __forceinline__ void split_bf16(float x, __nv_bfloat16& h, __nv_bfloat16& l) {
    h = __float2bfloat16(x);
    l = __float2bfloat16(x - __bfloat162float(h));
}

// ========================= PrRoI pooling helpers ===========================
static __device__ __forceinline__ float hatG(float t) {
    float tl = fminf(fmaxf(t, -1.0f), 0.0f);
    float tr = fminf(fmaxf(t, 0.0f), 1.0f);
    return 0.5f * (tl + 1.0f) * (tl + 1.0f) + 0.5f - 0.5f * (1.0f - tr) * (1.0f - tr);
}

static __device__ __forceinline__ void compute_weights(
    float x1, float y1, float x2, float y2,
    float (*wy)[16], float (*wx)[24],
    int* h0, int* h1, int* w0, int* w1, int tid)
{
    if (tid < 112) {
        int p = tid / 16, i = tid % 16;
        float e0 = y1 + (y2 - y1) * (float)p * (1.0f / 7.0f);
        float e1 = y1 + (y2 - y1) * (float)(p + 1) * (1.0f / 7.0f);
        wy[p][i] = hatG(e1 - (float)i) - hatG(e0 - (float)i);
    }
    if (tid < 168) {
        int q = tid / 24, i = tid % 24;
        float e0 = x1 + (x2 - x1) * (float)q * (1.0f / 7.0f);
        float e1 = x1 + (x2 - x1) * (float)(q + 1) * (1.0f / 7.0f);
        wx[q][i] = hatG(e1 - (float)i) - hatG(e0 - (float)i);
    }
    if (tid < 7) {
        float e0 = y1 + (y2 - y1) * (float)tid * (1.0f / 7.0f);
        float e1 = y1 + (y2 - y1) * (float)(tid + 1) * (1.0f / 7.0f);
        h0[tid] = max(0, (int)ceilf(e0) - 1);
        h1[tid] = min(16, (int)floorf(e1) + 2);
    }
    if (tid >= 32 && tid < 39) {
        int q = tid - 32;
        float e0 = x1 + (x2 - x1) * (float)q * (1.0f / 7.0f);
        float e1 = x1 + (x2 - x1) * (float)(q + 1) * (1.0f / 7.0f);
        w0[q] = max(0, (int)ceilf(e0) - 1);
        w1[q] = min(24, (int)floorf(e1) + 2);
    }
}

static __device__ __forceinline__ void pool_channel_acc_range(
    const float* __restrict__ fb, int ps,
    const float (*wy)[16], const float (*wx)[24],
    const int* w0, const int* w1,
    int hlo, int hhi, float* acc)
{
    for (int h = hlo; h < hhi; h++) {
        const float* row = fb + (long)h * 24 * ps;
        float colsum[7];
#pragma unroll
        for (int q = 0; q < 7; q++) {
            float a = 0.0f;
            for (int w = w0[q]; w < w1[q]; w++)
                a += wx[q][w] * row[(long)w * ps];
            colsum[q] = a;
        }
#pragma unroll
        for (int p = 0; p < 7; p++) {
            float wv = wy[p][h];
#pragma unroll
            for (int q = 0; q < 7; q++)
                acc[p * 7 + q] += wv * colsum[q];
        }
    }
}

// ===================== dual 1x1 conv (ctx + rel in one launch) =============
__global__ void __launch_bounds__(256) conv_dual_kernel(
    const float* __restrict__ input,
    const float* __restrict__ Wctx, const float* __restrict__ bctx,
    const float* __restrict__ Wrel, const float* __restrict__ brel)
{
    using namespace sg;
    __shared__ float As[16][65];
    __shared__ float Bs[16][68];

    const int b = blockIdx.z;
    const int tid = threadIdx.x;
    const int row0 = blockIdx.y * 64;
    const int col0 = blockIdx.x * 64;
    const bool isCtx = row0 < 256;
    const float* A = isCtx ? (Wctx + (long)row0 * 256)
                           : (Wrel + (long)(row0 - 256) * 256);
    const float* bias = isCtx ? bctx : brel;
    const int biasBase = isCtx ? row0 : row0 - 256;
    const float* Bm = input + (long)b * Cc * HW;
    float* Cm = isCtx ? (g_buf + OF_CTXF + (long)b * Cc * HW + (long)row0 * 384)
                      : (g_buf + OF_RELF + (long)b * C32 * HW + (long)(row0 - 256) * 384);

    const int ty = tid >> 4, tx = tid & 15;
    const int ty4 = ty * 4, tx4 = tx * 4;
    const int ar = tid >> 2, ak = (tid & 3) << 2;
    const int br = tid >> 4, bc = (tid & 15) << 2;

    float acc[4][4] = {};

    for (int k0 = 0; k0 < 256; k0 += 16) {
        float4 av = *(const float4*)(A + (long)ar * 256 + k0 + ak);
        As[ak + 0][ar] = av.x; As[ak + 1][ar] = av.y;
        As[ak + 2][ar] = av.z; As[ak + 3][ar] = av.w;
        float4 bv = *(const float4*)(Bm + (long)(k0 + br) * 384 + col0 + bc);
        *(float4*)&Bs[br][bc] = bv;
        __syncthreads();

#pragma unroll
        for (int k = 0; k < 16; k++) {
            float a0 = As[k][ty4 + 0], a1 = As[k][ty4 + 1];
            float a2 = As[k][ty4 + 2], a3 = As[k][ty4 + 3];
            float4 b4 = *(const float4*)&Bs[k][tx4];
            acc[0][0] += a0 * b4.x; acc[0][1] += a0 * b4.y; acc[0][2] += a0 * b4.z; acc[0][3] += a0 * b4.w;
            acc[1][0] += a1 * b4.x; acc[1][1] += a1 * b4.y; acc[1][2] += a1 * b4.z; acc[1][3] += a1 * b4.w;
            acc[2][0] += a2 * b4.x; acc[2][1] += a2 * b4.y; acc[2][2] += a2 * b4.z; acc[2][3] += a2 * b4.w;
            acc[3][0] += a3 * b4.x; acc[3][1] += a3 * b4.y; acc[3][2] += a3 * b4.z; acc[3][3] += a3 * b4.w;
        }
        __syncthreads();
    }

#pragma unroll
    for (int u = 0; u < 4; u++) {
        float bz = bias[biasBase + ty4 + u];
#pragma unroll
        for (int v = 0; v < 4; v++)
            Cm[(long)(ty4 + u) * 384 + col0 + tx4 + v] = acc[u][v] + bz;
    }
}

// fp32 128x128 GEMM, optional multi-term via grid.y folding.
__global__ void __launch_bounds__(256) sgemm128_kernel(
    const float* __restrict__ Aex, long offA, int lda,
    long offB, int ldb, long sBb,
    long offC, int ldc, long sCb,
    int N, int K, int kChunk, int splitK,
    const float* __restrict__ bias,
    int nTerm, long dAoff, long dCoff)
{
    __shared__ float As[2][8][132];
    __shared__ float Bs[2][8][132];

    const int z = blockIdx.z;
    const int b = z / splitK;
    const int ks = z - b * splitK;
    const int kBeg = ks * kChunk;
    const int kEnd = min(K, kBeg + kChunk);
    const int nk = (kEnd - kBeg) >> 3;

    const int rowTiles = gridDim.y / nTerm;
    const int term = blockIdx.y / rowTiles;
    const int row0 = (blockIdx.y - term * rowTiles) * 128;
    const int col0 = blockIdx.x * 128;

    const float* A = Aex + offA + (long)term * dAoff;
    const float* B = g_buf + offB + (long)b * sBb;
    float* C = g_buf + offC + (long)term * dCoff + (long)z * sCb;

    const int t = threadIdx.x;
    const int arow = t >> 1, akq = (t & 1) << 2;
    const int brow = t >> 5, bcol = (t & 31) << 2;
    const int tx = t & 15, ty = t >> 4;

    const float* aPtr = A + (long)(row0 + arow) * lda + kBeg + akq;
    const float* bPtr = B + (long)(kBeg + brow) * ldb + col0 + bcol;
    const bool bIn = (col0 + bcol + 3) < N;

    float4 pa = *(const float4*)aPtr;
    float4 pb;
    if (bIn) {
        pb = *(const float4*)bPtr;
    } else {
        pb.x = (col0 + bcol + 0 < N) ? bPtr[0] : 0.0f;
        pb.y = (col0 + bcol + 1 < N) ? bPtr[1] : 0.0f;
        pb.z = (col0 + bcol + 2 < N) ? bPtr[2] : 0.0f;
        pb.w = 0.0f;
    }
    As[0][akq + 0][arow] = pa.x; As[0][akq + 1][arow] = pa.y;
    As[0][akq + 2][arow] = pa.z; As[0][akq + 3][arow] = pa.w;
    *(float4*)&Bs[0][brow][bcol] = pb;
    __syncthreads();

    float acc[8][8] = {};

    for (int kt = 0; kt < nk; kt++) {
        const int buf = kt & 1;
        if (kt + 1 < nk) {
            pa = *(const float4*)(aPtr + (kt + 1) * 8);
            const float* bp = bPtr + (long)(kt + 1) * 8 * ldb;
            if (bIn) {
                pb = *(const float4*)bp;
            } else {
                pb.x = (col0 + bcol + 0 < N) ? bp[0] : 0.0f;
                pb.y = (col0 + bcol + 1 < N) ? bp[1] : 0.0f;
                pb.z = (col0 + bcol + 2 < N) ? bp[2] : 0.0f;
                pb.w = 0.0f;
            }
        }
#pragma unroll
        for (int kk = 0; kk < 8; kk++) {
            float4 a0 = *(const float4*)&As[buf][kk][ty * 4];
            float4 a1 = *(const float4*)&As[buf][kk][64 + ty * 4];
            float4 b0 = *(const float4*)&Bs[buf][kk][tx * 4];
            float4 b1 = *(const float4*)&Bs[buf][kk][64 + tx * 4];
            float av[8] = {a0.x, a0.y, a0.z, a0.w, a1.x, a1.y, a1.z, a1.w};
            float bv[8] = {b0.x, b0.y, b0.z, b0.w, b1.x, b1.y, b1.z, b1.w};
#pragma unroll
            for (int u = 0; u < 8; u++)
#pragma unroll
                for (int v = 0; v < 8; v++)
                    acc[u][v] += av[u] * bv[v];
        }
        if (kt + 1 < nk) {
            const int nb = buf ^ 1;
            As[nb][akq + 0][arow] = pa.x; As[nb][akq + 1][arow] = pa.y;
            As[nb][akq + 2][arow] = pa.z; As[nb][akq + 3][arow] = pa.w;
            *(float4*)&Bs[nb][brow][bcol] = pb;
            __syncthreads();
        }
    }

#pragma unroll
    for (int u = 0; u < 8; u++) {
        int r = row0 + ((u < 4) ? ty * 4 + u : 64 + ty * 4 + (u - 4));
        float bz = bias ? bias[r] : 0.0f;
#pragma unroll
        for (int v = 0; v < 8; v++) {
            int c = col0 + ((v < 4) ? tx * 4 + v : 64 + tx * 4 + (v - 4));
            if (c < N) C[(long)r * ldc + c] = acc[u][v] + bz;
        }
    }
}

// ================ HMMA (mma.sync) bf16-split GEMM ==========================
__global__ void __launch_bounds__(256) hmma_gemm_kernel(
    long offAhi, long offAlo, int lda,
    long offBhi, long offBlo, int ldb, long sBz,
    long offC, int ldc, long sCz,
    int kChunk, int batchB, int epiMode,
    long offAsub, long offAobj, const float* __restrict__ brf,
    long offRh, long offRl)
{
    extern __shared__ __nv_bfloat16 smb[];
    constexpr int STR = 40;
    constexpr int TILEE = 128 * STR;

    const int tid = threadIdx.x;
    const int warp = tid >> 5, lane = tid & 31;
    const int z = blockIdx.z;
    const int row0 = blockIdx.y * 128, col0 = blockIdx.x * 128;
    const long kBeg = batchB ? 0 : (long)z * kChunk;
    const int S = kChunk / 32;

    const __nv_bfloat16* Ahi = (const __nv_bfloat16*)(g_buf + offAhi);
    const __nv_bfloat16* Alo = (const __nv_bfloat16*)(g_buf + offAlo);
    const __nv_bfloat16* Bhi = (const __nv_bfloat16*)(g_buf + offBhi) + (batchB ? (long)z * sBz : 0);
    const __nv_bfloat16* Blo = (const __nv_bfloat16*)(g_buf + offBlo) + (batchB ? (long)z * sBz : 0);

    const int wm = (warp >> 2) * 64;
    const int wn = (warp & 3) * 32;

    float acc[4][4][4] = {};

    const uint32_t smem_base = smem_u32(smb);

    auto issue_load = [&](int s, int buf) {
        long koff = kBeg + (long)s * 32;
        uint32_t dstBase = smem_base + (uint32_t)buf * 4 * TILEE * 2;
#pragma unroll
        for (int t = 0; t < 4; t++) {
            const __nv_bfloat16* src = (t == 0) ? Ahi : (t == 1) ? Alo
                                      : (t == 2) ? Bhi : Blo;
            const int base0 = (t < 2) ? row0 : col0;
            const int ld = (t < 2) ? lda : ldb;
#pragma unroll
            for (int i = 0; i < 2; i++) {
                int idx = tid + i * 256;
                int r = idx >> 2;
                int cg = (idx & 3) * 8;
                cp_async16(dstBase + (uint32_t)((t * TILEE + r * STR + cg) * 2),
                           src + (long)(base0 + r) * ld + koff + cg);
            }
        }
        cp_commit();
    };

    issue_load(0, 0);

    for (int s = 0; s < S; s++) {
        if (s + 1 < S) {
            issue_load(s + 1, (s + 1) & 1);
            asm volatile("cp.async.wait_group 1;" ::: "memory");
        } else {
            asm volatile("cp.async.wait_group 0;" ::: "memory");
        }
        __syncthreads();

        const int buf = s & 1;
        const uint32_t tb = smem_base + (uint32_t)buf * 4 * TILEE * 2;
        const uint32_t aHiB = tb;
        const uint32_t aLoB = tb + TILEE * 2;
        const uint32_t bHiB = tb + 2 * TILEE * 2;
        const uint32_t bLoB = tb + 3 * TILEE * 2;
        const int lr = lane & 15;
        const int kofA = (lane >> 4) * 8;
        const int kofB = ((lane & 15) >> 3) * 8;

#pragma unroll
        for (int k16 = 0; k16 < 2; k16++) {
            uint32_t af[4][4], bh[4][2], bl[4][2];
#pragma unroll
            for (int mi = 0; mi < 4; mi++)
                ldsm4(af[mi], aHiB + (uint32_t)(((wm + mi * 16 + lr) * STR)
                                               + k16 * 16 + kofA) * 2);
#pragma unroll
            for (int ni = 0; ni < 4; ni++) {
                uint32_t ro = (uint32_t)(((wn + ni * 8 + (lr & 7)) * STR)
                                         + k16 * 16 + kofB) * 2;
                ldsm2(bh[ni], bHiB + ro);
                ldsm2(bl[ni], bLoB + ro);
            }
#pragma unroll
            for (int mi = 0; mi < 4; mi++)
#pragma unroll
                for (int ni = 0; ni < 4; ni++) {
                    mma16816(acc[mi][ni], af[mi], bh[ni]);   // hh
                    mma16816(acc[mi][ni], af[mi], bl[ni]);   // hl
                }
#pragma unroll
            for (int mi = 0; mi < 4; mi++)
                ldsm4(af[mi], aLoB + (uint32_t)(((wm + mi * 16 + lr) * STR)
                                               + k16 * 16 + kofA) * 2);
#pragma unroll
            for (int mi = 0; mi < 4; mi++)
#pragma unroll
                for (int ni = 0; ni < 4; ni++)
                    mma16816(acc[mi][ni], af[mi], bh[ni]);   // lh
        }
        __syncthreads();
    }

    if (epiMode == 0) {
        float* C = g_buf + offC + (long)z * sCz;
#pragma unroll
        for (int mi = 0; mi < 4; mi++) {
            int r = row0 + wm + mi * 16 + (lane >> 2);
#pragma unroll
            for (int ni = 0; ni < 4; ni++) {
                int cc = col0 + wn + ni * 8 + (lane & 3) * 2;
                *(float2*)&C[(long)r * ldc + cc] = make_float2(acc[mi][ni][0], acc[mi][ni][1]);
                *(float2*)&C[(long)(r + 8) * ldc + cc] = make_float2(acc[mi][ni][2], acc[mi][ni][3]);
            }
        }
    } else {
        using namespace sg;
        const float* A1b = g_buf + offAsub + (long)z * 256 * 784;
        const float* A2b = g_buf + offAobj + (long)z * 256 * 784;
        __nv_bfloat16* rh = (__nv_bfloat16*)(g_buf + offRh) + (long)z * 256 * KFC;
        __nv_bfloat16* rl = (__nv_bfloat16*)(g_buf + offRl) + (long)z * 256 * KFC;
#pragma unroll
        for (int mi = 0; mi < 4; mi++) {
#pragma unroll
            for (int half = 0; half < 2; half++) {
                int o = row0 + wm + mi * 16 + (lane >> 2) + half * 8;
                float bz = brf[o];
#pragma unroll
                for (int ni = 0; ni < 4; ni++) {
#pragma unroll
                    for (int e = 0; e < 2; e++) {
                        int cc = col0 + wn + ni * 8 + (lane & 3) * 2 + e;
                        int pair = cc / 49;
                        int s = cc - pair * 49;
                        int io = (pair >> 4) * 49 + s;
                        int jo = (pair & 15) * 49 + s;
                        float v = acc[mi][ni][half * 2 + e]
                                + A1b[(long)o * 784 + io]
                                + A2b[(long)o * 784 + jo] + bz;
                        v = fmaxf(v, 0.0f);
                        __nv_bfloat16 h, l;
                        split_bf16(v, h, l);
                        long di = (long)pair * KFC + o * 49 + s;
                        rh[di] = h;
                        rl[di] = l;
                    }
                }
            }
        }
    }
}

// ==================== misc data-movement / pooling =========================
__global__ void transpose_dual_kernel(const float* __restrict__ input)
{
    using namespace sg;
    __shared__ float tile[32][33];
    int b = blockIdx.z;
    const float* src;
    float* dst;
    int R, r0;
    if (blockIdx.y < 8) {
        R = 256; r0 = blockIdx.y * 32;
        src = input + (long)b * 256 * 384;
        dst = g_buf + OF_FEATT + (long)b * 256 * 384;
    } else {
        R = 384; r0 = (blockIdx.y - 8) * 32;
        src = g_buf + OF_RELF + (long)b * 384 * 384;
        dst = g_buf + OF_RELFT + (long)b * 384 * 384;
    }
    int c0 = blockIdx.x * 32;
    int tx = threadIdx.x, ty = threadIdx.y;
#pragma unroll
    for (int k = 0; k < 32; k += 8)
        tile[ty + k][tx] = src[(long)(r0 + ty + k) * 384 + c0 + tx];
    __syncthreads();
#pragma unroll
    for (int k = 0; k < 32; k += 8)
        dst[(long)(c0 + ty + k) * R + r0 + tx] = tile[tx][ty + k];
}

__global__ void __launch_bounds__(256) pool_obj_kernel(const float* __restrict__ boxes)
{
    using namespace sg;
    int b = blockIdx.y, n = blockIdx.x, tid = threadIdx.x;
    const float* bx = boxes + ((long)b * Nn + n) * 4;
    float x1 = bx[0], y1 = bx[1], x2 = bx[2], y2 = bx[3];
    float sx1 = x1 * SCALE, sy1 = y1 * SCALE, sx2 = x2 * SCALE, sy2 = y2 * SCALE;

    __shared__ float wy[7][16], wx[7][24];
    __shared__ int h0[7], h1[7], w0[7], w1[7];
    compute_weights(sx1, sy1, sx2, sy2, wy, wx, h0, h1, w0, w1, tid);

    if (tid < 49) {
        int p = tid / 7, q = tid % 7;
        float ye0 = IMGH * (float)p * (1.0f / 7.0f), ye1 = IMGH * (float)(p + 1) * (1.0f / 7.0f);
        float xe0 = IMGW * (float)q * (1.0f / 7.0f), xe1 = IMGW * (float)(q + 1) * (1.0f / 7.0f);
        float oy = fmaxf(fminf(ye1, y2) - fmaxf(ye0, y1), 0.0f);
        float ox = fmaxf(fminf(xe1, x2) - fmaxf(xe0, x1), 0.0f);
        float ch = IMGH * (1.0f / 7.0f), cw = IMGW * (1.0f / 7.0f);
        g_buf[OF_BIMAP + ((long)b * Nn + n) * PP + tid] = (oy / ch) * (ox / cw);
    }
    __syncthreads();

    float area = (sx2 - sx1) * (sy2 - sy1) * (1.0f / 49.0f);
    float inv = (area > 0.0f) ? 1.0f / fmaxf(area, 1e-9f) : 0.0f;

    int c = tid;
    const float* fb = g_buf + OF_FEATT + (long)b * HW * Cc + c;
    float acc[49];
#pragma unroll
    for (int s = 0; s < 49; s++) acc[s] = 0.0f;
    pool_channel_acc_range(fb, Cc, wy, wx, w0, w1, h0[0], h1[6], acc);

    float* X = g_buf + OF_XOBJ + ((long)b * 512 + c) * 784 + (long)n * 49;
#pragma unroll
    for (int s = 0; s < 49; s++) X[s] = acc[s] * inv;
}

__global__ void __launch_bounds__(256) pool_ctx_kernel()
{
    using namespace sg;
    int hq = blockIdx.x, b = blockIdx.y, tid = threadIdx.x;
    __shared__ float wy[7][16], wx[7][24];
    __shared__ int h0[7], h1[7], w0[7], w1[7];
    compute_weights(0.0f, 0.0f, 24.0f, 16.0f, wy, wx, h0, h1, w0, w1, tid);
    __syncthreads();

    float inv = 49.0f / (24.0f * 16.0f);
    int c = tid;
    const float* fb = g_buf + OF_CTXF + ((long)b * Cc + c) * HW;
    float acc[49];
#pragma unroll
    for (int s = 0; s < 49; s++) acc[s] = 0.0f;
    pool_channel_acc_range(fb, 1, wy, wx, w0, w1, hq * 4, hq * 4 + 4, acc);
    float* X = g_buf + OF_PCTX4 + (((long)b * 4 + hq) * Cc + c) * PP;
#pragma unroll
    for (int s = 0; s < 49; s++) X[s] = acc[s] * inv;
}

__global__ void pack_xobj_kernel()
{
    using namespace sg;
    int b = blockIdx.y;
    int base = blockIdx.x * blockDim.x + threadIdx.x;
    int stride = gridDim.x * blockDim.x;
    for (int idx = base; idx < 256 * 784; idx += stride) {
        int cc = idx / 784, rem = idx - cc * 784;
        int n = rem / 49, s = rem - n * 49;
        long p0 = OF_PCTX4 + ((long)b * 4 * Cc + cc) * PP + s;
        float v = g_buf[p0] + g_buf[p0 + (long)Cc * PP]
                + g_buf[p0 + 2L * Cc * PP] + g_buf[p0 + 3L * Cc * PP];
        if (cc >= 128) v *= g_buf[OF_BIMAP + ((long)b * Nn + n) * PP + s];
        g_buf[OF_XOBJ + ((long)b * 512 + 256 + cc) * 784 + rem] = v;
    }
}

// Symmetric pool_rel: union(i,j) == union(j,i). One block pools once for the
// unordered pair {i,j} (i<=j) and writes BOTH ordered pairs' XrelT rows
// (masks swap between the two). grid(136, 8), block 384.
__global__ void __launch_bounds__(384) pool_rel_kernel(const float* __restrict__ boxes)
{
    using namespace sg;
    extern __shared__ float stage[];
    int b = blockIdx.y, t = blockIdx.x, tid = threadIdx.x;
    // triangular unpack: t -> (i, j) with i <= j
    int i = 0, rem = t;
    while (rem >= 16 - i) { rem -= 16 - i; i++; }
    int j = i + rem;

    const float* bi = boxes + ((long)b * Nn + i) * 4;
    const float* bj = boxes + ((long)b * Nn + j) * 4;
    float ix1 = bi[0], iy1 = bi[1], ix2 = bi[2], iy2 = bi[3];
    float jx1 = bj[0], jy1 = bj[1], jx2 = bj[2], jy2 = bj[3];
    float ux1 = fminf(ix1, jx1), uy1 = fminf(iy1, jy1);
    float ux2 = fmaxf(ix2, jx2), uy2 = fmaxf(iy2, jy2);
    float sx1 = ux1 * SCALE, sy1 = uy1 * SCALE, sx2 = ux2 * SCALE, sy2 = uy2 * SCALE;

    __shared__ float wy[7][16], wx[7][24];
    __shared__ int h0[7], h1[7], w0[7], w1[7];
    __shared__ float subm[49], objm[49];
    compute_weights(sx1, sy1, sx2, sy2, wy, wx, h0, h1, w0, w1, tid);

    if (tid < 49) {
        int p = tid / 7, q = tid - p * 7;
        float ye0 = uy1 + (uy2 - uy1) * (float)p * (1.0f / 7.0f);
        float ye1 = uy1 + (uy2 - uy1) * (float)(p + 1) * (1.0f / 7.0f);
        float xe0 = ux1 + (ux2 - ux1) * (float)q * (1.0f / 7.0f);
        float xe1 = ux1 + (ux2 - ux1) * (float)(q + 1) * (1.0f / 7.0f);
        float ch = fmaxf((uy2 - uy1) * (1.0f / 7.0f), 1e-9f);
        float cw = fmaxf((ux2 - ux1) * (1.0f / 7.0f), 1e-9f);
        float oy = fmaxf(fminf(ye1, iy2) - fmaxf(ye0, iy1), 0.0f);
        float ox = fmaxf(fminf(xe1, ix2) - fmaxf(xe0, ix1), 0.0f);
        subm[tid] = (oy / ch) * (ox / cw);          // mask of box i
        oy = fmaxf(fminf(ye1, jy2) - fmaxf(ye0, jy1), 0.0f);
        ox = fmaxf(fminf(xe1, jx2) - fmaxf(xe0, jx1), 0.0f);
        objm[tid] = (oy / ch) * (ox / cw);          // mask of box j
    }
    __syncthreads();

    float area = (sx2 - sx1) * (sy2 - sy1) * (1.0f / 49.0f);
    float inv = (area > 0.0f) ? 1.0f / fmaxf(area, 1e-9f) : 0.0f;

    int c = tid;
    const float* fb = g_buf + OF_RELFT + (long)b * HW * C32 + c;
    float acc[49];
#pragma unroll
    for (int s = 0; s < 49; s++) acc[s] = 0.0f;
    pool_channel_acc_range(fb, C32, wy, wx, w0, w1, h0[0], h1[6], acc);

#pragma unroll
    for (int s = 0; s < 49; s++)
        stage[c * 49 + s] = acc[s] * inv;           // raw (unmasked)
    __syncthreads();

    __nv_bfloat16* xh = (__nv_bfloat16*)(g_buf + OF_XRTH);
    __nv_bfloat16* xl = (__nv_bfloat16*)(g_buf + OF_XRTL);
    int pair1 = i * 16 + j;                         // sub=i, obj=j
    int pair2 = j * 16 + i;                         // sub=j, obj=i
    long base1 = ((long)b * KFC + (long)pair1 * 49) * 384;
    long base2 = ((long)b * KFC + (long)pair2 * 49) * 384;
    for (int idx = tid; idx < 49 * 384; idx += 384) {
        int s = idx / 384, cc = idx - s * 384;
        float raw = stage[cc * 49 + s];
        float m1 = (cc < 128) ? 1.0f : (cc < 256 ? subm[s] : objm[s]);
        __nv_bfloat16 h, l;
        split_bf16(raw * m1, h, l);
        xh[base1 + (long)s * 384 + cc] = h;
        xl[base1 + (long)s * 384 + cc] = l;
        if (i != j) {
            float m2 = (cc < 128) ? 1.0f : (cc < 256 ? objm[s] : subm[s]);
            split_bf16(raw * m2, h, l);
            xh[base2 + (long)s * 384 + cc] = h;
            xl[base2 + (long)s * 384 + cc] = l;
        }
    }
}

// relu(obj) -> Robj^T hi/lo [128][12544]
__global__ void __launch_bounds__(256) combine_obj_kernel()
{
    using namespace sg;
    int row = blockIdx.x >> 3;
    int seg = blockIdx.x & 7;
    int b = row >> 4, i = row & 15;
    const float* obj = g_buf + OF_OBJ + (long)b * 256 * 784 + (long)i * 49;
    __nv_bfloat16* rh = (__nv_bfloat16*)(g_buf + OF_ROH) + (long)row * KFC;
    __nv_bfloat16* rl = (__nv_bfloat16*)(g_buf + OF_ROL) + (long)row * KFC;
    int beg = seg * 1568, end = beg + 1568;
    for (int idx = beg + threadIdx.x; idx < end; idx += 256) {
        int o = idx / 49, s = idx - o * 49;
        float v = fmaxf(obj[(long)o * 784 + s], 0.0f);
        __nv_bfloat16 h, l;
        split_bf16(v, h, l);
        rh[idx] = h; rl[idx] = l;
    }
}

__global__ void convert_w_kernel(const float* __restrict__ W, int lda, int colOff,
                                 long offHi, long offLo, long total, int Kout)
{
    __nv_bfloat16* ph = (__nv_bfloat16*)(g_buf + offHi);
    __nv_bfloat16* pl = (__nv_bfloat16*)(g_buf + offLo);
    for (long idx = (long)blockIdx.x * blockDim.x + threadIdx.x; idx < total;
         idx += (long)gridDim.x * blockDim.x) {
        long m = idx / Kout;
        int k = (int)(idx - m * Kout);
        float x = W[m * lda + colOff + k];
        __nv_bfloat16 h, l;
        split_bf16(x, h, l);
        ph[idx] = h; pl[idx] = l;
    }
}

__global__ void reduce_split_kernel(long offP, long offO, long MN, int Ncols,
                                    int S, const float* __restrict__ bias)
{
    long idx = (long)blockIdx.x * blockDim.x + threadIdx.x;
    if (idx >= MN) return;
    float s = 0.0f;
    for (int i = 0; i < S; i++) s += g_buf[offP + (long)i * MN + idx];
    int m = (int)(idx / Ncols);
    g_buf[offO + idx] = s + bias[m];
}

__global__ void finalize_kernel(long srcOff, int ncols, float* __restrict__ out)
{
    int col = blockIdx.x, n = threadIdx.x;
    float v = g_buf[srcOff + (long)n * ncols + col];
    float s = v * v;
#pragma unroll
    for (int o = 16; o > 0; o >>= 1) s += __shfl_xor_sync(0xffffffffu, s, o);
    __shared__ float red[8];
    if ((n & 31) == 0) red[n >> 5] = s;
    __syncthreads();
    float tot = red[0] + red[1] + red[2] + red[3] + red[4] + red[5] + red[6] + red[7];
    out[(long)col * 256 + n] = v / sqrtf(tot);
}

// ===========================================================================
extern "C" void kernel_launch(void* const* d_in, const int* in_sizes, int n_in,
                              void* d_out, int out_size)
{
    using namespace sg;
    const float* input = (const float*)d_in[0];
    const float* boxes = (const float*)d_in[1];
    const float* W_ctx = (const float*)d_in[3];
    const float* b_ctx = (const float*)d_in[4];
    const float* W_rel = (const float*)d_in[5];
    const float* b_rel = (const float*)d_in[6];
    const float* W_of  = (const float*)d_in[7];
    const float* b_of  = (const float*)d_in[8];
    const float* W_rf  = (const float*)d_in[9];
    const float* b_rf  = (const float*)d_in[10];
    const float* W_ofc = (const float*)d_in[11];
    const float* b_ofc = (const float*)d_in[12];
    const float* W_rfc = (const float*)d_in[13];
    const float* b_rfc = (const float*)d_in[14];
    float* out = (float*)d_out;

    const long s784  = 256L * 784;
    const int SMEM_HMMA = 2 * 4 * 128 * 40 * 2;   // 81920 bytes

    cudaFuncSetAttribute(hmma_gemm_kernel, cudaFuncAttributeMaxDynamicSharedMemorySize, SMEM_HMMA);
    cudaFuncSetAttribute(pool_rel_kernel, cudaFuncAttributeMaxDynamicSharedMemorySize, 384 * 49 * 4);

    // 0. fused ctx + rel 1x1 convs
    conv_dual_kernel<<<dim3(6, 10, 8), 256>>>(input, W_ctx, b_ctx, W_rel, b_rel);
    // 1. fused transposes (feat + relf)
    transpose_dual_kernel<<<dim3(12, 20, 8), dim3(32, 8)>>>(input);
    // 2. pair-GEMM weight conversion
    convert_w_kernel<<<384, 256>>>(W_rf, 896, 512, OF_WPH, OF_WPL, 256L * 384, 384);
    // 3. pool rel, symmetric pairs  (index 3 -> ncu capture target)
    pool_rel_kernel<<<dim3(NPAIRU, 8), 384, 384 * 49 * 4>>>(boxes);
    // 4-5. ctx/obj pooling
    pool_ctx_kernel<<<dim3(4, 8), 256>>>();
    pool_obj_kernel<<<dim3(16, 8), 256>>>(boxes);
    // 6. pack ctx-pooled channels into Xobj (sums 4 ctx partials)
    pack_xobj_kernel<<<dim3(16, 8), 256>>>();
    // 7. obj conv (fp32)
    sgemm128_kernel<<<dim3(7, 2, 8), 256>>>(W_of, 0, 512, OF_XOBJ, 784, 512L * 784,
                                            OF_OBJ, 784, s784, 784, 512, 512, 1, b_of,
                                            1, 0, 0);
    // 8. Asub + Aobj in ONE launch
    sgemm128_kernel<<<dim3(7, 4, 8), 256>>>(W_rf, 0, 896, OF_OBJ, 784, s784,
                                            OF_ASUB, 784, s784, 784, 256, 256, 1, nullptr,
                                            2, 256, OF_AOBJ - OF_ASUB);
    // 9. pair GEMM (HMMA, batched) + fused combine/relu/split epilogue -> R^T
    hmma_gemm_kernel<<<dim3(98, 2, 8), 256, SMEM_HMMA>>>(
        OF_WPH, OF_WPL, 384, OF_XRTH, OF_XRTL, 384, (long)KFC * 384,
        0, 0, 0, 384, 1, 1, OF_ASUB, OF_AOBJ, b_rf, OF_RTH, OF_RTL);
    // 10. rel FC weight conversion
    convert_w_kernel<<<4096, 256>>>(W_rfc, KFC, 0, OF_WRH, OF_WRL, 256L * KFC, KFC);
    // 11. rel FC (HMMA, split-K 14) + reduce
    hmma_gemm_kernel<<<dim3(16, 2, SPLK), 256, SMEM_HMMA>>>(
        OF_WRH, OF_WRL, KFC, OF_RTH, OF_RTL, KFC, 0,
        OF_FP, 2048, 256L * 2048, KFC / SPLK, 0, 0, 0, 0, nullptr, 0, 0);
    reduce_split_kernel<<<2048, 256>>>(OF_FP, OF_FREL, 256L * 2048, 2048, SPLK, b_rfc);
    // 12. relu(obj) -> Robj^T bf16 hi/lo
    combine_obj_kernel<<<1024, 256>>>();
    // 13. obj FC weight conversion
    convert_w_kernel<<<4096, 256>>>(W_ofc, KFC, 0, OF_WOH, OF_WOL, 256L * KFC, KFC);
    // 14. obj FC (HMMA, split-K 49) + reduce
    hmma_gemm_kernel<<<dim3(1, 2, SPLKO), 256, SMEM_HMMA>>>(
        OF_WOH, OF_WOL, KFC, OF_ROH, OF_ROL, KFC, 0,
        OF_FPO, 128, 256L * 128, KFC / SPLKO, 0, 0, 0, 0, nullptr, 0, 0);
    reduce_split_kernel<<<128, 256>>>(OF_FPO, OF_FOBJ, 256L * 128, 128, SPLKO, b_ofc);
    // 15-16. l2norm heads
    finalize_kernel<<<128, 256>>>(OF_FOBJ, 128, out);
    finalize_kernel<<<2048, 256>>>(OF_FREL, 2048, out + 32768);
}

// round 11
// speedup vs baseline: 5.3543x; 1.0364x over previous
#include <cuda_runtime.h>
#include <cuda_bf16.h>
#include <math.h>
#include <stdint.h>

namespace sg {
constexpr int Bn = 8, Cc = 256, Nn = 16;
constexpr int HW = 384;
constexpr int C32 = 384;
constexpr float SCALE = 1.0f / 16.0f;
constexpr float IMGW = 384.0f, IMGH = 256.0f;
constexpr int PP = 49;
constexpr int KFC = 12544;
constexpr int SPLK = 14;
constexpr int SPLKO = 49;
constexpr int NPAIRU = 136;

constexpr long SZ_CTXF  = (long)Bn * Cc * HW;
constexpr long SZ_RELF  = (long)Bn * C32 * HW;
constexpr long SZ_FEATT = SZ_CTXF;
constexpr long SZ_RELFT = SZ_RELF;
constexpr long SZ_PCTX4 = (long)Bn * 4 * Cc * PP;
constexpr long SZ_BIMAP = (long)Bn * Nn * PP;
constexpr long SZ_XOBJ  = (long)Bn * 512 * 784;
constexpr long SZ_OBJ   = (long)Bn * 256 * 784;
constexpr long SZ_ASUB  = SZ_OBJ;
constexpr long SZ_AOBJ  = SZ_OBJ;
constexpr long SZ_FREL  = 256L * 2048;
constexpr long SZ_FOBJ  = 256L * 128;
constexpr long SZ_FP    = (long)SPLK * 256 * 2048;
constexpr long SZ_FPO   = (long)SPLKO * 256 * 128;
constexpr long FU_WP  = 256L * 384 / 2;
constexpr long FU_XRT = (long)Bn * KFC * 384 / 2;
constexpr long FU_WR  = 256L * KFC / 2;
constexpr long FU_RT  = 2048L * KFC / 2;
constexpr long FU_WO  = FU_WR;
constexpr long FU_RO  = 128L * KFC / 2;

constexpr long OF_CTXF  = 0;
constexpr long OF_RELF  = OF_CTXF  + SZ_CTXF;
constexpr long OF_FEATT = OF_RELF  + SZ_RELF;
constexpr long OF_RELFT = OF_FEATT + SZ_FEATT;
constexpr long OF_PCTX4 = OF_RELFT + SZ_RELFT;
constexpr long OF_BIMAP = OF_PCTX4 + SZ_PCTX4;
constexpr long OF_XOBJ  = OF_BIMAP + SZ_BIMAP;
constexpr long OF_OBJ   = OF_XOBJ  + SZ_XOBJ;
constexpr long OF_ASUB  = OF_OBJ   + SZ_OBJ;
constexpr long OF_AOBJ  = OF_ASUB  + SZ_ASUB;
constexpr long OF_FREL  = OF_AOBJ  + SZ_AOBJ;
constexpr long OF_FOBJ  = OF_FREL  + SZ_FREL;
constexpr long OF_FP    = OF_FOBJ  + SZ_FOBJ;
constexpr long OF_FPO   = OF_FP    + SZ_FP;
constexpr long OF_WPH   = OF_FPO   + SZ_FPO;
constexpr long OF_WPL   = OF_WPH   + FU_WP;
constexpr long OF_XRTH  = OF_WPL   + FU_WP;
constexpr long OF_XRTL  = OF_XRTH  + FU_XRT;
constexpr long OF_WRH   = OF_XRTL  + FU_XRT;
constexpr long OF_WRL   = OF_WRH   + FU_WR;
constexpr long OF_RTH   = OF_WRL   + FU_WR;
constexpr long OF_RTL   = OF_RTH   + FU_RT;
constexpr long OF_WOH   = OF_RTL   + FU_RT;
constexpr long OF_WOL   = OF_WOH   + FU_WO;
constexpr long OF_ROH   = OF_WOL   + FU_WO;
constexpr long OF_ROL   = OF_ROH   + FU_RO;
constexpr long TOTAL    = OF_ROL   + FU_RO;
}  // namespace sg

__device__ float g_buf[sg::TOTAL];

// ========================= low-level helpers ===============================
__device__ __forceinline__ uint32_t smem_u32(const void* p) {
    uint32_t a;
    asm("{ .reg .u64 t; cvta.to.shared.u64 t, %1; cvt.u32.u64 %0, t; }" : "=r"(a) : "l"(p));
    return a;
}
__device__ __forceinline__ void cp_async16(uint32_t dst, const void* src) {
    asm volatile("cp.async.cg.shared.global [%0], [%1], 16;" :: "r"(dst), "l"(src));
}
__device__ __forceinline__ void cp_commit() {
    asm volatile("cp.async.commit_group;" ::: "memory");
}
__device__ __forceinline__ void ldsm4(uint32_t* a, uint32_t addr) {
    asm volatile("ldmatrix.sync.aligned.m8n8.x4.shared.b16 {%0,%1,%2,%3}, [%4];"
        : "=r"(a[0]), "=r"(a[1]), "=r"(a[2]), "=r"(a[3]) : "r"(addr));
}
__device__ __forceinline__ void ldsm2(uint32_t* b, uint32_t addr) {
    asm volatile("ldmatrix.sync.aligned.m8n8.x2.shared.b16 {%0,%1}, [%2];"
        : "=r"(b[0]), "=r"(b[1]) : "r"(addr));
}
__device__ __forceinline__ void mma16816(float* d, const uint32_t* a, const uint32_t* b) {
    asm volatile("mma.sync.aligned.m16n8k16.row.col.f32.bf16.bf16.f32 "
        "{%0,%1,%2,%3}, {%4,%5,%6,%7}, {%8,%9}, {%0,%1,%2,%3};"
        : "+f"(d[0]), "+f"(d[1]), "+f"(d[2]), "+f"(d[3])
        : "r"(a[0]), "r"(a[1]), "r"(a[2]), "r"(a[3]), "r"(b[0]), "r"(b[1]));
}
__device__ __forceinline__ void split_bf16(float x, __nv_bfloat16& h, __nv_bfloat16& l) {
    h = __float2bfloat16(x);
    l = __float2bfloat16(x - __bfloat162float(h));
}

// ========================= PrRoI pooling helpers ===========================
static __device__ __forceinline__ float hatG(float t) {
    float tl = fminf(fmaxf(t, -1.0f), 0.0f);
    float tr = fminf(fmaxf(t, 0.0f), 1.0f);
    return 0.5f * (tl + 1.0f) * (tl + 1.0f) + 0.5f - 0.5f * (1.0f - tr) * (1.0f - tr);
}

// wx padded to [7][32] (cols >= 24 are exact zeros) to allow fixed-6 unroll.
static __device__ __forceinline__ void compute_weights(
    float x1, float y1, float x2, float y2,
    float (*wy)[16], float (*wx)[32],
    int* h0, int* h1, int* w0, int* w1, int tid)
{
    if (tid < 112) {
        int p = tid / 16, i = tid % 16;
        float e0 = y1 + (y2 - y1) * (float)p * (1.0f / 7.0f);
        float e1 = y1 + (y2 - y1) * (float)(p + 1) * (1.0f / 7.0f);
        wy[p][i] = hatG(e1 - (float)i) - hatG(e0 - (float)i);
    }
    if (tid < 224) {
        int q = tid >> 5, i = tid & 31;
        float v = 0.0f;
        if (i < 24) {
            float e0 = x1 + (x2 - x1) * (float)q * (1.0f / 7.0f);
            float e1 = x1 + (x2 - x1) * (float)(q + 1) * (1.0f / 7.0f);
            v = hatG(e1 - (float)i) - hatG(e0 - (float)i);
        }
        wx[q][i] = v;
    }
    if (tid < 7) {
        float e0 = y1 + (y2 - y1) * (float)tid * (1.0f / 7.0f);
        float e1 = y1 + (y2 - y1) * (float)(tid + 1) * (1.0f / 7.0f);
        h0[tid] = max(0, (int)ceilf(e0) - 1);
        h1[tid] = min(16, (int)floorf(e1) + 2);
    }
    if (tid >= 32 && tid < 39) {
        int q = tid - 32;
        float e0 = x1 + (x2 - x1) * (float)q * (1.0f / 7.0f);
        float e1 = x1 + (x2 - x1) * (float)(q + 1) * (1.0f / 7.0f);
        w0[q] = max(0, (int)ceilf(e0) - 1);
        w1[q] = min(24, (int)floorf(e1) + 2);
    }
}

// Separable pooling, fixed-6 unrolled colsum (bin span provably <= 6; padded
// zero weights make extra terms exact zeros -> numerically identical).
static __device__ __forceinline__ void pool_channel_acc_range(
    const float* __restrict__ fb, int ps,
    const float (*wy)[16], const float (*wx)[32],
    const int* w0,
    int hlo, int hhi, float* acc)
{
    for (int h = hlo; h < hhi; h++) {
        const float* row = fb + (long)h * 24 * ps;
        float colsum[7];
#pragma unroll
        for (int q = 0; q < 7; q++) {
            int base = w0[q];
            float a = 0.0f;
#pragma unroll
            for (int k = 0; k < 6; k++) {
                int w = base + k;
                float wt = wx[q][w];           // 0 beyond support / >=24
                int wc = min(w, 23);           // clamped load (weight 0 there)
                a += wt * row[(long)wc * ps];
            }
            colsum[q] = a;
        }
#pragma unroll
        for (int p = 0; p < 7; p++) {
            float wv = wy[p][h];
#pragma unroll
            for (int q = 0; q < 7; q++)
                acc[p * 7 + q] += wv * colsum[q];
        }
    }
}

// ===================== dual 1x1 conv (ctx + rel in one launch) =============
__global__ void __launch_bounds__(256) conv_dual_kernel(
    const float* __restrict__ input,
    const float* __restrict__ Wctx, const float* __restrict__ bctx,
    const float* __restrict__ Wrel, const float* __restrict__ brel)
{
    using namespace sg;
    __shared__ float As[16][65];
    __shared__ float Bs[16][68];

    const int b = blockIdx.z;
    const int tid = threadIdx.x;
    const int row0 = blockIdx.y * 64;
    const int col0 = blockIdx.x * 64;
    const bool isCtx = row0 < 256;
    const float* A = isCtx ? (Wctx + (long)row0 * 256)
                           : (Wrel + (long)(row0 - 256) * 256);
    const float* bias = isCtx ? bctx : brel;
    const int biasBase = isCtx ? row0 : row0 - 256;
    const float* Bm = input + (long)b * Cc * HW;
    float* Cm = isCtx ? (g_buf + OF_CTXF + (long)b * Cc * HW + (long)row0 * 384)
                      : (g_buf + OF_RELF + (long)b * C32 * HW + (long)(row0 - 256) * 384);

    const int ty = tid >> 4, tx = tid & 15;
    const int ty4 = ty * 4, tx4 = tx * 4;
    const int ar = tid >> 2, ak = (tid & 3) << 2;
    const int br = tid >> 4, bc = (tid & 15) << 2;

    float acc[4][4] = {};

    for (int k0 = 0; k0 < 256; k0 += 16) {
        float4 av = *(const float4*)(A + (long)ar * 256 + k0 + ak);
        As[ak + 0][ar] = av.x; As[ak + 1][ar] = av.y;
        As[ak + 2][ar] = av.z; As[ak + 3][ar] = av.w;
        float4 bv = *(const float4*)(Bm + (long)(k0 + br) * 384 + col0 + bc);
        *(float4*)&Bs[br][bc] = bv;
        __syncthreads();

#pragma unroll
        for (int k = 0; k < 16; k++) {
            float a0 = As[k][ty4 + 0], a1 = As[k][ty4 + 1];
            float a2 = As[k][ty4 + 2], a3 = As[k][ty4 + 3];
            float4 b4 = *(const float4*)&Bs[k][tx4];
            acc[0][0] += a0 * b4.x; acc[0][1] += a0 * b4.y; acc[0][2] += a0 * b4.z; acc[0][3] += a0 * b4.w;
            acc[1][0] += a1 * b4.x; acc[1][1] += a1 * b4.y; acc[1][2] += a1 * b4.z; acc[1][3] += a1 * b4.w;
            acc[2][0] += a2 * b4.x; acc[2][1] += a2 * b4.y; acc[2][2] += a2 * b4.z; acc[2][3] += a2 * b4.w;
            acc[3][0] += a3 * b4.x; acc[3][1] += a3 * b4.y; acc[3][2] += a3 * b4.z; acc[3][3] += a3 * b4.w;
        }
        __syncthreads();
    }

#pragma unroll
    for (int u = 0; u < 4; u++) {
        float bz = bias[biasBase + ty4 + u];
#pragma unroll
        for (int v = 0; v < 4; v++)
            Cm[(long)(ty4 + u) * 384 + col0 + tx4 + v] = acc[u][v] + bz;
    }
}

// fp32 128x128 GEMM, optional multi-term via grid.y folding.
__global__ void __launch_bounds__(256) sgemm128_kernel(
    const float* __restrict__ Aex, long offA, int lda,
    long offB, int ldb, long sBb,
    long offC, int ldc, long sCb,
    int N, int K, int kChunk, int splitK,
    const float* __restrict__ bias,
    int nTerm, long dAoff, long dCoff)
{
    __shared__ float As[2][8][132];
    __shared__ float Bs[2][8][132];

    const int z = blockIdx.z;
    const int b = z / splitK;
    const int ks = z - b * splitK;
    const int kBeg = ks * kChunk;
    const int kEnd = min(K, kBeg + kChunk);
    const int nk = (kEnd - kBeg) >> 3;

    const int rowTiles = gridDim.y / nTerm;
    const int term = blockIdx.y / rowTiles;
    const int row0 = (blockIdx.y - term * rowTiles) * 128;
    const int col0 = blockIdx.x * 128;

    const float* A = Aex + offA + (long)term * dAoff;
    const float* B = g_buf + offB + (long)b * sBb;
    float* C = g_buf + offC + (long)term * dCoff + (long)z * sCb;

    const int t = threadIdx.x;
    const int arow = t >> 1, akq = (t & 1) << 2;
    const int brow = t >> 5, bcol = (t & 31) << 2;
    const int tx = t & 15, ty = t >> 4;

    const float* aPtr = A + (long)(row0 + arow) * lda + kBeg + akq;
    const float* bPtr = B + (long)(kBeg + brow) * ldb + col0 + bcol;
    const bool bIn = (col0 + bcol + 3) < N;

    float4 pa = *(const float4*)aPtr;
    float4 pb;
    if (bIn) {
        pb = *(const float4*)bPtr;
    } else {
        pb.x = (col0 + bcol + 0 < N) ? bPtr[0] : 0.0f;
        pb.y = (col0 + bcol + 1 < N) ? bPtr[1] : 0.0f;
        pb.z = (col0 + bcol + 2 < N) ? bPtr[2] : 0.0f;
        pb.w = 0.0f;
    }
    As[0][akq + 0][arow] = pa.x; As[0][akq + 1][arow] = pa.y;
    As[0][akq + 2][arow] = pa.z; As[0][akq + 3][arow] = pa.w;
    *(float4*)&Bs[0][brow][bcol] = pb;
    __syncthreads();

    float acc[8][8] = {};

    for (int kt = 0; kt < nk; kt++) {
        const int buf = kt & 1;
        if (kt + 1 < nk) {
            pa = *(const float4*)(aPtr + (kt + 1) * 8);
            const float* bp = bPtr + (long)(kt + 1) * 8 * ldb;
            if (bIn) {
                pb = *(const float4*)bp;
            } else {
                pb.x = (col0 + bcol + 0 < N) ? bp[0] : 0.0f;
                pb.y = (col0 + bcol + 1 < N) ? bp[1] : 0.0f;
                pb.z = (col0 + bcol + 2 < N) ? bp[2] : 0.0f;
                pb.w = 0.0f;
            }
        }
#pragma unroll
        for (int kk = 0; kk < 8; kk++) {
            float4 a0 = *(const float4*)&As[buf][kk][ty * 4];
            float4 a1 = *(const float4*)&As[buf][kk][64 + ty * 4];
            float4 b0 = *(const float4*)&Bs[buf][kk][tx * 4];
            float4 b1 = *(const float4*)&Bs[buf][kk][64 + tx * 4];
            float av[8] = {a0.x, a0.y, a0.z, a0.w, a1.x, a1.y, a1.z, a1.w};
            float bv[8] = {b0.x, b0.y, b0.z, b0.w, b1.x, b1.y, b1.z, b1.w};
#pragma unroll
            for (int u = 0; u < 8; u++)
#pragma unroll
                for (int v = 0; v < 8; v++)
                    acc[u][v] += av[u] * bv[v];
        }
        if (kt + 1 < nk) {
            const int nb = buf ^ 1;
            As[nb][akq + 0][arow] = pa.x; As[nb][akq + 1][arow] = pa.y;
            As[nb][akq + 2][arow] = pa.z; As[nb][akq + 3][arow] = pa.w;
            *(float4*)&Bs[nb][brow][bcol] = pb;
            __syncthreads();
        }
    }

#pragma unroll
    for (int u = 0; u < 8; u++) {
        int r = row0 + ((u < 4) ? ty * 4 + u : 64 + ty * 4 + (u - 4));
        float bz = bias ? bias[r] : 0.0f;
#pragma unroll
        for (int v = 0; v < 8; v++) {
            int c = col0 + ((v < 4) ? tx * 4 + v : 64 + tx * 4 + (v - 4));
            if (c < N) C[(long)r * ldc + c] = acc[u][v] + bz;
        }
    }
}

// ================ HMMA (mma.sync) bf16-split GEMM ==========================
__global__ void __launch_bounds__(256, 2) hmma_gemm_kernel(
    long offAhi, long offAlo, int lda,
    long offBhi, long offBlo, int ldb, long sBz,
    long offC, int ldc, long sCz,
    int kChunk, int batchB, int epiMode,
    long offAsub, long offAobj, const float* __restrict__ brf,
    long offRh, long offRl)
{
    extern __shared__ __nv_bfloat16 smb[];
    constexpr int STR = 40;
    constexpr int TILEE = 128 * STR;

    const int tid = threadIdx.x;
    const int warp = tid >> 5, lane = tid & 31;
    const int z = blockIdx.z;
    const int row0 = blockIdx.y * 128, col0 = blockIdx.x * 128;
    const long kBeg = batchB ? 0 : (long)z * kChunk;
    const int S = kChunk / 32;

    const __nv_bfloat16* Ahi = (const __nv_bfloat16*)(g_buf + offAhi);
    const __nv_bfloat16* Alo = (const __nv_bfloat16*)(g_buf + offAlo);
    const __nv_bfloat16* Bhi = (const __nv_bfloat16*)(g_buf + offBhi) + (batchB ? (long)z * sBz : 0);
    const __nv_bfloat16* Blo = (const __nv_bfloat16*)(g_buf + offBlo) + (batchB ? (long)z * sBz : 0);

    const int wm = (warp >> 2) * 64;
    const int wn = (warp & 3) * 32;

    float acc[4][4][4] = {};

    const uint32_t smem_base = smem_u32(smb);

    auto issue_load = [&](int s, int buf) {
        long koff = kBeg + (long)s * 32;
        uint32_t dstBase = smem_base + (uint32_t)buf * 4 * TILEE * 2;
#pragma unroll
        for (int t = 0; t < 4; t++) {
            const __nv_bfloat16* src = (t == 0) ? Ahi : (t == 1) ? Alo
                                      : (t == 2) ? Bhi : Blo;
            const int base0 = (t < 2) ? row0 : col0;
            const int ld = (t < 2) ? lda : ldb;
#pragma unroll
            for (int i = 0; i < 2; i++) {
                int idx = tid + i * 256;
                int r = idx >> 2;
                int cg = (idx & 3) * 8;
                cp_async16(dstBase + (uint32_t)((t * TILEE + r * STR + cg) * 2),
                           src + (long)(base0 + r) * ld + koff + cg);
            }
        }
        cp_commit();
    };

    issue_load(0, 0);

    for (int s = 0; s < S; s++) {
        if (s + 1 < S) {
            issue_load(s + 1, (s + 1) & 1);
            asm volatile("cp.async.wait_group 1;" ::: "memory");
        } else {
            asm volatile("cp.async.wait_group 0;" ::: "memory");
        }
        __syncthreads();

        const int buf = s & 1;
        const uint32_t tb = smem_base + (uint32_t)buf * 4 * TILEE * 2;
        const uint32_t aHiB = tb;
        const uint32_t aLoB = tb + TILEE * 2;
        const uint32_t bHiB = tb + 2 * TILEE * 2;
        const uint32_t bLoB = tb + 3 * TILEE * 2;
        const int lr = lane & 15;
        const int kofA = (lane >> 4) * 8;
        const int kofB = ((lane & 15) >> 3) * 8;

#pragma unroll
        for (int k16 = 0; k16 < 2; k16++) {
            uint32_t af[4][4], bh[4][2], bl[4][2];
#pragma unroll
            for (int mi = 0; mi < 4; mi++)
                ldsm4(af[mi], aHiB + (uint32_t)(((wm + mi * 16 + lr) * STR)
                                               + k16 * 16 + kofA) * 2);
#pragma unroll
            for (int ni = 0; ni < 4; ni++) {
                uint32_t ro = (uint32_t)(((wn + ni * 8 + (lr & 7)) * STR)
                                         + k16 * 16 + kofB) * 2;
                ldsm2(bh[ni], bHiB + ro);
                ldsm2(bl[ni], bLoB + ro);
            }
#pragma unroll
            for (int mi = 0; mi < 4; mi++)
#pragma unroll
                for (int ni = 0; ni < 4; ni++) {
                    mma16816(acc[mi][ni], af[mi], bh[ni]);   // hh
                    mma16816(acc[mi][ni], af[mi], bl[ni]);   // hl
                }
#pragma unroll
            for (int mi = 0; mi < 4; mi++)
                ldsm4(af[mi], aLoB + (uint32_t)(((wm + mi * 16 + lr) * STR)
                                               + k16 * 16 + kofA) * 2);
#pragma unroll
            for (int mi = 0; mi < 4; mi++)
#pragma unroll
                for (int ni = 0; ni < 4; ni++)
                    mma16816(acc[mi][ni], af[mi], bh[ni]);   // lh
        }
        __syncthreads();
    }

    if (epiMode == 0) {
        float* C = g_buf + offC + (long)z * sCz;
#pragma unroll
        for (int mi = 0; mi < 4; mi++) {
            int r = row0 + wm + mi * 16 + (lane >> 2);
#pragma unroll
            for (int ni = 0; ni < 4; ni++) {
                int cc = col0 + wn + ni * 8 + (lane & 3) * 2;
                *(float2*)&C[(long)r * ldc + cc] = make_float2(acc[mi][ni][0], acc[mi][ni][1]);
                *(float2*)&C[(long)(r + 8) * ldc + cc] = make_float2(acc[mi][ni][2], acc[mi][ni][3]);
            }
        }
    } else {
        using namespace sg;
        const float* A1b = g_buf + offAsub + (long)z * 256 * 784;
        const float* A2b = g_buf + offAobj + (long)z * 256 * 784;
        __nv_bfloat16* rh = (__nv_bfloat16*)(g_buf + offRh) + (long)z * 256 * KFC;
        __nv_bfloat16* rl = (__nv_bfloat16*)(g_buf + offRl) + (long)z * 256 * KFC;
#pragma unroll
        for (int mi = 0; mi < 4; mi++) {
#pragma unroll
            for (int half = 0; half < 2; half++) {
                int o = row0 + wm + mi * 16 + (lane >> 2) + half * 8;
                float bz = brf[o];
#pragma unroll
                for (int ni = 0; ni < 4; ni++) {
#pragma unroll
                    for (int e = 0; e < 2; e++) {
                        int cc = col0 + wn + ni * 8 + (lane & 3) * 2 + e;
                        int pair = cc / 49;
                        int s = cc - pair * 49;
                        int io = (pair >> 4) * 49 + s;
                        int jo = (pair & 15) * 49 + s;
                        float v = acc[mi][ni][half * 2 + e]
                                + A1b[(long)o * 784 + io]
                                + A2b[(long)o * 784 + jo] + bz;
                        v = fmaxf(v, 0.0f);
                        __nv_bfloat16 h, l;
                        split_bf16(v, h, l);
                        long di = (long)pair * KFC + o * 49 + s;
                        rh[di] = h;
                        rl[di] = l;
                    }
                }
            }
        }
    }
}

// ==================== misc data-movement / pooling =========================
__global__ void transpose_dual_kernel(const float* __restrict__ input)
{
    using namespace sg;
    __shared__ float tile[32][33];
    int b = blockIdx.z;
    const float* src;
    float* dst;
    int R, r0;
    if (blockIdx.y < 8) {
        R = 256; r0 = blockIdx.y * 32;
        src = input + (long)b * 256 * 384;
        dst = g_buf + OF_FEATT + (long)b * 256 * 384;
    } else {
        R = 384; r0 = (blockIdx.y - 8) * 32;
        src = g_buf + OF_RELF + (long)b * 384 * 384;
        dst = g_buf + OF_RELFT + (long)b * 384 * 384;
    }
    int c0 = blockIdx.x * 32;
    int tx = threadIdx.x, ty = threadIdx.y;
#pragma unroll
    for (int k = 0; k < 32; k += 8)
        tile[ty + k][tx] = src[(long)(r0 + ty + k) * 384 + c0 + tx];
    __syncthreads();
#pragma unroll
    for (int k = 0; k < 32; k += 8)
        dst[(long)(c0 + ty + k) * R + r0 + tx] = tile[tx][ty + k];
}

__global__ void __launch_bounds__(256) pool_obj_kernel(const float* __restrict__ boxes)
{
    using namespace sg;
    int b = blockIdx.y, n = blockIdx.x, tid = threadIdx.x;
    const float* bx = boxes + ((long)b * Nn + n) * 4;
    float x1 = bx[0], y1 = bx[1], x2 = bx[2], y2 = bx[3];
    float sx1 = x1 * SCALE, sy1 = y1 * SCALE, sx2 = x2 * SCALE, sy2 = y2 * SCALE;

    __shared__ float wy[7][16], wx[7][32];
    __shared__ int h0[7], h1[7], w0[7], w1[7];
    compute_weights(sx1, sy1, sx2, sy2, wy, wx, h0, h1, w0, w1, tid);

    if (tid < 49) {
        int p = tid / 7, q = tid % 7;
        float ye0 = IMGH * (float)p * (1.0f / 7.0f), ye1 = IMGH * (float)(p + 1) * (1.0f / 7.0f);
        float xe0 = IMGW * (float)q * (1.0f / 7.0f), xe1 = IMGW * (float)(q + 1) * (1.0f / 7.0f);
        float oy = fmaxf(fminf(ye1, y2) - fmaxf(ye0, y1), 0.0f);
        float ox = fmaxf(fminf(xe1, x2) - fmaxf(xe0, x1), 0.0f);
        float ch = IMGH * (1.0f / 7.0f), cw = IMGW * (1.0f / 7.0f);
        g_buf[OF_BIMAP + ((long)b * Nn + n) * PP + tid] = (oy / ch) * (ox / cw);
    }
    __syncthreads();

    float area = (sx2 - sx1) * (sy2 - sy1) * (1.0f / 49.0f);
    float inv = (area > 0.0f) ? 1.0f / fmaxf(area, 1e-9f) : 0.0f;

    int c = tid;
    const float* fb = g_buf + OF_FEATT + (long)b * HW * Cc + c;
    float acc[49];
#pragma unroll
    for (int s = 0; s < 49; s++) acc[s] = 0.0f;
    pool_channel_acc_range(fb, Cc, wy, wx, w0, h0[0], h1[6], acc);

    float* X = g_buf + OF_XOBJ + ((long)b * 512 + c) * 784 + (long)n * 49;
#pragma unroll
    for (int s = 0; s < 49; s++) X[s] = acc[s] * inv;
}

__global__ void __launch_bounds__(256) pool_ctx_kernel()
{
    using namespace sg;
    int hq = blockIdx.x, b = blockIdx.y, tid = threadIdx.x;
    __shared__ float wy[7][16], wx[7][32];
    __shared__ int h0[7], h1[7], w0[7], w1[7];
    compute_weights(0.0f, 0.0f, 24.0f, 16.0f, wy, wx, h0, h1, w0, w1, tid);
    __syncthreads();

    float inv = 49.0f / (24.0f * 16.0f);
    int c = tid;
    const float* fb = g_buf + OF_CTXF + ((long)b * Cc + c) * HW;
    float acc[49];
#pragma unroll
    for (int s = 0; s < 49; s++) acc[s] = 0.0f;
    pool_channel_acc_range(fb, 1, wy, wx, w0, hq * 4, hq * 4 + 4, acc);
    float* X = g_buf + OF_PCTX4 + (((long)b * 4 + hq) * Cc + c) * PP;
#pragma unroll
    for (int s = 0; s < 49; s++) X[s] = acc[s] * inv;
}

__global__ void pack_xobj_kernel()
{
    using namespace sg;
    int b = blockIdx.y;
    int base = blockIdx.x * blockDim.x + threadIdx.x;
    int stride = gridDim.x * blockDim.x;
    for (int idx = base; idx < 256 * 784; idx += stride) {
        int cc = idx / 784, rem = idx - cc * 784;
        int n = rem / 49, s = rem - n * 49;
        long p0 = OF_PCTX4 + ((long)b * 4 * Cc + cc) * PP + s;
        float v = g_buf[p0] + g_buf[p0 + (long)Cc * PP]
                + g_buf[p0 + 2L * Cc * PP] + g_buf[p0 + 3L * Cc * PP];
        if (cc >= 128) v *= g_buf[OF_BIMAP + ((long)b * Nn + n) * PP + s];
        g_buf[OF_XOBJ + ((long)b * 512 + 256 + cc) * 784 + rem] = v;
    }
}

// Symmetric pool_rel: one block per unordered pair {i,j}; writes both ordered
// pairs (masks swap). grid(136, 8), block 384.
__global__ void __launch_bounds__(384) pool_rel_kernel(const float* __restrict__ boxes)
{
    using namespace sg;
    extern __shared__ float stage[];
    int b = blockIdx.y, t = blockIdx.x, tid = threadIdx.x;
    int i = 0, rem = t;
    while (rem >= 16 - i) { rem -= 16 - i; i++; }
    int j = i + rem;

    const float* bi = boxes + ((long)b * Nn + i) * 4;
    const float* bj = boxes + ((long)b * Nn + j) * 4;
    float ix1 = bi[0], iy1 = bi[1], ix2 = bi[2], iy2 = bi[3];
    float jx1 = bj[0], jy1 = bj[1], jx2 = bj[2], jy2 = bj[3];
    float ux1 = fminf(ix1, jx1), uy1 = fminf(iy1, jy1);
    float ux2 = fmaxf(ix2, jx2), uy2 = fmaxf(iy2, jy2);
    float sx1 = ux1 * SCALE, sy1 = uy1 * SCALE, sx2 = ux2 * SCALE, sy2 = uy2 * SCALE;

    __shared__ float wy[7][16], wx[7][32];
    __shared__ int h0[7], h1[7], w0[7], w1[7];
    __shared__ float subm[49], objm[49];
    compute_weights(sx1, sy1, sx2, sy2, wy, wx, h0, h1, w0, w1, tid);

    if (tid < 49) {
        int p = tid / 7, q = tid - p * 7;
        float ye0 = uy1 + (uy2 - uy1) * (float)p * (1.0f / 7.0f);
        float ye1 = uy1 + (uy2 - uy1) * (float)(p + 1) * (1.0f / 7.0f);
        float xe0 = ux1 + (ux2 - ux1) * (float)q * (1.0f / 7.0f);
        float xe1 = ux1 + (ux2 - ux1) * (float)(q + 1) * (1.0f / 7.0f);
        float ch = fmaxf((uy2 - uy1) * (1.0f / 7.0f), 1e-9f);
        float cw = fmaxf((ux2 - ux1) * (1.0f / 7.0f), 1e-9f);
        float oy = fmaxf(fminf(ye1, iy2) - fmaxf(ye0, iy1), 0.0f);
        float ox = fmaxf(fminf(xe1, ix2) - fmaxf(xe0, ix1), 0.0f);
        subm[tid] = (oy / ch) * (ox / cw);
        oy = fmaxf(fminf(ye1, jy2) - fmaxf(ye0, jy1), 0.0f);
        ox = fmaxf(fminf(xe1, jx2) - fmaxf(xe0, jx1), 0.0f);
        objm[tid] = (oy / ch) * (ox / cw);
    }
    __syncthreads();

    float area = (sx2 - sx1) * (sy2 - sy1) * (1.0f / 49.0f);
    float inv = (area > 0.0f) ? 1.0f / fmaxf(area, 1e-9f) : 0.0f;

    int c = tid;
    const float* fb = g_buf + OF_RELFT + (long)b * HW * C32 + c;
    float acc[49];
#pragma unroll
    for (int s = 0; s < 49; s++) acc[s] = 0.0f;
    pool_channel_acc_range(fb, C32, wy, wx, w0, h0[0], h1[6], acc);

#pragma unroll
    for (int s = 0; s < 49; s++)
        stage[c * 49 + s] = acc[s] * inv;
    __syncthreads();

    __nv_bfloat16* xh = (__nv_bfloat16*)(g_buf + OF_XRTH);
    __nv_bfloat16* xl = (__nv_bfloat16*)(g_buf + OF_XRTL);
    int pair1 = i * 16 + j;
    int pair2 = j * 16 + i;
    long base1 = ((long)b * KFC + (long)pair1 * 49) * 384;
    long base2 = ((long)b * KFC + (long)pair2 * 49) * 384;
    for (int idx = tid; idx < 49 * 384; idx += 384) {
        int s = idx / 384, cc = idx - s * 384;
        float raw = stage[cc * 49 + s];
        float m1 = (cc < 128) ? 1.0f : (cc < 256 ? subm[s] : objm[s]);
        __nv_bfloat16 h, l;
        split_bf16(raw * m1, h, l);
        xh[base1 + (long)s * 384 + cc] = h;
        xl[base1 + (long)s * 384 + cc] = l;
        if (i != j) {
            float m2 = (cc < 128) ? 1.0f : (cc < 256 ? objm[s] : subm[s]);
            split_bf16(raw * m2, h, l);
            xh[base2 + (long)s * 384 + cc] = h;
            xl[base2 + (long)s * 384 + cc] = l;
        }
    }
}

__global__ void __launch_bounds__(256) combine_obj_kernel()
{
    using namespace sg;
    int row = blockIdx.x >> 3;
    int seg = blockIdx.x & 7;
    int b = row >> 4, i = row & 15;
    const float* obj = g_buf + OF_OBJ + (long)b * 256 * 784 + (long)i * 49;
    __nv_bfloat16* rh = (__nv_bfloat16*)(g_buf + OF_ROH) + (long)row * KFC;
    __nv_bfloat16* rl = (__nv_bfloat16*)(g_buf + OF_ROL) + (long)row * KFC;
    int beg = seg * 1568, end = beg + 1568;
    for (int idx = beg + threadIdx.x; idx < end; idx += 256) {
        int o = idx / 49, s = idx - o * 49;
        float v = fmaxf(obj[(long)o * 784 + s], 0.0f);
        __nv_bfloat16 h, l;
        split_bf16(v, h, l);
        rh[idx] = h; rl[idx] = l;
    }
}

__global__ void convert_w_kernel(const float* __restrict__ W, int lda, int colOff,
                                 long offHi, long offLo, long total, int Kout)
{
    __nv_bfloat16* ph = (__nv_bfloat16*)(g_buf + offHi);
    __nv_bfloat16* pl = (__nv_bfloat16*)(g_buf + offLo);
    for (long idx = (long)blockIdx.x * blockDim.x + threadIdx.x; idx < total;
         idx += (long)gridDim.x * blockDim.x) {
        long m = idx / Kout;
        int k = (int)(idx - m * Kout);
        float x = W[m * lda + colOff + k];
        __nv_bfloat16 h, l;
        split_bf16(x, h, l);
        ph[idx] = h; pl[idx] = l;
    }
}

__global__ void reduce_split_kernel(long offP, long offO, long MN, int Ncols,
                                    int S, const float* __restrict__ bias)
{
    long idx = (long)blockIdx.x * blockDim.x + threadIdx.x;
    if (idx >= MN) return;
    float s = 0.0f;
    for (int i = 0; i < S; i++) s += g_buf[offP + (long)i * MN + idx];
    int m = (int)(idx / Ncols);
    g_buf[offO + idx] = s + bias[m];
}

__global__ void finalize_kernel(long srcOff, int ncols, float* __restrict__ out)
{
    int col = blockIdx.x, n = threadIdx.x;
    float v = g_buf[srcOff + (long)n * ncols + col];
    float s = v * v;
#pragma unroll
    for (int o = 16; o > 0; o >>= 1) s += __shfl_xor_sync(0xffffffffu, s, o);
    __shared__ float red[8];
    if ((n & 31) == 0) red[n >> 5] = s;
    __syncthreads();
    float tot = red[0] + red[1] + red[2] + red[3] + red[4] + red[5] + red[6] + red[7];
    out[(long)col * 256 + n] = v / sqrtf(tot);
}

// ===========================================================================
extern "C" void kernel_launch(void* const* d_in, const int* in_sizes, int n_in,
                              void* d_out, int out_size)
{
    using namespace sg;
    const float* input = (const float*)d_in[0];
    const float* boxes = (const float*)d_in[1];
    const float* W_ctx = (const float*)d_in[3];
    const float* b_ctx = (const float*)d_in[4];
    const float* W_rel = (const float*)d_in[5];
    const float* b_rel = (const float*)d_in[6];
    const float* W_of  = (const float*)d_in[7];
    const float* b_of  = (const float*)d_in[8];
    const float* W_rf  = (const float*)d_in[9];
    const float* b_rf  = (const float*)d_in[10];
    const float* W_ofc = (const float*)d_in[11];
    const float* b_ofc = (const float*)d_in[12];
    const float* W_rfc = (const float*)d_in[13];
    const float* b_rfc = (const float*)d_in[14];
    float* out = (float*)d_out;

    const long s784  = 256L * 784;
    const int SMEM_HMMA = 2 * 4 * 128 * 40 * 2;   // 81920 bytes

    cudaFuncSetAttribute(hmma_gemm_kernel, cudaFuncAttributeMaxDynamicSharedMemorySize, SMEM_HMMA);
    cudaFuncSetAttribute(pool_rel_kernel, cudaFuncAttributeMaxDynamicSharedMemorySize, 384 * 49 * 4);

    // 0. fused ctx + rel 1x1 convs
    conv_dual_kernel<<<dim3(6, 10, 8), 256>>>(input, W_ctx, b_ctx, W_rel, b_rel);
    // 1. fused transposes (feat + relf)
    transpose_dual_kernel<<<dim3(12, 20, 8), dim3(32, 8)>>>(input);
    // 2. pair-GEMM weight conversion
    convert_w_kernel<<<384, 256>>>(W_rf, 896, 512, OF_WPH, OF_WPL, 256L * 384, 384);
    // 3. pool rel, symmetric pairs  (index 3 -> ncu capture target)
    pool_rel_kernel<<<dim3(NPAIRU, 8), 384, 384 * 49 * 4>>>(boxes);
    // 4-5. ctx/obj pooling
    pool_ctx_kernel<<<dim3(4, 8), 256>>>();
    pool_obj_kernel<<<dim3(16, 8), 256>>>(boxes);
    // 6. pack ctx-pooled channels into Xobj
    pack_xobj_kernel<<<dim3(16, 8), 256>>>();
    // 7. obj conv (fp32)
    sgemm128_kernel<<<dim3(7, 2, 8), 256>>>(W_of, 0, 512, OF_XOBJ, 784, 512L * 784,
                                            OF_OBJ, 784, s784, 784, 512, 512, 1, b_of,
                                            1, 0, 0);
    // 8. Asub + Aobj in ONE launch
    sgemm128_kernel<<<dim3(7, 4, 8), 256>>>(W_rf, 0, 896, OF_OBJ, 784, s784,
                                            OF_ASUB, 784, s784, 784, 256, 256, 1, nullptr,
                                            2, 256, OF_AOBJ - OF_ASUB);
    // 9. pair GEMM (HMMA, batched) + fused combine/relu/split epilogue -> R^T
    hmma_gemm_kernel<<<dim3(98, 2, 8), 256, SMEM_HMMA>>>(
        OF_WPH, OF_WPL, 384, OF_XRTH, OF_XRTL, 384, (long)KFC * 384,
        0, 0, 0, 384, 1, 1, OF_ASUB, OF_AOBJ, b_rf, OF_RTH, OF_RTL);
    // 10. rel FC weight conversion
    convert_w_kernel<<<4096, 256>>>(W_rfc, KFC, 0, OF_WRH, OF_WRL, 256L * KFC, KFC);
    // 11. rel FC (HMMA, split-K 14) + reduce
    hmma_gemm_kernel<<<dim3(16, 2, SPLK), 256, SMEM_HMMA>>>(
        OF_WRH, OF_WRL, KFC, OF_RTH, OF_RTL, KFC, 0,
        OF_FP, 2048, 256L * 2048, KFC / SPLK, 0, 0, 0, 0, nullptr, 0, 0);
    reduce_split_kernel<<<2048, 256>>>(OF_FP, OF_FREL, 256L * 2048, 2048, SPLK, b_rfc);
    // 12. relu(obj) -> Robj^T bf16 hi/lo
    combine_obj_kernel<<<1024, 256>>>();
    // 13. obj FC weight conversion
    convert_w_kernel<<<4096, 256>>>(W_ofc, KFC, 0, OF_WOH, OF_WOL, 256L * KFC, KFC);
    // 14. obj FC (HMMA, split-K 49) + reduce
    hmma_gemm_kernel<<<dim3(1, 2, SPLKO), 256, SMEM_HMMA>>>(
        OF_WOH, OF_WOL, KFC, OF_ROH, OF_ROL, KFC, 0,
        OF_FPO, 128, 256L * 128, KFC / SPLKO, 0, 0, 0, 0, nullptr, 0, 0);
    reduce_split_kernel<<<128, 256>>>(OF_FPO, OF_FOBJ, 256L * 128, 128, SPLKO, b_ofc);
    // 15-16. l2norm heads
    finalize_kernel<<<128, 256>>>(OF_FOBJ, 128, out);
    finalize_kernel<<<2048, 256>>>(OF_FREL, 2048, out + 32768);
}

// round 12
// speedup vs baseline: 5.4141x; 1.0112x over previous
#include <cuda_runtime.h>
#include <cuda_bf16.h>
#include <math.h>
#include <stdint.h>

namespace sg {
constexpr int Bn = 8, Cc = 256, Nn = 16;
constexpr int HW = 384;
constexpr int C32 = 384;
constexpr float SCALE = 1.0f / 16.0f;
constexpr float IMGW = 384.0f, IMGH = 256.0f;
constexpr int PP = 49;
constexpr int KFC = 12544;
constexpr int SPLK = 7;               // rel FC split-K (7*1792 = 12544)
constexpr int SPLKO = 49;
constexpr int NPAIRU = 136;

constexpr long SZ_CTXF  = (long)Bn * Cc * HW;
constexpr long SZ_RELF  = (long)Bn * C32 * HW;
constexpr long SZ_FEATT = SZ_CTXF;
constexpr long SZ_RELFT = SZ_RELF;
constexpr long SZ_PCTX4 = (long)Bn * 4 * Cc * PP;
constexpr long SZ_BIMAP = (long)Bn * Nn * PP;
constexpr long SZ_XOBJ  = (long)Bn * 512 * 784;
constexpr long SZ_OBJ   = (long)Bn * 256 * 784;
constexpr long SZ_ASUB  = SZ_OBJ;
constexpr long SZ_AOBJ  = SZ_OBJ;
constexpr long SZ_FREL  = 256L * 2048;
constexpr long SZ_FOBJ  = 256L * 128;
constexpr long SZ_FP    = 14L * 256 * 2048;   // sized for max splitK used
constexpr long SZ_FPO   = (long)SPLKO * 256 * 128;
constexpr long FU_WP  = 256L * 384 / 2;
constexpr long FU_XRT = (long)Bn * KFC * 384 / 2;
constexpr long FU_WR  = 256L * KFC / 2;
constexpr long FU_RT  = 2048L * KFC / 2;
constexpr long FU_WO  = FU_WR;
constexpr long FU_RO  = 128L * KFC / 2;

constexpr long OF_CTXF  = 0;
constexpr long OF_RELF  = OF_CTXF  + SZ_CTXF;
constexpr long OF_FEATT = OF_RELF  + SZ_RELF;
constexpr long OF_RELFT = OF_FEATT + SZ_FEATT;
constexpr long OF_PCTX4 = OF_RELFT + SZ_RELFT;
constexpr long OF_BIMAP = OF_PCTX4 + SZ_PCTX4;
constexpr long OF_XOBJ  = OF_BIMAP + SZ_BIMAP;
constexpr long OF_OBJ   = OF_XOBJ  + SZ_XOBJ;
constexpr long OF_ASUB  = OF_OBJ   + SZ_OBJ;
constexpr long OF_AOBJ  = OF_ASUB  + SZ_ASUB;
constexpr long OF_FREL  = OF_AOBJ  + SZ_AOBJ;
constexpr long OF_FOBJ  = OF_FREL  + SZ_FREL;
constexpr long OF_FP    = OF_FOBJ  + SZ_FOBJ;
constexpr long OF_FPO   = OF_FP    + SZ_FP;
constexpr long OF_WPH   = OF_FPO   + SZ_FPO;
constexpr long OF_WPL   = OF_WPH   + FU_WP;
constexpr long OF_XRTH  = OF_WPL   + FU_WP;
constexpr long OF_XRTL  = OF_XRTH  + FU_XRT;
constexpr long OF_WRH   = OF_XRTL  + FU_XRT;
constexpr long OF_WRL   = OF_WRH   + FU_WR;
constexpr long OF_RTH   = OF_WRL   + FU_WR;
constexpr long OF_RTL   = OF_RTH   + FU_RT;
constexpr long OF_WOH   = OF_RTL   + FU_RT;
constexpr long OF_WOL   = OF_WOH   + FU_WO;
constexpr long OF_ROH   = OF_WOL   + FU_WO;
constexpr long OF_ROL   = OF_ROH   + FU_RO;
constexpr long TOTAL    = OF_ROL   + FU_RO + 64;   // pad for harmless overreads
}  // namespace sg

__device__ float g_buf[sg::TOTAL];

// ========================= low-level helpers ===============================
__device__ __forceinline__ uint32_t smem_u32(const void* p) {
    uint32_t a;
    asm("{ .reg .u64 t; cvta.to.shared.u64 t, %1; cvt.u32.u64 %0, t; }" : "=r"(a) : "l"(p));
    return a;
}
__device__ __forceinline__ void cp_async16(uint32_t dst, const void* src) {
    asm volatile("cp.async.cg.shared.global [%0], [%1], 16;" :: "r"(dst), "l"(src));
}
__device__ __forceinline__ void cp_commit() {
    asm volatile("cp.async.commit_group;" ::: "memory");
}
__device__ __forceinline__ void ldsm4(uint32_t* a, uint32_t addr) {
    asm volatile("ldmatrix.sync.aligned.m8n8.x4.shared.b16 {%0,%1,%2,%3}, [%4];"
        : "=r"(a[0]), "=r"(a[1]), "=r"(a[2]), "=r"(a[3]) : "r"(addr));
}
__device__ __forceinline__ void ldsm2(uint32_t* b, uint32_t addr) {
    asm volatile("ldmatrix.sync.aligned.m8n8.x2.shared.b16 {%0,%1}, [%2];"
        : "=r"(b[0]), "=r"(b[1]) : "r"(addr));
}
__device__ __forceinline__ void mma16816(float* d, const uint32_t* a, const uint32_t* b) {
    asm volatile("mma.sync.aligned.m16n8k16.row.col.f32.bf16.bf16.f32 "
        "{%0,%1,%2,%3}, {%4,%5,%6,%7}, {%8,%9}, {%0,%1,%2,%3};"
        : "+f"(d[0]), "+f"(d[1]), "+f"(d[2]), "+f"(d[3])
        : "r"(a[0]), "r"(a[1]), "r"(a[2]), "r"(a[3]), "r"(b[0]), "r"(b[1]));
}
__device__ __forceinline__ void split_bf16(float x, __nv_bfloat16& h, __nv_bfloat16& l) {
    h = __float2bfloat16(x);
    l = __float2bfloat16(x - __bfloat162float(h));
}

// ========================= PrRoI pooling helpers ===========================
static __device__ __forceinline__ float hatG(float t) {
    float tl = fminf(fmaxf(t, -1.0f), 0.0f);
    float tr = fminf(fmaxf(t, 0.0f), 1.0f);
    return 0.5f * (tl + 1.0f) * (tl + 1.0f) + 0.5f - 0.5f * (1.0f - tr) * (1.0f - tr);
}

// wx padded to [7][32] (cols >= 24 exact zeros) for fixed-6 unroll.
static __device__ __forceinline__ void compute_weights(
    float x1, float y1, float x2, float y2,
    float (*wy)[16], float (*wx)[32],
    int* h0, int* h1, int* w0, int* w1, int tid)
{
    if (tid < 112) {
        int p = tid / 16, i = tid % 16;
        float e0 = y1 + (y2 - y1) * (float)p * (1.0f / 7.0f);
        float e1 = y1 + (y2 - y1) * (float)(p + 1) * (1.0f / 7.0f);
        wy[p][i] = hatG(e1 - (float)i) - hatG(e0 - (float)i);
    }
    if (tid < 224) {
        int q = tid >> 5, i = tid & 31;
        float v = 0.0f;
        if (i < 24) {
            float e0 = x1 + (x2 - x1) * (float)q * (1.0f / 7.0f);
            float e1 = x1 + (x2 - x1) * (float)(q + 1) * (1.0f / 7.0f);
            v = hatG(e1 - (float)i) - hatG(e0 - (float)i);
        }
        wx[q][i] = v;
    }
    if (tid < 7) {
        float e0 = y1 + (y2 - y1) * (float)tid * (1.0f / 7.0f);
        float e1 = y1 + (y2 - y1) * (float)(tid + 1) * (1.0f / 7.0f);
        h0[tid] = max(0, (int)ceilf(e0) - 1);
        h1[tid] = min(16, (int)floorf(e1) + 2);
    }
    if (tid >= 32 && tid < 39) {
        int q = tid - 32;
        float e0 = x1 + (x2 - x1) * (float)q * (1.0f / 7.0f);
        float e1 = x1 + (x2 - x1) * (float)(q + 1) * (1.0f / 7.0f);
        w0[q] = max(0, (int)ceilf(e0) - 1);
        w1[q] = min(24, (int)floorf(e1) + 2);
    }
}

// Separable pooling, fixed-6 unrolled colsum, NO index clamp: overrun columns
// (w in [24,29)) read adjacent finite data but carry exact-zero weights.
static __device__ __forceinline__ void pool_channel_acc_range(
    const float* __restrict__ fb, int ps,
    const float (*wy)[16], const float (*wx)[32],
    const int* w0,
    int hlo, int hhi, float* acc)
{
    for (int h = hlo; h < hhi; h++) {
        const float* row = fb + (long)h * 24 * ps;
        float colsum[7];
#pragma unroll
        for (int q = 0; q < 7; q++) {
            int base = w0[q];
            const float* rp = row + (long)base * ps;
            float a = 0.0f;
#pragma unroll
            for (int k = 0; k < 6; k++)
                a += wx[q][base + k] * rp[(long)k * ps];
            colsum[q] = a;
        }
#pragma unroll
        for (int p = 0; p < 7; p++) {
            float wv = wy[p][h];
#pragma unroll
            for (int q = 0; q < 7; q++)
                acc[p * 7 + q] += wv * colsum[q];
        }
    }
}

// ===================== dual 1x1 conv (ctx + rel in one launch) =============
__global__ void __launch_bounds__(256) conv_dual_kernel(
    const float* __restrict__ input,
    const float* __restrict__ Wctx, const float* __restrict__ bctx,
    const float* __restrict__ Wrel, const float* __restrict__ brel)
{
    using namespace sg;
    __shared__ float As[16][65];
    __shared__ float Bs[16][68];

    const int b = blockIdx.z;
    const int tid = threadIdx.x;
    const int row0 = blockIdx.y * 64;
    const int col0 = blockIdx.x * 64;
    const bool isCtx = row0 < 256;
    const float* A = isCtx ? (Wctx + (long)row0 * 256)
                           : (Wrel + (long)(row0 - 256) * 256);
    const float* bias = isCtx ? bctx : brel;
    const int biasBase = isCtx ? row0 : row0 - 256;
    const float* Bm = input + (long)b * Cc * HW;
    float* Cm = isCtx ? (g_buf + OF_CTXF + (long)b * Cc * HW + (long)row0 * 384)
                      : (g_buf + OF_RELF + (long)b * C32 * HW + (long)(row0 - 256) * 384);

    const int ty = tid >> 4, tx = tid & 15;
    const int ty4 = ty * 4, tx4 = tx * 4;
    const int ar = tid >> 2, ak = (tid & 3) << 2;
    const int br = tid >> 4, bc = (tid & 15) << 2;

    float acc[4][4] = {};

    for (int k0 = 0; k0 < 256; k0 += 16) {
        float4 av = *(const float4*)(A + (long)ar * 256 + k0 + ak);
        As[ak + 0][ar] = av.x; As[ak + 1][ar] = av.y;
        As[ak + 2][ar] = av.z; As[ak + 3][ar] = av.w;
        float4 bv = *(const float4*)(Bm + (long)(k0 + br) * 384 + col0 + bc);
        *(float4*)&Bs[br][bc] = bv;
        __syncthreads();

#pragma unroll
        for (int k = 0; k < 16; k++) {
            float a0 = As[k][ty4 + 0], a1 = As[k][ty4 + 1];
            float a2 = As[k][ty4 + 2], a3 = As[k][ty4 + 3];
            float4 b4 = *(const float4*)&Bs[k][tx4];
            acc[0][0] += a0 * b4.x; acc[0][1] += a0 * b4.y; acc[0][2] += a0 * b4.z; acc[0][3] += a0 * b4.w;
            acc[1][0] += a1 * b4.x; acc[1][1] += a1 * b4.y; acc[1][2] += a1 * b4.z; acc[1][3] += a1 * b4.w;
            acc[2][0] += a2 * b4.x; acc[2][1] += a2 * b4.y; acc[2][2] += a2 * b4.z; acc[2][3] += a2 * b4.w;
            acc[3][0] += a3 * b4.x; acc[3][1] += a3 * b4.y; acc[3][2] += a3 * b4.z; acc[3][3] += a3 * b4.w;
        }
        __syncthreads();
    }

#pragma unroll
    for (int u = 0; u < 4; u++) {
        float bz = bias[biasBase + ty4 + u];
#pragma unroll
        for (int v = 0; v < 4; v++)
            Cm[(long)(ty4 + u) * 384 + col0 + tx4 + v] = acc[u][v] + bz;
    }
}

// fp32 128x128 GEMM, optional multi-term via grid.y folding.
__global__ void __launch_bounds__(256) sgemm128_kernel(
    const float* __restrict__ Aex, long offA, int lda,
    long offB, int ldb, long sBb,
    long offC, int ldc, long sCb,
    int N, int K, int kChunk, int splitK,
    const float* __restrict__ bias,
    int nTerm, long dAoff, long dCoff)
{
    __shared__ float As[2][8][132];
    __shared__ float Bs[2][8][132];

    const int z = blockIdx.z;
    const int b = z / splitK;
    const int ks = z - b * splitK;
    const int kBeg = ks * kChunk;
    const int kEnd = min(K, kBeg + kChunk);
    const int nk = (kEnd - kBeg) >> 3;

    const int rowTiles = gridDim.y / nTerm;
    const int term = blockIdx.y / rowTiles;
    const int row0 = (blockIdx.y - term * rowTiles) * 128;
    const int col0 = blockIdx.x * 128;

    const float* A = Aex + offA + (long)term * dAoff;
    const float* B = g_buf + offB + (long)b * sBb;
    float* C = g_buf + offC + (long)term * dCoff + (long)z * sCb;

    const int t = threadIdx.x;
    const int arow = t >> 1, akq = (t & 1) << 2;
    const int brow = t >> 5, bcol = (t & 31) << 2;
    const int tx = t & 15, ty = t >> 4;

    const float* aPtr = A + (long)(row0 + arow) * lda + kBeg + akq;
    const float* bPtr = B + (long)(kBeg + brow) * ldb + col0 + bcol;
    const bool bIn = (col0 + bcol + 3) < N;

    float4 pa = *(const float4*)aPtr;
    float4 pb;
    if (bIn) {
        pb = *(const float4*)bPtr;
    } else {
        pb.x = (col0 + bcol + 0 < N) ? bPtr[0] : 0.0f;
        pb.y = (col0 + bcol + 1 < N) ? bPtr[1] : 0.0f;
        pb.z = (col0 + bcol + 2 < N) ? bPtr[2] : 0.0f;
        pb.w = 0.0f;
    }
    As[0][akq + 0][arow] = pa.x; As[0][akq + 1][arow] = pa.y;
    As[0][akq + 2][arow] = pa.z; As[0][akq + 3][arow] = pa.w;
    *(float4*)&Bs[0][brow][bcol] = pb;
    __syncthreads();

    float acc[8][8] = {};

    for (int kt = 0; kt < nk; kt++) {
        const int buf = kt & 1;
        if (kt + 1 < nk) {
            pa = *(const float4*)(aPtr + (kt + 1) * 8);
            const float* bp = bPtr + (long)(kt + 1) * 8 * ldb;
            if (bIn) {
                pb = *(const float4*)bp;
            } else {
                pb.x = (col0 + bcol + 0 < N) ? bp[0] : 0.0f;
                pb.y = (col0 + bcol + 1 < N) ? bp[1] : 0.0f;
                pb.z = (col0 + bcol + 2 < N) ? bp[2] : 0.0f;
                pb.w = 0.0f;
            }
        }
#pragma unroll
        for (int kk = 0; kk < 8; kk++) {
            float4 a0 = *(const float4*)&As[buf][kk][ty * 4];
            float4 a1 = *(const float4*)&As[buf][kk][64 + ty * 4];
            float4 b0 = *(const float4*)&Bs[buf][kk][tx * 4];
            float4 b1 = *(const float4*)&Bs[buf][kk][64 + tx * 4];
            float av[8] = {a0.x, a0.y, a0.z, a0.w, a1.x, a1.y, a1.z, a1.w};
            float bv[8] = {b0.x, b0.y, b0.z, b0.w, b1.x, b1.y, b1.z, b1.w};
#pragma unroll
            for (int u = 0; u < 8; u++)
#pragma unroll
                for (int v = 0; v < 8; v++)
                    acc[u][v] += av[u] * bv[v];
        }
        if (kt + 1 < nk) {
            const int nb = buf ^ 1;
            As[nb][akq + 0][arow] = pa.x; As[nb][akq + 1][arow] = pa.y;
            As[nb][akq + 2][arow] = pa.z; As[nb][akq + 3][arow] = pa.w;
            *(float4*)&Bs[nb][brow][bcol] = pb;
            __syncthreads();
        }
    }

#pragma unroll
    for (int u = 0; u < 8; u++) {
        int r = row0 + ((u < 4) ? ty * 4 + u : 64 + ty * 4 + (u - 4));
        float bz = bias ? bias[r] : 0.0f;
#pragma unroll
        for (int v = 0; v < 8; v++) {
            int c = col0 + ((v < 4) ? tx * 4 + v : 64 + tx * 4 + (v - 4));
            if (c < N) C[(long)r * ldc + c] = acc[u][v] + bz;
        }
    }
}

// ================ HMMA (mma.sync) bf16-split GEMM ==========================
__global__ void __launch_bounds__(256, 2) hmma_gemm_kernel(
    long offAhi, long offAlo, int lda,
    long offBhi, long offBlo, int ldb, long sBz,
    long offC, int ldc, long sCz,
    int kChunk, int batchB, int epiMode,
    long offAsub, long offAobj, const float* __restrict__ brf,
    long offRh, long offRl)
{
    extern __shared__ __nv_bfloat16 smb[];
    constexpr int STR = 40;
    constexpr int TILEE = 128 * STR;

    const int tid = threadIdx.x;
    const int warp = tid >> 5, lane = tid & 31;
    const int z = blockIdx.z;
    const int row0 = blockIdx.y * 128, col0 = blockIdx.x * 128;
    const long kBeg = batchB ? 0 : (long)z * kChunk;
    const int S = kChunk / 32;

    const __nv_bfloat16* Ahi = (const __nv_bfloat16*)(g_buf + offAhi);
    const __nv_bfloat16* Alo = (const __nv_bfloat16*)(g_buf + offAlo);
    const __nv_bfloat16* Bhi = (const __nv_bfloat16*)(g_buf + offBhi) + (batchB ? (long)z * sBz : 0);
    const __nv_bfloat16* Blo = (const __nv_bfloat16*)(g_buf + offBlo) + (batchB ? (long)z * sBz : 0);

    const int wm = (warp >> 2) * 64;
    const int wn = (warp & 3) * 32;

    float acc[4][4][4] = {};

    const uint32_t smem_base = smem_u32(smb);

    auto issue_load = [&](int s, int buf) {
        long koff = kBeg + (long)s * 32;
        uint32_t dstBase = smem_base + (uint32_t)buf * 4 * TILEE * 2;
#pragma unroll
        for (int t = 0; t < 4; t++) {
            const __nv_bfloat16* src = (t == 0) ? Ahi : (t == 1) ? Alo
                                      : (t == 2) ? Bhi : Blo;
            const int base0 = (t < 2) ? row0 : col0;
            const int ld = (t < 2) ? lda : ldb;
#pragma unroll
            for (int i = 0; i < 2; i++) {
                int idx = tid + i * 256;
                int r = idx >> 2;
                int cg = (idx & 3) * 8;
                cp_async16(dstBase + (uint32_t)((t * TILEE + r * STR + cg) * 2),
                           src + (long)(base0 + r) * ld + koff + cg);
            }
        }
        cp_commit();
    };

    issue_load(0, 0);

    for (int s = 0; s < S; s++) {
        if (s + 1 < S) {
            issue_load(s + 1, (s + 1) & 1);
            asm volatile("cp.async.wait_group 1;" ::: "memory");
        } else {
            asm volatile("cp.async.wait_group 0;" ::: "memory");
        }
        __syncthreads();

        const int buf = s & 1;
        const uint32_t tb = smem_base + (uint32_t)buf * 4 * TILEE * 2;
        const uint32_t aHiB = tb;
        const uint32_t aLoB = tb + TILEE * 2;
        const uint32_t bHiB = tb + 2 * TILEE * 2;
        const uint32_t bLoB = tb + 3 * TILEE * 2;
        const int lr = lane & 15;
        const int kofA = (lane >> 4) * 8;
        const int kofB = ((lane & 15) >> 3) * 8;

#pragma unroll
        for (int k16 = 0; k16 < 2; k16++) {
            uint32_t af[4][4], bh[4][2], bl[4][2];
#pragma unroll
            for (int mi = 0; mi < 4; mi++)
                ldsm4(af[mi], aHiB + (uint32_t)(((wm + mi * 16 + lr) * STR)
                                               + k16 * 16 + kofA) * 2);
#pragma unroll
            for (int ni = 0; ni < 4; ni++) {
                uint32_t ro = (uint32_t)(((wn + ni * 8 + (lr & 7)) * STR)
                                         + k16 * 16 + kofB) * 2;
                ldsm2(bh[ni], bHiB + ro);
                ldsm2(bl[ni], bLoB + ro);
            }
#pragma unroll
            for (int mi = 0; mi < 4; mi++)
#pragma unroll
                for (int ni = 0; ni < 4; ni++) {
                    mma16816(acc[mi][ni], af[mi], bh[ni]);   // hh
                    mma16816(acc[mi][ni], af[mi], bl[ni]);   // hl
                }
#pragma unroll
            for (int mi = 0; mi < 4; mi++)
                ldsm4(af[mi], aLoB + (uint32_t)(((wm + mi * 16 + lr) * STR)
                                               + k16 * 16 + kofA) * 2);
#pragma unroll
            for (int mi = 0; mi < 4; mi++)
#pragma unroll
                for (int ni = 0; ni < 4; ni++)
                    mma16816(acc[mi][ni], af[mi], bh[ni]);   // lh
        }
        __syncthreads();
    }

    if (epiMode == 0) {
        float* C = g_buf + offC + (long)z * sCz;
#pragma unroll
        for (int mi = 0; mi < 4; mi++) {
            int r = row0 + wm + mi * 16 + (lane >> 2);
#pragma unroll
            for (int ni = 0; ni < 4; ni++) {
                int cc = col0 + wn + ni * 8 + (lane & 3) * 2;
                *(float2*)&C[(long)r * ldc + cc] = make_float2(acc[mi][ni][0], acc[mi][ni][1]);
                *(float2*)&C[(long)(r + 8) * ldc + cc] = make_float2(acc[mi][ni][2], acc[mi][ni][3]);
            }
        }
    } else {
        using namespace sg;
        const float* A1b = g_buf + offAsub + (long)z * 256 * 784;
        const float* A2b = g_buf + offAobj + (long)z * 256 * 784;
        __nv_bfloat16* rh = (__nv_bfloat16*)(g_buf + offRh) + (long)z * 256 * KFC;
        __nv_bfloat16* rl = (__nv_bfloat16*)(g_buf + offRl) + (long)z * 256 * KFC;
#pragma unroll
        for (int mi = 0; mi < 4; mi++) {
#pragma unroll
            for (int half = 0; half < 2; half++) {
                int o = row0 + wm + mi * 16 + (lane >> 2) + half * 8;
                float bz = brf[o];
#pragma unroll
                for (int ni = 0; ni < 4; ni++) {
#pragma unroll
                    for (int e = 0; e < 2; e++) {
                        int cc = col0 + wn + ni * 8 + (lane & 3) * 2 + e;
                        int pair = cc / 49;
                        int s = cc - pair * 49;
                        int io = (pair >> 4) * 49 + s;
                        int jo = (pair & 15) * 49 + s;
                        float v = acc[mi][ni][half * 2 + e]
                                + A1b[(long)o * 784 + io]
                                + A2b[(long)o * 784 + jo] + bz;
                        v = fmaxf(v, 0.0f);
                        __nv_bfloat16 h, l;
                        split_bf16(v, h, l);
                        long di = (long)pair * KFC + o * 49 + s;
                        rh[di] = h;
                        rl[di] = l;
                    }
                }
            }
        }
    }
}

// ==================== misc data-movement / pooling =========================
__global__ void transpose_dual_kernel(const float* __restrict__ input)
{
    using namespace sg;
    __shared__ float tile[32][33];
    int b = blockIdx.z;
    const float* src;
    float* dst;
    int R, r0;
    if (blockIdx.y < 8) {
        R = 256; r0 = blockIdx.y * 32;
        src = input + (long)b * 256 * 384;
        dst = g_buf + OF_FEATT + (long)b * 256 * 384;
    } else {
        R = 384; r0 = (blockIdx.y - 8) * 32;
        src = g_buf + OF_RELF + (long)b * 384 * 384;
        dst = g_buf + OF_RELFT + (long)b * 384 * 384;
    }
    int c0 = blockIdx.x * 32;
    int tx = threadIdx.x, ty = threadIdx.y;
#pragma unroll
    for (int k = 0; k < 32; k += 8)
        tile[ty + k][tx] = src[(long)(r0 + ty + k) * 384 + c0 + tx];
    __syncthreads();
#pragma unroll
    for (int k = 0; k < 32; k += 8)
        dst[(long)(c0 + ty + k) * R + r0 + tx] = tile[tx][ty + k];
}

__global__ void __launch_bounds__(256) pool_obj_kernel(const float* __restrict__ boxes)
{
    using namespace sg;
    int b = blockIdx.y, n = blockIdx.x, tid = threadIdx.x;
    const float* bx = boxes + ((long)b * Nn + n) * 4;
    float x1 = bx[0], y1 = bx[1], x2 = bx[2], y2 = bx[3];
    float sx1 = x1 * SCALE, sy1 = y1 * SCALE, sx2 = x2 * SCALE, sy2 = y2 * SCALE;

    __shared__ float wy[7][16], wx[7][32];
    __shared__ int h0[7], h1[7], w0[7], w1[7];
    compute_weights(sx1, sy1, sx2, sy2, wy, wx, h0, h1, w0, w1, tid);

    if (tid < 49) {
        int p = tid / 7, q = tid % 7;
        float ye0 = IMGH * (float)p * (1.0f / 7.0f), ye1 = IMGH * (float)(p + 1) * (1.0f / 7.0f);
        float xe0 = IMGW * (float)q * (1.0f / 7.0f), xe1 = IMGW * (float)(q + 1) * (1.0f / 7.0f);
        float oy = fmaxf(fminf(ye1, y2) - fmaxf(ye0, y1), 0.0f);
        float ox = fmaxf(fminf(xe1, x2) - fmaxf(xe0, x1), 0.0f);
        float ch = IMGH * (1.0f / 7.0f), cw = IMGW * (1.0f / 7.0f);
        g_buf[OF_BIMAP + ((long)b * Nn + n) * PP + tid] = (oy / ch) * (ox / cw);
    }
    __syncthreads();

    float area = (sx2 - sx1) * (sy2 - sy1) * (1.0f / 49.0f);
    float inv = (area > 0.0f) ? 1.0f / fmaxf(area, 1e-9f) : 0.0f;

    int c = tid;
    const float* fb = g_buf + OF_FEATT + (long)b * HW * Cc + c;
    float acc[49];
#pragma unroll
    for (int s = 0; s < 49; s++) acc[s] = 0.0f;
    pool_channel_acc_range(fb, Cc, wy, wx, w0, h0[0], h1[6], acc);

    float* X = g_buf + OF_XOBJ + ((long)b * 512 + c) * 784 + (long)n * 49;
#pragma unroll
    for (int s = 0; s < 49; s++) X[s] = acc[s] * inv;
}

__global__ void __launch_bounds__(256) pool_ctx_kernel()
{
    using namespace sg;
    int hq = blockIdx.x, b = blockIdx.y, tid = threadIdx.x;
    __shared__ float wy[7][16], wx[7][32];
    __shared__ int h0[7], h1[7], w0[7], w1[7];
    compute_weights(0.0f, 0.0f, 24.0f, 16.0f, wy, wx, h0, h1, w0, w1, tid);
    __syncthreads();

    float inv = 49.0f / (24.0f * 16.0f);
    int c = tid;
    const float* fb = g_buf + OF_CTXF + ((long)b * Cc + c) * HW;
    float acc[49];
#pragma unroll
    for (int s = 0; s < 49; s++) acc[s] = 0.0f;
    pool_channel_acc_range(fb, 1, wy, wx, w0, hq * 4, hq * 4 + 4, acc);
    float* X = g_buf + OF_PCTX4 + (((long)b * 4 + hq) * Cc + c) * PP;
#pragma unroll
    for (int s = 0; s < 49; s++) X[s] = acc[s] * inv;
}

__global__ void pack_xobj_kernel()
{
    using namespace sg;
    int b = blockIdx.y;
    int base = blockIdx.x * blockDim.x + threadIdx.x;
    int stride = gridDim.x * blockDim.x;
    for (int idx = base; idx < 256 * 784; idx += stride) {
        int cc = idx / 784, rem = idx - cc * 784;
        int n = rem / 49, s = rem - n * 49;
        long p0 = OF_PCTX4 + ((long)b * 4 * Cc + cc) * PP + s;
        float v = g_buf[p0] + g_buf[p0 + (long)Cc * PP]
                + g_buf[p0 + 2L * Cc * PP] + g_buf[p0 + 3L * Cc * PP];
        if (cc >= 128) v *= g_buf[OF_BIMAP + ((long)b * Nn + n) * PP + s];
        g_buf[OF_XOBJ + ((long)b * 512 + 256 + cc) * 784 + rem] = v;
    }
}

// Symmetric pool_rel: one block per unordered pair {i,j}; writes both ordered
// pairs (masks swap). grid(136, 8), block 384.
__global__ void __launch_bounds__(384, 2) pool_rel_kernel(const float* __restrict__ boxes)
{
    using namespace sg;
    extern __shared__ float stage[];
    int b = blockIdx.y, t = blockIdx.x, tid = threadIdx.x;
    int i = 0, rem = t;
    while (rem >= 16 - i) { rem -= 16 - i; i++; }
    int j = i + rem;

    const float* bi = boxes + ((long)b * Nn + i) * 4;
    const float* bj = boxes + ((long)b * Nn + j) * 4;
    float ix1 = bi[0], iy1 = bi[1], ix2 = bi[2], iy2 = bi[3];
    float jx1 = bj[0], jy1 = bj[1], jx2 = bj[2], jy2 = bj[3];
    float ux1 = fminf(ix1, jx1), uy1 = fminf(iy1, jy1);
    float ux2 = fmaxf(ix2, jx2), uy2 = fmaxf(iy2, jy2);
    float sx1 = ux1 * SCALE, sy1 = uy1 * SCALE, sx2 = ux2 * SCALE, sy2 = uy2 * SCALE;

    __shared__ float wy[7][16], wx[7][32];
    __shared__ int h0[7], h1[7], w0[7], w1[7];
    __shared__ float subm[49], objm[49];
    compute_weights(sx1, sy1, sx2, sy2, wy, wx, h0, h1, w0, w1, tid);

    if (tid < 49) {
        int p = tid / 7, q = tid - p * 7;
        float ye0 = uy1 + (uy2 - uy1) * (float)p * (1.0f / 7.0f);
        float ye1 = uy1 + (uy2 - uy1) * (float)(p + 1) * (1.0f / 7.0f);
        float xe0 = ux1 + (ux2 - ux1) * (float)q * (1.0f / 7.0f);
        float xe1 = ux1 + (ux2 - ux1) * (float)(q + 1) * (1.0f / 7.0f);
        float ch = fmaxf((uy2 - uy1) * (1.0f / 7.0f), 1e-9f);
        float cw = fmaxf((ux2 - ux1) * (1.0f / 7.0f), 1e-9f);
        float oy = fmaxf(fminf(ye1, iy2) - fmaxf(ye0, iy1), 0.0f);
        float ox = fmaxf(fminf(xe1, ix2) - fmaxf(xe0, ix1), 0.0f);
        subm[tid] = (oy / ch) * (ox / cw);
        oy = fmaxf(fminf(ye1, jy2) - fmaxf(ye0, jy1), 0.0f);
        ox = fmaxf(fminf(xe1, jx2) - fmaxf(xe0, jx1), 0.0f);
        objm[tid] = (oy / ch) * (ox / cw);
    }
    __syncthreads();

    float area = (sx2 - sx1) * (sy2 - sy1) * (1.0f / 49.0f);
    float inv = (area > 0.0f) ? 1.0f / fmaxf(area, 1e-9f) : 0.0f;

    int c = tid;
    const float* fb = g_buf + OF_RELFT + (long)b * HW * C32 + c;
    float acc[49];
#pragma unroll
    for (int s = 0; s < 49; s++) acc[s] = 0.0f;
    pool_channel_acc_range(fb, C32, wy, wx, w0, h0[0], h1[6], acc);

#pragma unroll
    for (int s = 0; s < 49; s++)
        stage[c * 49 + s] = acc[s] * inv;
    __syncthreads();

    __nv_bfloat16* xh = (__nv_bfloat16*)(g_buf + OF_XRTH);
    __nv_bfloat16* xl = (__nv_bfloat16*)(g_buf + OF_XRTL);
    int pair1 = i * 16 + j;
    int pair2 = j * 16 + i;
    long base1 = ((long)b * KFC + (long)pair1 * 49) * 384;
    long base2 = ((long)b * KFC + (long)pair2 * 49) * 384;
    for (int idx = tid; idx < 49 * 384; idx += 384) {
        int s = idx / 384, cc = idx - s * 384;
        float raw = stage[cc * 49 + s];
        float m1 = (cc < 128) ? 1.0f : (cc < 256 ? subm[s] : objm[s]);
        __nv_bfloat16 h, l;
        split_bf16(raw * m1, h, l);
        xh[base1 + (long)s * 384 + cc] = h;
        xl[base1 + (long)s * 384 + cc] = l;
        if (i != j) {
            float m2 = (cc < 128) ? 1.0f : (cc < 256 ? objm[s] : subm[s]);
            split_bf16(raw * m2, h, l);
            xh[base2 + (long)s * 384 + cc] = h;
            xl[base2 + (long)s * 384 + cc] = l;
        }
    }
}

__global__ void __launch_bounds__(256) combine_obj_kernel()
{
    using namespace sg;
    int row = blockIdx.x >> 3;
    int seg = blockIdx.x & 7;
    int b = row >> 4, i = row & 15;
    const float* obj = g_buf + OF_OBJ + (long)b * 256 * 784 + (long)i * 49;
    __nv_bfloat16* rh = (__nv_bfloat16*)(g_buf + OF_ROH) + (long)row * KFC;
    __nv_bfloat16* rl = (__nv_bfloat16*)(g_buf + OF_ROL) + (long)row * KFC;
    int beg = seg * 1568, end = beg + 1568;
    for (int idx = beg + threadIdx.x; idx < end; idx += 256) {
        int o = idx / 49, s = idx - o * 49;
        float v = fmaxf(obj[(long)o * 784 + s], 0.0f);
        __nv_bfloat16 h, l;
        split_bf16(v, h, l);
        rh[idx] = h; rl[idx] = l;
    }
}

__global__ void convert_w_kernel(const float* __restrict__ W, int lda, int colOff,
                                 long offHi, long offLo, long total, int Kout)
{
    __nv_bfloat16* ph = (__nv_bfloat16*)(g_buf + offHi);
    __nv_bfloat16* pl = (__nv_bfloat16*)(g_buf + offLo);
    for (long idx = (long)blockIdx.x * blockDim.x + threadIdx.x; idx < total;
         idx += (long)gridDim.x * blockDim.x) {
        long m = idx / Kout;
        int k = (int)(idx - m * Kout);
        float x = W[m * lda + colOff + k];
        __nv_bfloat16 h, l;
        split_bf16(x, h, l);
        ph[idx] = h; pl[idx] = l;
    }
}

__global__ void reduce_split_kernel(long offP, long offO, long MN, int Ncols,
                                    int S, const float* __restrict__ bias)
{
    long idx = (long)blockIdx.x * blockDim.x + threadIdx.x;
    if (idx >= MN) return;
    float s = 0.0f;
    for (int i = 0; i < S; i++) s += g_buf[offP + (long)i * MN + idx];
    int m = (int)(idx / Ncols);
    g_buf[offO + idx] = s + bias[m];
}

__global__ void finalize_kernel(long srcOff, int ncols, float* __restrict__ out)
{
    int col = blockIdx.x, n = threadIdx.x;
    float v = g_buf[srcOff + (long)n * ncols + col];
    float s = v * v;
#pragma unroll
    for (int o = 16; o > 0; o >>= 1) s += __shfl_xor_sync(0xffffffffu, s, o);
    __shared__ float red[8];
    if ((n & 31) == 0) red[n >> 5] = s;
    __syncthreads();
    float tot = red[0] + red[1] + red[2] + red[3] + red[4] + red[5] + red[6] + red[7];
    out[(long)col * 256 + n] = v / sqrtf(tot);
}

// ===========================================================================
extern "C" void kernel_launch(void* const* d_in, const int* in_sizes, int n_in,
                              void* d_out, int out_size)
{
    using namespace sg;
    const float* input = (const float*)d_in[0];
    const float* boxes = (const float*)d_in[1];
    const float* W_ctx = (const float*)d_in[3];
    const float* b_ctx = (const float*)d_in[4];
    const float* W_rel = (const float*)d_in[5];
    const float* b_rel = (const float*)d_in[6];
    const float* W_of  = (const float*)d_in[7];
    const float* b_of  = (const float*)d_in[8];
    const float* W_rf  = (const float*)d_in[9];
    const float* b_rf  = (const float*)d_in[10];
    const float* W_ofc = (const float*)d_in[11];
    const float* b_ofc = (const float*)d_in[12];
    const float* W_rfc = (const float*)d_in[13];
    const float* b_rfc = (const float*)d_in[14];
    float* out = (float*)d_out;

    const long s784  = 256L * 784;
    const int SMEM_HMMA = 2 * 4 * 128 * 40 * 2;   // 81920 bytes

    cudaFuncSetAttribute(hmma_gemm_kernel, cudaFuncAttributeMaxDynamicSharedMemorySize, SMEM_HMMA);
    cudaFuncSetAttribute(pool_rel_kernel, cudaFuncAttributeMaxDynamicSharedMemorySize, 384 * 49 * 4);

    // 0. fused ctx + rel 1x1 convs
    conv_dual_kernel<<<dim3(6, 10, 8), 256>>>(input, W_ctx, b_ctx, W_rel, b_rel);
    // 1. fused transposes (feat + relf)
    transpose_dual_kernel<<<dim3(12, 20, 8), dim3(32, 8)>>>(input);
    // 2. pair-GEMM weight conversion
    convert_w_kernel<<<384, 256>>>(W_rf, 896, 512, OF_WPH, OF_WPL, 256L * 384, 384);
    // 3. pool rel, symmetric pairs  (index 3 -> ncu capture target)
    pool_rel_kernel<<<dim3(NPAIRU, 8), 384, 384 * 49 * 4>>>(boxes);
    // 4-5. ctx/obj pooling
    pool_ctx_kernel<<<dim3(4, 8), 256>>>();
    pool_obj_kernel<<<dim3(16, 8), 256>>>(boxes);
    // 6. pack ctx-pooled channels into Xobj
    pack_xobj_kernel<<<dim3(16, 8), 256>>>();
    // 7. obj conv (fp32)
    sgemm128_kernel<<<dim3(7, 2, 8), 256>>>(W_of, 0, 512, OF_XOBJ, 784, 512L * 784,
                                            OF_OBJ, 784, s784, 784, 512, 512, 1, b_of,
                                            1, 0, 0);
    // 8. Asub + Aobj in ONE launch
    sgemm128_kernel<<<dim3(7, 4, 8), 256>>>(W_rf, 0, 896, OF_OBJ, 784, s784,
                                            OF_ASUB, 784, s784, 784, 256, 256, 1, nullptr,
                                            2, 256, OF_AOBJ - OF_ASUB);
    // 9. pair GEMM (HMMA, batched) + fused combine/relu/split epilogue -> R^T
    hmma_gemm_kernel<<<dim3(98, 2, 8), 256, SMEM_HMMA>>>(
        OF_WPH, OF_WPL, 384, OF_XRTH, OF_XRTL, 384, (long)KFC * 384,
        0, 0, 0, 384, 1, 1, OF_ASUB, OF_AOBJ, b_rf, OF_RTH, OF_RTL);
    // 10. rel FC weight conversion
    convert_w_kernel<<<4096, 256>>>(W_rfc, KFC, 0, OF_WRH, OF_WRL, 256L * KFC, KFC);
    // 11. rel FC (HMMA, split-K 7) + reduce
    hmma_gemm_kernel<<<dim3(16, 2, SPLK), 256, SMEM_HMMA>>>(
        OF_WRH, OF_WRL, KFC, OF_RTH, OF_RTL, KFC, 0,
        OF_FP, 2048, 256L * 2048, KFC / SPLK, 0, 0, 0, 0, nullptr, 0, 0);
    reduce_split_kernel<<<2048, 256>>>(OF_FP, OF_FREL, 256L * 2048, 2048, SPLK, b_rfc);
    // 12. relu(obj) -> Robj^T bf16 hi/lo
    combine_obj_kernel<<<1024, 256>>>();
    // 13. obj FC weight conversion
    convert_w_kernel<<<4096, 256>>>(W_ofc, KFC, 0, OF_WOH, OF_WOL, 256L * KFC, KFC);
    // 14. obj FC (HMMA, split-K 49) + reduce
    hmma_gemm_kernel<<<dim3(1, 2, SPLKO), 256, SMEM_HMMA>>>(
        OF_WOH, OF_WOL, KFC, OF_ROH, OF_ROL, KFC, 0,
        OF_FPO, 128, 256L * 128, KFC / SPLKO, 0, 0, 0, 0, nullptr, 0, 0);
    reduce_split_kernel<<<128, 256>>>(OF_FPO, OF_FOBJ, 256L * 128, 128, SPLKO, b_ofc);
    // 15-16. l2norm heads
    finalize_kernel<<<128, 256>>>(OF_FOBJ, 128, out);
    finalize_kernel<<<2048, 256>>>(OF_FREL, 2048, out + 32768);
}